// round 11
// baseline (speedup 1.0000x reference)
#include <cuda_runtime.h>
#include <cuda_bf16.h>
#include <math.h>
#include <stdint.h>

using bf16 = __nv_bfloat16;
typedef unsigned long long u64;

// ---------------------------------------------------------------------------
// Problem constants
// ---------------------------------------------------------------------------
constexpr int S_LEN   = 4096;
constexpr int EMB_D   = 2048;
constexpr int N_KH    = 16;
constexpr int N_VH    = 32;
constexpr int D_K     = 128;
constexpr int D_V     = 128;
constexpr int KEY_DIM = N_KH * D_K;                  // 2048
constexpr int VAL_DIM = N_VH * D_V;                  // 4096
constexpr int QKVZ_N  = 2 * KEY_DIM + 2 * VAL_DIM;   // 12288
constexpr int CH      = 64;
constexpr int NCH     = S_LEN / CH;                  // 64
constexpr float RSQRT_DK = 0.08838834764831845f;

constexpr int SKP = 130;   // 64x128 f32 tiles (intra) -- even for 8B pairs
constexpr int SDP = 65;    // 64x64 tiles (intra)
constexpr int SYP = 257;   // 64x256 solve buffer

// ---------------------------------------------------------------------------
// Scratch (static device globals)
// ---------------------------------------------------------------------------
__device__ float g_qkvz[(size_t)S_LEN * QKVZ_N];
__device__ float g_ba_part[16][(size_t)S_LEN * 64];
__device__ float g_q   [(size_t)S_LEN * KEY_DIM];
__device__ float g_k   [(size_t)S_LEN * KEY_DIM];
__device__ float g_v   [(size_t)S_LEN * VAL_DIM];
__device__ float g_beta[(size_t)S_LEN * N_VH];
__device__ float g_g   [(size_t)S_LEN * N_VH];
__device__ float g_qg  [(size_t)NCH * N_VH * CH * D_K];
__device__ float g_kg  [(size_t)NCH * N_VH * CH * D_K];
__device__ float g_kcd [(size_t)NCH * N_VH * CH * D_K];
__device__ float g_vi  [(size_t)NCH * N_VH * CH * D_V];
__device__ float g_am  [(size_t)NCH * N_VH * CH * CH];
__device__ float g_egl [(size_t)NCH * N_VH];
__device__ float g_core[(size_t)S_LEN * VAL_DIM];
// bf16-split operands for the tensor-core GEMMs
__device__ bf16 g_Ah[(size_t)4096 * 4096];
__device__ bf16 g_Al[(size_t)4096 * 4096];
__device__ bf16 g_Bh[(size_t)12288 * 2048];   // [N][K] K-major
__device__ bf16 g_Bl[(size_t)12288 * 2048];

// ---------------------------------------------------------------------------
// Helpers
// ---------------------------------------------------------------------------
__device__ __forceinline__ uint32_t smem_u32(const void* p) {
    uint32_t a;
    asm("{ .reg .u64 t; cvta.to.shared.u64 t, %1; cvt.u32.u64 %0, t; }" : "=r"(a) : "l"(p));
    return a;
}
#define CP_ASYNC16(dst, src) \
    asm volatile("cp.async.cg.shared.global [%0], [%1], 16;" :: "r"(dst), "l"(src))
#define CP_COMMIT() asm volatile("cp.async.commit_group;")
#define CP_WAIT0()  asm volatile("cp.async.wait_group 0;")

// packed dual-fp32 FMA (sm_100+ baseline PTX)
__device__ __forceinline__ u64 pack2(float lo, float hi) {
    u64 r;
    asm("mov.b64 %0, {%1, %2};" : "=l"(r) : "f"(lo), "f"(hi));
    return r;
}
__device__ __forceinline__ void unpack2(u64 v, float& lo, float& hi) {
    asm("mov.b64 {%0, %1}, %2;" : "=f"(lo), "=f"(hi) : "l"(v));
}
__device__ __forceinline__ void fma2(u64& d, u64 a, u64 b) {
    asm("fma.rn.f32x2 %0, %1, %2, %0;" : "+l"(d) : "l"(a), "l"(b));
}

// Non-volatile MMA wrapper: pure register dataflow, compiler may reschedule.
__device__ __forceinline__ void mma16816(float* cc, const uint32_t* a, const uint32_t* b) {
    asm("mma.sync.aligned.m16n8k16.row.col.f32.bf16.bf16.f32 "
        "{%0,%1,%2,%3}, {%4,%5,%6,%7}, {%8,%9}, {%0,%1,%2,%3};"
        : "+f"(cc[0]), "+f"(cc[1]), "+f"(cc[2]), "+f"(cc[3])
        : "r"(a[0]), "r"(a[1]), "r"(a[2]), "r"(a[3]), "r"(b[0]), "r"(b[1]));
}

// ---------------------------------------------------------------------------
// Prep: elementwise bf16 hi/lo split of an fp32 matrix (layout preserved)
// ---------------------------------------------------------------------------
__global__ __launch_bounds__(256) void split_bf16_kernel(
    const float* __restrict__ X, bf16* __restrict__ Xh, bf16* __restrict__ Xl, size_t n4)
{
    size_t i = (size_t)blockIdx.x * 256 + threadIdx.x;
    if (i >= n4) return;
    float4 v = reinterpret_cast<const float4*>(X)[i];
    bf16 h0 = __float2bfloat16_rn(v.x);
    bf16 h1 = __float2bfloat16_rn(v.y);
    bf16 h2 = __float2bfloat16_rn(v.z);
    bf16 h3 = __float2bfloat16_rn(v.w);
    bf16 l0 = __float2bfloat16_rn(v.x - __bfloat162float(h0));
    bf16 l1 = __float2bfloat16_rn(v.y - __bfloat162float(h1));
    bf16 l2 = __float2bfloat16_rn(v.z - __bfloat162float(h2));
    bf16 l3 = __float2bfloat16_rn(v.w - __bfloat162float(h3));
    __nv_bfloat162* ph = reinterpret_cast<__nv_bfloat162*>(Xh);
    __nv_bfloat162* pl = reinterpret_cast<__nv_bfloat162*>(Xl);
    ph[2 * i]     = __nv_bfloat162(h0, h1);
    ph[2 * i + 1] = __nv_bfloat162(h2, h3);
    pl[2 * i]     = __nv_bfloat162(l0, l1);
    pl[2 * i + 1] = __nv_bfloat162(l2, l3);
}

// Prep: W[K][N] -> Bt[N][K] with bf16 hi/lo split
__global__ __launch_bounds__(256) void transpose_split_bf16(
    const float* __restrict__ W, bf16* __restrict__ Bh, bf16* __restrict__ Bl, int K, int N)
{
    __shared__ float t[32][33];
    const int n0 = blockIdx.x * 32, k0 = blockIdx.y * 32;
    const int c = threadIdx.x & 31, r0 = threadIdx.x >> 5;
#pragma unroll
    for (int i = 0; i < 4; i++)
        t[r0 + i * 8][c] = W[(size_t)(k0 + r0 + i * 8) * N + n0 + c];
    __syncthreads();
#pragma unroll
    for (int i = 0; i < 4; i++) {
        int rr = r0 + i * 8;
        float x = t[c][rr];
        bf16 h = __float2bfloat16_rn(x);
        size_t o = (size_t)(n0 + rr) * K + k0 + c;
        Bh[o] = h;
        Bl[o] = __float2bfloat16_rn(x - __bfloat162float(h));
    }
}

// ---------------------------------------------------------------------------
// bf16-split tensor-core GEMM via mma.sync: C[M,N] = A[M,K] @ Bt[N,K]^T
// CTA 128x128, BK=32, 256 threads (2x4 warps, warp tile 64x32),
// 2-stage cp.async pipeline, 2 CTAs/SM. aL-reload hoisted above pass 2 so
// AhBl MMAs cover the LDSM latency.
// ---------------------------------------------------------------------------
constexpr int GROWB  = 80;             // smem bytes per 32-half row (64 + 16 pad)
constexpr int GTILE  = 128 * GROWB;    // 10240 B per operand tile
constexpr int GSTAGE = 4 * GTILE;      // Ah, Al, Bh, Bl
constexpr int GSMEM  = 2 * GSTAGE;     // 81920 B

__global__ __launch_bounds__(256, 2) void mma_gemm_kernel(
    const bf16* __restrict__ Ah, const bf16* __restrict__ Al,
    const bf16* __restrict__ Bh, const bf16* __restrict__ Bl,
    float* __restrict__ C, int M, int N, int K)
{
    extern __shared__ char smg[];
    const uint32_t sbase = smem_u32(smg);
    const int tid  = threadIdx.x;
    const int lane = tid & 31, wid = tid >> 5;
    const int m0 = blockIdx.x * 128, n0 = blockIdx.y * 128;
    const int wm = (wid >> 2) * 64, wn = (wid & 3) * 32;
    const int NT = K / 32;

    float acc[4][4][4];
#pragma unroll
    for (int a = 0; a < 4; a++)
#pragma unroll
        for (int b = 0; b < 4; b++)
#pragma unroll
            for (int c = 0; c < 4; c++) acc[a][b][c] = 0.f;

    auto load_stage = [&](int kt, int st) {
        const int kc = kt * 32;
        const uint32_t dbase = sbase + st * GSTAGE;
#pragma unroll
        for (int it = 0; it < 8; it++) {
            int idx = tid + it * 256;
            int type = idx >> 9;            // 0:Ah 1:Al 2:Bh 3:Bl
            int rem = idx & 511;
            int r = rem >> 2, c = rem & 3;  // 128 rows x 4 float4 (32 halves)
            const bf16* src;
            if (type == 0)      src = Ah + (size_t)(m0 + r) * K + kc + c * 8;
            else if (type == 1) src = Al + (size_t)(m0 + r) * K + kc + c * 8;
            else if (type == 2) src = Bh + (size_t)(n0 + r) * K + kc + c * 8;
            else                src = Bl + (size_t)(n0 + r) * K + kc + c * 8;
            uint32_t dst = dbase + type * GTILE + r * GROWB + c * 16;
            CP_ASYNC16(dst, src);
        }
    };

    const int arow = lane & 15;
    const uint32_t aoff = (uint32_t)(lane >> 4) * 16;
    const int brow = (lane & 7) + ((lane >> 4) << 3);
    const uint32_t boff = (uint32_t)((lane >> 3) & 1) * 16;

    load_stage(0, 0);
    CP_COMMIT();

    for (int kt = 0; kt < NT; kt++) {
        const int st = kt & 1;
        CP_WAIT0();
        __syncthreads();
        if (kt + 1 < NT) {
            load_stage(kt + 1, st ^ 1);
            CP_COMMIT();
        }
        const uint32_t ab = sbase + st * GSTAGE;
        const uint32_t bb = ab + 2 * GTILE;
#pragma unroll
        for (int ks = 0; ks < 2; ks++) {
            const uint32_t kb = ks * 32;
            uint32_t aH[4][4], aL[4][4], bH[2][4], bL[2][4];
#pragma unroll
            for (int mt = 0; mt < 4; mt++)
                asm volatile("ldmatrix.sync.aligned.m8n8.x4.shared.b16 {%0,%1,%2,%3}, [%4];"
                    : "=r"(aH[mt][0]), "=r"(aH[mt][1]), "=r"(aH[mt][2]), "=r"(aH[mt][3])
                    : "r"(ab + (uint32_t)(wm + mt * 16 + arow) * GROWB + aoff + kb));
#pragma unroll
            for (int gg = 0; gg < 2; gg++) {
                uint32_t ba_ = bb + (uint32_t)(wn + gg * 16 + brow) * GROWB + boff + kb;
                asm volatile("ldmatrix.sync.aligned.m8n8.x4.shared.b16 {%0,%1,%2,%3}, [%4];"
                    : "=r"(bH[gg][0]), "=r"(bH[gg][1]), "=r"(bH[gg][2]), "=r"(bH[gg][3])
                    : "r"(ba_));
                asm volatile("ldmatrix.sync.aligned.m8n8.x4.shared.b16 {%0,%1,%2,%3}, [%4];"
                    : "=r"(bL[gg][0]), "=r"(bL[gg][1]), "=r"(bL[gg][2]), "=r"(bL[gg][3])
                    : "r"(ba_ + GTILE));
            }
            // Pass 1: Ah * Bh
#pragma unroll
            for (int mt = 0; mt < 4; mt++)
#pragma unroll
                for (int nt = 0; nt < 4; nt++)
                    mma16816(acc[mt][nt], aH[mt], &bH[nt >> 1][(nt & 1) * 2]);
            // Hoisted aL reload: latency covered by Pass 2 below
#pragma unroll
            for (int mt = 0; mt < 4; mt++)
                asm volatile("ldmatrix.sync.aligned.m8n8.x4.shared.b16 {%0,%1,%2,%3}, [%4];"
                    : "=r"(aL[mt][0]), "=r"(aL[mt][1]), "=r"(aL[mt][2]), "=r"(aL[mt][3])
                    : "r"(ab + GTILE + (uint32_t)(wm + mt * 16 + arow) * GROWB + aoff + kb));
            // Pass 2: Ah * Bl
#pragma unroll
            for (int mt = 0; mt < 4; mt++)
#pragma unroll
                for (int nt = 0; nt < 4; nt++)
                    mma16816(acc[mt][nt], aH[mt], &bL[nt >> 1][(nt & 1) * 2]);
            // Pass 3: Al * Bh
#pragma unroll
            for (int mt = 0; mt < 4; mt++)
#pragma unroll
                for (int nt = 0; nt < 4; nt++)
                    mma16816(acc[mt][nt], aL[mt], &bH[nt >> 1][(nt & 1) * 2]);
        }
    }

#pragma unroll
    for (int mt = 0; mt < 4; mt++) {
        int row = m0 + wm + mt * 16 + (lane >> 2);
#pragma unroll
        for (int nt = 0; nt < 4; nt++) {
            int col = n0 + wn + nt * 8 + 2 * (lane & 3);
            *reinterpret_cast<float2*>(C + (size_t)row * N + col) =
                make_float2(acc[mt][nt][0], acc[mt][nt][1]);
            *reinterpret_cast<float2*>(C + (size_t)(row + 8) * N + col) =
                make_float2(acc[mt][nt][2], acc[mt][nt][3]);
        }
    }
}

// ---------------------------------------------------------------------------
// ba = hidden @ W_ba  : split-K (16 slices); reduce folded into conv_gate
// ---------------------------------------------------------------------------
constexpr int BA_SPLITS = 16;
constexpr int BA_KSEG   = EMB_D / BA_SPLITS;   // 128

__global__ __launch_bounds__(256) void ba_gemm_kernel(
    const float* __restrict__ A, const float* __restrict__ B)
{
    __shared__ float As[16][64];
    __shared__ float Bs[16][64];
    const int m0 = blockIdx.x * 64;
    const int z  = blockIdx.y;
    const int k0 = z * BA_KSEG;
    const int tid = threadIdx.x;
    const int tx = tid & 15, ty = tid >> 4;
    float acc[4][4] = {};

    for (int kk = 0; kk < BA_KSEG; kk += 16) {
        int r = tid >> 2, c4 = (tid & 3) * 4;
        float4 av = *reinterpret_cast<const float4*>(A + (size_t)(m0 + r) * EMB_D + k0 + kk + c4);
        As[c4 + 0][r] = av.x; As[c4 + 1][r] = av.y;
        As[c4 + 2][r] = av.z; As[c4 + 3][r] = av.w;
        int r2 = tid >> 4, c2 = (tid & 15) * 4;
        *reinterpret_cast<float4*>(&Bs[r2][c2]) =
            *reinterpret_cast<const float4*>(B + (size_t)(k0 + kk + r2) * 64 + c2);
        __syncthreads();
#pragma unroll
        for (int k = 0; k < 16; k++) {
            float ar[4], br[4];
#pragma unroll
            for (int i = 0; i < 4; i++) ar[i] = As[k][ty * 4 + i];
#pragma unroll
            for (int j = 0; j < 4; j++) br[j] = Bs[k][tx * 4 + j];
#pragma unroll
            for (int i = 0; i < 4; i++)
#pragma unroll
                for (int j = 0; j < 4; j++) acc[i][j] += ar[i] * br[j];
        }
        __syncthreads();
    }
    float* P = g_ba_part[z];
#pragma unroll
    for (int i = 0; i < 4; i++)
#pragma unroll
        for (int j = 0; j < 4; j++)
            P[(size_t)(m0 + ty * 4 + i) * 64 + tx * 4 + j] = acc[i][j];
}

// ---------------------------------------------------------------------------
// Depthwise causal conv (KSZ=4) + SiLU + gates, s-tiled x4:
// each block computes 4 consecutive positions; 7 loads serve 4 outputs.
// ---------------------------------------------------------------------------
__global__ __launch_bounds__(256) void conv_gate_kernel(
    const float* __restrict__ conv_w, const float* __restrict__ A_log,
    const float* __restrict__ dt_bias)
{
    const int s0 = blockIdx.x * 4;
    for (int c = threadIdx.x; c < 8192; c += 256) {
        int col;
        float* dst;
        int stride;
        if (c < 2048) {
            int kh = c >> 7, d = c & 127;
            col = kh * 768 + d;
            dst = &g_q[(size_t)s0 * KEY_DIM + c];
            stride = KEY_DIM;
        } else if (c < 4096) {
            int cc = c - 2048;
            int kh = cc >> 7, d = cc & 127;
            col = kh * 768 + 128 + d;
            dst = &g_k[(size_t)s0 * KEY_DIM + cc];
            stride = KEY_DIM;
        } else {
            int cc = c - 4096;
            int vh = cc >> 7, d = cc & 127;
            col = (vh >> 1) * 768 + 256 + (vh & 1) * 128 + d;
            dst = &g_v[(size_t)s0 * VAL_DIM + cc];
            stride = VAL_DIM;
        }
        float w0 = conv_w[0 * 8192 + c];
        float w1 = conv_w[1 * 8192 + c];
        float w2 = conv_w[2 * 8192 + c];
        float w3 = conv_w[3 * 8192 + c];
        float x[7];
#pragma unroll
        for (int t = 0; t < 7; t++) {
            int ss = s0 + t - 3;
            x[t] = (ss >= 0) ? g_qkvz[(size_t)ss * QKVZ_N + col] : 0.f;
        }
#pragma unroll
        for (int t = 0; t < 4; t++) {
            float acc = x[t] * w0 + x[t + 1] * w1 + x[t + 2] * w2 + x[t + 3] * w3;
            dst[(size_t)t * stride] = acc / (1.f + __expf(-acc));
        }
    }
    if (threadIdx.x < 128) {                  // 4 positions x 32 heads
        int s  = s0 + (threadIdx.x >> 5);
        int vh = threadIdx.x & 31;
        int kh = vh >> 1, j = vh & 1;
        float bg = 0.f, ag = 0.f;
#pragma unroll
        for (int z = 0; z < BA_SPLITS; z++) {
            bg += g_ba_part[z][s * 64 + kh * 4 + j];
            ag += g_ba_part[z][s * 64 + kh * 4 + 2 + j];
        }
        g_beta[s * N_VH + vh] = 1.f / (1.f + expf(-bg));
        float x = ag + dt_bias[vh];
        float sp = (x > 20.f) ? x : log1pf(expf(x));
        g_g[s * N_VH + vh] = -expf(A_log[vh]) * sp;
    }
}

// ---------------------------------------------------------------------------
// Intra-chunk kernel (decay table + fused dual matmul with f32x2 + warp scan)
// ---------------------------------------------------------------------------
constexpr int INTRA_SMEM = (64 * SKP * 2 + 64 * SDP * 2 + 64 * SYP + 192) * 4;

__global__ __launch_bounds__(256) void intra_kernel()
{
    extern __shared__ float sm[];
    float* sK  = sm;
    float* sQ  = sK + 64 * SKP;
    float* sD  = sQ + 64 * SKP;
    float* sL  = sD + 64 * SDP;
    float* sY  = sL + 64 * SDP;
    float* sgc = sY + 64 * SYP;
    float* sb  = sgc + 64;
    float* sE  = sb + 64;

    const int c   = blockIdx.x;
    const int h   = blockIdx.y;
    const int kh  = h >> 1;
    const int s0  = c * CH;
    const int tid = threadIdx.x;
    const size_t base = (size_t)(c * N_VH + h);

    for (int idx = tid; idx < CH * D_K; idx += 256) {
        int i = idx >> 7, d = idx & 127;
        sK[i * SKP + d] = g_k[(size_t)(s0 + i) * KEY_DIM + kh * D_K + d];
        sQ[i * SKP + d] = g_q[(size_t)(s0 + i) * KEY_DIM + kh * D_K + d] * RSQRT_DK;
    }
    if (tid < CH) {
        sb[tid]  = g_beta[(s0 + tid) * N_VH + h];
        sgc[tid] = g_g[(s0 + tid) * N_VH + h];
    }
    __syncthreads();

    // inclusive cumsum of g: one warp, 2 elems/lane
    if (tid < 32) {
        float x0 = sgc[2 * tid], x1 = sgc[2 * tid + 1];
        float s = x0 + x1;
#pragma unroll
        for (int off = 1; off < 32; off <<= 1) {
            float t = __shfl_up_sync(0xffffffffu, s, off);
            if (tid >= off) s += t;
        }
        float excl = s - (x0 + x1);
        sgc[2 * tid]     = excl + x0;
        sgc[2 * tid + 1] = excl + x0 + x1;
    }
    __syncthreads();

    // decay table + e^{gc}
    for (int idx = tid; idx < CH * CH; idx += 256) {
        int i = idx >> 6, j = idx & 63;
        sD[i * SDP + j] = (j <= i) ? __expf(sgc[i] - sgc[j]) : 0.f;
    }
    if (tid < CH) sE[tid] = __expf(sgc[tid]);
    __syncthreads();

    // fused dual matmul via f32x2 pairs over d: accL = k.k^T ; accA = q.k^T
    {
        const int ty = tid >> 4, tx = tid & 15;
        const int i0 = ty * 4, j0 = tx * 4;
        u64 accLp[4][4], accAp[4][4];
#pragma unroll
        for (int ii = 0; ii < 4; ii++)
#pragma unroll
            for (int jj = 0; jj < 4; jj++) { accLp[ii][jj] = 0ull; accAp[ii][jj] = 0ull; }
        for (int d = 0; d < D_K; d += 2) {
            u64 avp[4], qvp[4], bvp[4];
#pragma unroll
            for (int ii = 0; ii < 4; ii++) {
                avp[ii] = *reinterpret_cast<const u64*>(&sK[(i0 + ii) * SKP + d]);
                qvp[ii] = *reinterpret_cast<const u64*>(&sQ[(i0 + ii) * SKP + d]);
            }
#pragma unroll
            for (int jj = 0; jj < 4; jj++)
                bvp[jj] = *reinterpret_cast<const u64*>(&sK[(j0 + jj) * SKP + d]);
#pragma unroll
            for (int ii = 0; ii < 4; ii++)
#pragma unroll
                for (int jj = 0; jj < 4; jj++) {
                    fma2(accLp[ii][jj], avp[ii], bvp[jj]);
                    fma2(accAp[ii][jj], qvp[ii], bvp[jj]);
                }
        }
#pragma unroll
        for (int ii = 0; ii < 4; ii++)
#pragma unroll
            for (int jj = 0; jj < 4; jj++) {
                int i = i0 + ii, j = j0 + jj;
                float l0, l1, a0, a1;
                unpack2(accLp[ii][jj], l0, l1);
                unpack2(accAp[ii][jj], a0, a1);
                float dec = sD[i * SDP + j];
                sL[i * SDP + j] = (j < i) ? -(l0 + l1) * sb[i] * dec : 0.f;
                g_am[base * (CH * CH) + i * CH + j] = (a0 + a1) * dec;  // dec=0 for j>i
            }
    }

    // Y init: [v*beta | k*beta*e^{gc}]
    for (int idx = tid; idx < CH * 256; idx += 256) {
        int i = idx >> 8, cc = idx & 255;
        float v;
        if (cc < 128) v = g_v[(size_t)(s0 + i) * VAL_DIM + h * D_V + cc] * sb[i];
        else          v = sK[i * SKP + (cc - 128)] * sb[i] * sE[i];
        sY[i * SYP + cc] = v;
    }
    __syncthreads();

    // forward substitution (I-L)Y = B; one column per thread
    {
        const int cc = tid;
        for (int i = 1; i < CH; i++) {
            const float* lrow = &sL[i * SDP];
            float a0 = 0.f, a1 = 0.f, a2 = 0.f, a3 = 0.f;
            int j = 0;
            for (; j + 4 <= i; j += 4) {
                a0 += lrow[j + 0] * sY[(j + 0) * SYP + cc];
                a1 += lrow[j + 1] * sY[(j + 1) * SYP + cc];
                a2 += lrow[j + 2] * sY[(j + 2) * SYP + cc];
                a3 += lrow[j + 3] * sY[(j + 3) * SYP + cc];
            }
            for (; j < i; j++) a0 += lrow[j] * sY[j * SYP + cc];
            sY[i * SYP + cc] += (a0 + a1) + (a2 + a3);
        }
    }
    __syncthreads();

    // outputs
    for (int idx = tid; idx < CH * D_K; idx += 256) {
        int i = idx >> 7, d = idx & 127;
        g_vi [base * (CH * D_V) + idx] = sY[i * SYP + d];
        g_kcd[base * (CH * D_K) + idx] = sY[i * SYP + 128 + d];
        g_kg [base * (CH * D_K) + idx] = sK[i * SKP + d] * sD[63 * SDP + i];
        g_qg [base * (CH * D_K) + idx] = sQ[i * SKP + d] * sE[i];
    }
    if (tid == 0) g_egl[c * N_VH + h] = sE[63];
}

// ---------------------------------------------------------------------------
// Inter-chunk scan: grid (N_VH, 4 DV-groups), 512 threads (4 warps/SMSP).
// Each thread: 1 out-row x 4 cols (main), 1 state-row x 8 cols (update).
// ---------------------------------------------------------------------------
constexpr int SK2 = 132;   // kcd/qg/kg row stride
constexpr int SC2 = 68;    // am row stride
constexpr int SV2 = 36;    // vi row stride
constexpr int SST = 36;    // state row stride
constexpr int SBT = 36;    // v_new row stride
constexpr int SCAN_SMEM =
    (128 * SST + 3 * 64 * SK2 + 64 * SC2 + 64 * SV2 + 64 * SBT) * 4;

__global__ __launch_bounds__(512) void scan_kernel()
{
    extern __shared__ float sm[];
    float* sSt  = sm;                    // 128*36
    float* sKcd = sSt + 128 * SST;       // 64*132
    float* sQg  = sKcd + 64 * SK2;
    float* sKg  = sQg + 64 * SK2;
    float* sC   = sKg + 64 * SK2;        // 64*68
    float* sVi  = sC + 64 * SC2;         // 64*36
    float* sB   = sVi + 64 * SV2;        // 64*36

    const int h   = blockIdx.x;
    const int grp = blockIdx.y;
    const int e0  = grp * 32;
    const int tid = threadIdx.x;
    const int tx  = tid & 7;             // 8 col-groups of 4
    const int ty  = tid >> 3;            // 0..63 out-row
    const int stx = tid & 3;             // 4 col-groups of 8
    const int sty = tid >> 2;            // 0..127 state-row
    const uint32_t uKcd = smem_u32(sKcd), uQg = smem_u32(sQg), uKg = smem_u32(sKg);
    const uint32_t uC = smem_u32(sC), uVi = smem_u32(sVi);

    for (int idx = tid; idx < 128 * SST; idx += 512) sSt[idx] = 0.f;
    __syncthreads();

    auto issue_loads = [&](int c) {
        const size_t base = (size_t)(c * N_VH + h);
        const float* kcd = g_kcd + base * (CH * D_K);
        const float* qg  = g_qg  + base * (CH * D_K);
        const float* kg  = g_kg  + base * (CH * D_K);
        const float* am  = g_am  + base * (CH * CH);
        const float* vi  = g_vi  + base * (CH * D_V);
        // kcd/qg/kg: 2048 float4 each
#pragma unroll
        for (int it = 0; it < 4; it++) {
            int idx = tid + it * 512;
            int r = idx >> 5, q = idx & 31;
            CP_ASYNC16(uKcd + (uint32_t)(r * SK2 + q * 4) * 4, kcd + r * 128 + q * 4);
            CP_ASYNC16(uQg  + (uint32_t)(r * SK2 + q * 4) * 4, qg  + r * 128 + q * 4);
            CP_ASYNC16(uKg  + (uint32_t)(r * SK2 + q * 4) * 4, kg  + r * 128 + q * 4);
        }
        // am: 1024 float4
#pragma unroll
        for (int it = 0; it < 2; it++) {
            int idx = tid + it * 512;
            int r = idx >> 4, q = idx & 15;
            CP_ASYNC16(uC + (uint32_t)(r * SC2 + q * 4) * 4, am + r * 64 + q * 4);
        }
        // vi slice: 512 float4
        {
            int rr = tid >> 3, qq = tid & 7;
            CP_ASYNC16(uVi + (uint32_t)(rr * SV2 + qq * 4) * 4, vi + rr * 128 + e0 + qq * 4);
        }
        CP_COMMIT();
    };

    issue_loads(0);

    for (int c = 0; c < NCH; c++) {
        CP_WAIT0();
        __syncthreads();                           // S1: tiles ready

        // merged: kst = kcd@state ; ost = qg@state (1 row x 4 cols per thread)
        u64 kst[2] = {0ull, 0ull};
        u64 ost[2] = {0ull, 0ull};
        const float* kr = &sKcd[ty * SK2];
        const float* qr = &sQg[ty * SK2];
        for (int kd = 0; kd < D_K; kd++) {
            ulonglong2 b = *reinterpret_cast<const ulonglong2*>(&sSt[kd * SST + tx * 4]);
            float kv = kr[kd], qv = qr[kd];
            u64 pk = pack2(kv, kv);
            u64 pq = pack2(qv, qv);
            fma2(kst[0], pk, b.x); fma2(kst[1], pk, b.y);
            fma2(ost[0], pq, b.x); fma2(ost[1], pq, b.y);
        }
        // v_new = vi - kst -> sB
        {
            float k0, k1, k2, k3;
            unpack2(kst[0], k0, k1);
            unpack2(kst[1], k2, k3);
            const float* vr = &sVi[ty * SV2 + tx * 4];
            float* br = &sB[ty * SBT + tx * 4];
            br[0] = vr[0] - k0; br[1] = vr[1] - k1;
            br[2] = vr[2] - k2; br[3] = vr[3] - k3;
        }
        __syncthreads();                           // S2: v_new ready

        // ost += am @ v_new  (lower-triangular: j <= ty)
        {
            const float* crow = &sC[ty * SC2];
            for (int j = 0; j <= ty; j++) {
                ulonglong2 b = *reinterpret_cast<const ulonglong2*>(&sB[j * SBT + tx * 4]);
                float cv = crow[j];
                u64 p = pack2(cv, cv);
                fma2(ost[0], p, b.x); fma2(ost[1], p, b.y);
            }
        }
        // sacc = kg^T @ v_new (1 state-row x 8 cols per thread)
        u64 sacc[4] = {0ull, 0ull, 0ull, 0ull};
        for (int t = 0; t < CH; t++) {
            float a = sKg[t * SK2 + sty];
            u64 q = pack2(a, a);
            ulonglong2 b0 = *reinterpret_cast<const ulonglong2*>(&sB[t * SBT + stx * 8]);
            ulonglong2 b1 = *reinterpret_cast<const ulonglong2*>(&sB[t * SBT + stx * 8 + 4]);
            fma2(sacc[0], q, b0.x); fma2(sacc[1], q, b0.y);
            fma2(sacc[2], q, b1.x); fma2(sacc[3], q, b1.y);
        }
        const float egl = g_egl[c * N_VH + h];
        __syncthreads();                           // S3: all tile reads done

        if (c + 1 < NCH) issue_loads(c + 1);       // overlap with tail work

        // state = state*egl + sacc
        const u64 pe = pack2(egl, egl);
#pragma unroll
        for (int p = 0; p < 4; p++) {
            u64* sp = reinterpret_cast<u64*>(&sSt[sty * SST + stx * 8 + p * 2]);
            u64 st = *sp;
            fma2(sacc[p], pe, st);
            *sp = sacc[p];
        }
        // out store
        {
            ulonglong2 ov;
            ov.x = ost[0];
            ov.y = ost[1];
            *reinterpret_cast<ulonglong2*>(
                &g_core[(size_t)(c * CH + ty) * VAL_DIM + h * D_V + e0 + tx * 4]) = ov;
        }
    }
}

// ---------------------------------------------------------------------------
// Gated RMSNorm, fused bf16 hi/lo split output
// ---------------------------------------------------------------------------
__global__ __launch_bounds__(128) void norm_kernel(
    const float* __restrict__ norm_w, bf16* __restrict__ Ah, bf16* __restrict__ Al)
{
    __shared__ float red[4];
    const int s = blockIdx.x, vh = blockIdx.y;
    const int d = threadIdx.x;
    const int kh = vh >> 1;
    float x  = g_core[(size_t)(s * N_VH + vh) * D_V + d];
    float zv = g_qkvz[(size_t)s * QKVZ_N + kh * 768 + 512 + (vh & 1) * 128 + d];
    float xf = x * (zv / (1.f + __expf(-zv)));
    float v = xf * xf;
#pragma unroll
    for (int o = 16; o > 0; o >>= 1) v += __shfl_xor_sync(0xffffffffu, v, o);
    if ((d & 31) == 0) red[d >> 5] = v;
    __syncthreads();
    float var = (red[0] + red[1] + red[2] + red[3]) * (1.f / 128.f);
    float y = xf * rsqrtf(var + 1e-6f) * norm_w[d];
    size_t o = (size_t)s * VAL_DIM + vh * D_V + d;
    bf16 hy = __float2bfloat16_rn(y);
    Ah[o] = hy;
    Al[o] = __float2bfloat16_rn(y - __bfloat162float(hy));
}

// ---------------------------------------------------------------------------
// Launch (mma_gemm qkvz stays the 4th launch for ncu verification)
// ---------------------------------------------------------------------------
extern "C" void kernel_launch(void* const* d_in, const int* in_sizes, int n_in,
                              void* d_out, int out_size)
{
    const float* hidden  = (const float*)d_in[0];
    const float* W_qkvz  = (const float*)d_in[1];
    const float* W_ba    = (const float*)d_in[2];
    const float* conv_w  = (const float*)d_in[3];
    const float* A_log   = (const float*)d_in[4];
    const float* dt_bias = (const float*)d_in[5];
    const float* norm_w  = (const float*)d_in[6];
    const float* W_out   = (const float*)d_in[7];
    float* out = (float*)d_out;

    float *qkvz;
    bf16 *Ah, *Al, *Bh, *Bl;
    cudaGetSymbolAddress((void**)&qkvz, g_qkvz);
    cudaGetSymbolAddress((void**)&Ah,   g_Ah);
    cudaGetSymbolAddress((void**)&Al,   g_Al);
    cudaGetSymbolAddress((void**)&Bh,   g_Bh);
    cudaGetSymbolAddress((void**)&Bl,   g_Bl);

    static bool attr_set = false;
    if (!attr_set) {
        cudaFuncSetAttribute(intra_kernel, cudaFuncAttributeMaxDynamicSharedMemorySize, INTRA_SMEM);
        cudaFuncSetAttribute(scan_kernel,  cudaFuncAttributeMaxDynamicSharedMemorySize, SCAN_SMEM);
        cudaFuncSetAttribute(mma_gemm_kernel, cudaFuncAttributeMaxDynamicSharedMemorySize, GSMEM);
        attr_set = true;
    }

    // 1-2: operand prep for qkvz GEMM
    {
        size_t n4 = (size_t)S_LEN * EMB_D / 4;
        split_bf16_kernel<<<(unsigned)((n4 + 255) / 256), 256>>>(hidden, Ah, Al, n4);
        transpose_split_bf16<<<dim3(QKVZ_N / 32, EMB_D / 32), 256>>>(W_qkvz, Bh, Bl, EMB_D, QKVZ_N);
    }
    // 3: ba split-K partials (independent)
    ba_gemm_kernel<<<dim3(S_LEN / 64, BA_SPLITS), 256>>>(hidden, W_ba);
    // 4: qkvz GEMM  <- ncu captures this launch
    mma_gemm_kernel<<<dim3(S_LEN / 128, QKVZ_N / 128), 256, GSMEM>>>(
        Ah, Al, Bh, Bl, qkvz, S_LEN, QKVZ_N, EMB_D);
    // 5: conv + gates (s-tiled, ba reduce folded in)
    conv_gate_kernel<<<S_LEN / 4, 256>>>(conv_w, A_log, dt_bias);
    // 6-7: delta-rule core
    intra_kernel<<<dim3(NCH, N_VH), 256, INTRA_SMEM>>>();
    scan_kernel<<<dim3(N_VH, 4), 512, SCAN_SMEM>>>();
    // 8: gated RMSNorm + fused bf16 split
    norm_kernel<<<dim3(S_LEN, N_VH), 128>>>(norm_w, Ah, Al);
    // 9-10: out GEMM
    transpose_split_bf16<<<dim3(EMB_D / 32, VAL_DIM / 32), 256>>>(W_out, Bh, Bl, VAL_DIM, EMB_D);
    mma_gemm_kernel<<<dim3(S_LEN / 128, EMB_D / 128), 256, GSMEM>>>(
        Ah, Al, Bh, Bl, out, S_LEN, EMB_D, VAL_DIM);
}

// round 12
// speedup vs baseline: 1.0944x; 1.0944x over previous
#include <cuda_runtime.h>
#include <cuda_bf16.h>
#include <math.h>
#include <stdint.h>

using bf16 = __nv_bfloat16;
typedef unsigned long long u64;

// ---------------------------------------------------------------------------
// Problem constants
// ---------------------------------------------------------------------------
constexpr int S_LEN   = 4096;
constexpr int EMB_D   = 2048;
constexpr int N_KH    = 16;
constexpr int N_VH    = 32;
constexpr int D_K     = 128;
constexpr int D_V     = 128;
constexpr int KEY_DIM = N_KH * D_K;                  // 2048
constexpr int VAL_DIM = N_VH * D_V;                  // 4096
constexpr int QKVZ_N  = 2 * KEY_DIM + 2 * VAL_DIM;   // 12288
constexpr int CH      = 64;
constexpr int NCH     = S_LEN / CH;                  // 64
constexpr float RSQRT_DK = 0.08838834764831845f;

constexpr int SKP = 130;   // 64x128 f32 tiles (intra) -- even for 8B pairs
constexpr int SDP = 65;    // 64x64 tiles (intra)
constexpr int SYP = 257;   // 64x256 solve buffer

// ---------------------------------------------------------------------------
// Scratch (static device globals)
// ---------------------------------------------------------------------------
__device__ float g_qkvz[(size_t)S_LEN * QKVZ_N];
__device__ float g_ba_part[16][(size_t)S_LEN * 64];
__device__ float g_q   [(size_t)S_LEN * KEY_DIM];
__device__ float g_k   [(size_t)S_LEN * KEY_DIM];
__device__ float g_v   [(size_t)S_LEN * VAL_DIM];
__device__ float g_beta[(size_t)S_LEN * N_VH];
__device__ float g_g   [(size_t)S_LEN * N_VH];
__device__ float g_qg  [(size_t)NCH * N_VH * CH * D_K];
__device__ float g_kg  [(size_t)NCH * N_VH * CH * D_K];
__device__ float g_kcd [(size_t)NCH * N_VH * CH * D_K];
__device__ float g_vi  [(size_t)NCH * N_VH * CH * D_V];
__device__ float g_am  [(size_t)NCH * N_VH * CH * CH];
__device__ float g_egl [(size_t)NCH * N_VH];
__device__ float g_core[(size_t)S_LEN * VAL_DIM];
// bf16-split operands for the tensor-core GEMMs
__device__ bf16 g_Ah[(size_t)4096 * 4096];
__device__ bf16 g_Al[(size_t)4096 * 4096];
__device__ bf16 g_Bh[(size_t)12288 * 2048];   // [N][K] K-major
__device__ bf16 g_Bl[(size_t)12288 * 2048];

// ---------------------------------------------------------------------------
// Helpers
// ---------------------------------------------------------------------------
__device__ __forceinline__ uint32_t smem_u32(const void* p) {
    uint32_t a;
    asm("{ .reg .u64 t; cvta.to.shared.u64 t, %1; cvt.u32.u64 %0, t; }" : "=r"(a) : "l"(p));
    return a;
}
#define CP_ASYNC16(dst, src) \
    asm volatile("cp.async.cg.shared.global [%0], [%1], 16;" :: "r"(dst), "l"(src))
#define CP_COMMIT() asm volatile("cp.async.commit_group;")
#define CP_WAIT0()  asm volatile("cp.async.wait_group 0;")

// packed dual-fp32 FMA (sm_100+ baseline PTX)
__device__ __forceinline__ u64 pack2(float lo, float hi) {
    u64 r;
    asm("mov.b64 %0, {%1, %2};" : "=l"(r) : "f"(lo), "f"(hi));
    return r;
}
__device__ __forceinline__ void unpack2(u64 v, float& lo, float& hi) {
    asm("mov.b64 {%0, %1}, %2;" : "=f"(lo), "=f"(hi) : "l"(v));
}
__device__ __forceinline__ void fma2(u64& d, u64 a, u64 b) {
    asm("fma.rn.f32x2 %0, %1, %2, %0;" : "+l"(d) : "l"(a), "l"(b));
}

// Non-volatile MMA wrapper: pure register dataflow, compiler may reschedule.
__device__ __forceinline__ void mma16816(float* cc, const uint32_t* a, const uint32_t* b) {
    asm("mma.sync.aligned.m16n8k16.row.col.f32.bf16.bf16.f32 "
        "{%0,%1,%2,%3}, {%4,%5,%6,%7}, {%8,%9}, {%0,%1,%2,%3};"
        : "+f"(cc[0]), "+f"(cc[1]), "+f"(cc[2]), "+f"(cc[3])
        : "r"(a[0]), "r"(a[1]), "r"(a[2]), "r"(a[3]), "r"(b[0]), "r"(b[1]));
}

// ---------------------------------------------------------------------------
// Prep: elementwise bf16 hi/lo split of an fp32 matrix (layout preserved)
// ---------------------------------------------------------------------------
__global__ __launch_bounds__(256) void split_bf16_kernel(
    const float* __restrict__ X, bf16* __restrict__ Xh, bf16* __restrict__ Xl, size_t n4)
{
    size_t i = (size_t)blockIdx.x * 256 + threadIdx.x;
    if (i >= n4) return;
    float4 v = reinterpret_cast<const float4*>(X)[i];
    bf16 h0 = __float2bfloat16_rn(v.x);
    bf16 h1 = __float2bfloat16_rn(v.y);
    bf16 h2 = __float2bfloat16_rn(v.z);
    bf16 h3 = __float2bfloat16_rn(v.w);
    bf16 l0 = __float2bfloat16_rn(v.x - __bfloat162float(h0));
    bf16 l1 = __float2bfloat16_rn(v.y - __bfloat162float(h1));
    bf16 l2 = __float2bfloat16_rn(v.z - __bfloat162float(h2));
    bf16 l3 = __float2bfloat16_rn(v.w - __bfloat162float(h3));
    __nv_bfloat162* ph = reinterpret_cast<__nv_bfloat162*>(Xh);
    __nv_bfloat162* pl = reinterpret_cast<__nv_bfloat162*>(Xl);
    ph[2 * i]     = __nv_bfloat162(h0, h1);
    ph[2 * i + 1] = __nv_bfloat162(h2, h3);
    pl[2 * i]     = __nv_bfloat162(l0, l1);
    pl[2 * i + 1] = __nv_bfloat162(l2, l3);
}

// Prep: W[K][N] -> Bt[N][K] with bf16 hi/lo split
__global__ __launch_bounds__(256) void transpose_split_bf16(
    const float* __restrict__ W, bf16* __restrict__ Bh, bf16* __restrict__ Bl, int K, int N)
{
    __shared__ float t[32][33];
    const int n0 = blockIdx.x * 32, k0 = blockIdx.y * 32;
    const int c = threadIdx.x & 31, r0 = threadIdx.x >> 5;
#pragma unroll
    for (int i = 0; i < 4; i++)
        t[r0 + i * 8][c] = W[(size_t)(k0 + r0 + i * 8) * N + n0 + c];
    __syncthreads();
#pragma unroll
    for (int i = 0; i < 4; i++) {
        int rr = r0 + i * 8;
        float x = t[c][rr];
        bf16 h = __float2bfloat16_rn(x);
        size_t o = (size_t)(n0 + rr) * K + k0 + c;
        Bh[o] = h;
        Bl[o] = __float2bfloat16_rn(x - __bfloat162float(h));
    }
}

// ---------------------------------------------------------------------------
// bf16-split tensor-core GEMM via mma.sync (round-10 structure, measured 67.3%)
// CTA 128x128, BK=32, 256 threads, 2-stage cp.async, 2 CTAs/SM.
// ---------------------------------------------------------------------------
constexpr int GROWB  = 80;             // smem bytes per 32-half row (64 + 16 pad)
constexpr int GTILE  = 128 * GROWB;    // 10240 B per operand tile
constexpr int GSTAGE = 4 * GTILE;      // Ah, Al, Bh, Bl
constexpr int GSMEM  = 2 * GSTAGE;     // 81920 B

__global__ __launch_bounds__(256, 2) void mma_gemm_kernel(
    const bf16* __restrict__ Ah, const bf16* __restrict__ Al,
    const bf16* __restrict__ Bh, const bf16* __restrict__ Bl,
    float* __restrict__ C, int M, int N, int K)
{
    extern __shared__ char smg[];
    const uint32_t sbase = smem_u32(smg);
    const int tid  = threadIdx.x;
    const int lane = tid & 31, wid = tid >> 5;
    const int m0 = blockIdx.x * 128, n0 = blockIdx.y * 128;
    const int wm = (wid >> 2) * 64, wn = (wid & 3) * 32;
    const int NT = K / 32;

    float acc[4][4][4];
#pragma unroll
    for (int a = 0; a < 4; a++)
#pragma unroll
        for (int b = 0; b < 4; b++)
#pragma unroll
            for (int c = 0; c < 4; c++) acc[a][b][c] = 0.f;

    auto load_stage = [&](int kt, int st) {
        const int kc = kt * 32;
        const uint32_t dbase = sbase + st * GSTAGE;
#pragma unroll
        for (int it = 0; it < 8; it++) {
            int idx = tid + it * 256;
            int type = idx >> 9;            // 0:Ah 1:Al 2:Bh 3:Bl
            int rem = idx & 511;
            int r = rem >> 2, c = rem & 3;  // 128 rows x 4 float4 (32 halves)
            const bf16* src;
            if (type == 0)      src = Ah + (size_t)(m0 + r) * K + kc + c * 8;
            else if (type == 1) src = Al + (size_t)(m0 + r) * K + kc + c * 8;
            else if (type == 2) src = Bh + (size_t)(n0 + r) * K + kc + c * 8;
            else                src = Bl + (size_t)(n0 + r) * K + kc + c * 8;
            uint32_t dst = dbase + type * GTILE + r * GROWB + c * 16;
            CP_ASYNC16(dst, src);
        }
    };

    const int arow = lane & 15;
    const uint32_t aoff = (uint32_t)(lane >> 4) * 16;
    const int brow = (lane & 7) + ((lane >> 4) << 3);
    const uint32_t boff = (uint32_t)((lane >> 3) & 1) * 16;

    load_stage(0, 0);
    CP_COMMIT();

    for (int kt = 0; kt < NT; kt++) {
        const int st = kt & 1;
        CP_WAIT0();
        __syncthreads();
        if (kt + 1 < NT) {
            load_stage(kt + 1, st ^ 1);
            CP_COMMIT();
        }
        const uint32_t ab = sbase + st * GSTAGE;
        const uint32_t bb = ab + 2 * GTILE;
#pragma unroll
        for (int ks = 0; ks < 2; ks++) {
            const uint32_t kb = ks * 32;
            uint32_t aF[4][4], bH[2][4], bL[2][4];
#pragma unroll
            for (int mt = 0; mt < 4; mt++)
                asm volatile("ldmatrix.sync.aligned.m8n8.x4.shared.b16 {%0,%1,%2,%3}, [%4];"
                    : "=r"(aF[mt][0]), "=r"(aF[mt][1]), "=r"(aF[mt][2]), "=r"(aF[mt][3])
                    : "r"(ab + (uint32_t)(wm + mt * 16 + arow) * GROWB + aoff + kb));
#pragma unroll
            for (int gg = 0; gg < 2; gg++) {
                uint32_t ba_ = bb + (uint32_t)(wn + gg * 16 + brow) * GROWB + boff + kb;
                asm volatile("ldmatrix.sync.aligned.m8n8.x4.shared.b16 {%0,%1,%2,%3}, [%4];"
                    : "=r"(bH[gg][0]), "=r"(bH[gg][1]), "=r"(bH[gg][2]), "=r"(bH[gg][3])
                    : "r"(ba_));
                asm volatile("ldmatrix.sync.aligned.m8n8.x4.shared.b16 {%0,%1,%2,%3}, [%4];"
                    : "=r"(bL[gg][0]), "=r"(bL[gg][1]), "=r"(bL[gg][2]), "=r"(bL[gg][3])
                    : "r"(ba_ + GTILE));
            }
            // Pass 1: Ah * Bh
#pragma unroll
            for (int mt = 0; mt < 4; mt++)
#pragma unroll
                for (int nt = 0; nt < 4; nt++)
                    mma16816(acc[mt][nt], aF[mt], &bH[nt >> 1][(nt & 1) * 2]);
            // Pass 2: Ah * Bl
#pragma unroll
            for (int mt = 0; mt < 4; mt++)
#pragma unroll
                for (int nt = 0; nt < 4; nt++)
                    mma16816(acc[mt][nt], aF[mt], &bL[nt >> 1][(nt & 1) * 2]);
            // Reload A-low fragments, then Pass 3: Al * Bh
#pragma unroll
            for (int mt = 0; mt < 4; mt++)
                asm volatile("ldmatrix.sync.aligned.m8n8.x4.shared.b16 {%0,%1,%2,%3}, [%4];"
                    : "=r"(aF[mt][0]), "=r"(aF[mt][1]), "=r"(aF[mt][2]), "=r"(aF[mt][3])
                    : "r"(ab + GTILE + (uint32_t)(wm + mt * 16 + arow) * GROWB + aoff + kb));
#pragma unroll
            for (int mt = 0; mt < 4; mt++)
#pragma unroll
                for (int nt = 0; nt < 4; nt++)
                    mma16816(acc[mt][nt], aF[mt], &bH[nt >> 1][(nt & 1) * 2]);
        }
    }

#pragma unroll
    for (int mt = 0; mt < 4; mt++) {
        int row = m0 + wm + mt * 16 + (lane >> 2);
#pragma unroll
        for (int nt = 0; nt < 4; nt++) {
            int col = n0 + wn + nt * 8 + 2 * (lane & 3);
            *reinterpret_cast<float2*>(C + (size_t)row * N + col) =
                make_float2(acc[mt][nt][0], acc[mt][nt][1]);
            *reinterpret_cast<float2*>(C + (size_t)(row + 8) * N + col) =
                make_float2(acc[mt][nt][2], acc[mt][nt][3]);
        }
    }
}

// ---------------------------------------------------------------------------
// ba = hidden @ W_ba  : split-K (16 slices); reduce folded into conv_gate
// ---------------------------------------------------------------------------
constexpr int BA_SPLITS = 16;
constexpr int BA_KSEG   = EMB_D / BA_SPLITS;   // 128

__global__ __launch_bounds__(256) void ba_gemm_kernel(
    const float* __restrict__ A, const float* __restrict__ B)
{
    __shared__ float As[16][64];
    __shared__ float Bs[16][64];
    const int m0 = blockIdx.x * 64;
    const int z  = blockIdx.y;
    const int k0 = z * BA_KSEG;
    const int tid = threadIdx.x;
    const int tx = tid & 15, ty = tid >> 4;
    float acc[4][4] = {};

    for (int kk = 0; kk < BA_KSEG; kk += 16) {
        int r = tid >> 2, c4 = (tid & 3) * 4;
        float4 av = *reinterpret_cast<const float4*>(A + (size_t)(m0 + r) * EMB_D + k0 + kk + c4);
        As[c4 + 0][r] = av.x; As[c4 + 1][r] = av.y;
        As[c4 + 2][r] = av.z; As[c4 + 3][r] = av.w;
        int r2 = tid >> 4, c2 = (tid & 15) * 4;
        *reinterpret_cast<float4*>(&Bs[r2][c2]) =
            *reinterpret_cast<const float4*>(B + (size_t)(k0 + kk + r2) * 64 + c2);
        __syncthreads();
#pragma unroll
        for (int k = 0; k < 16; k++) {
            float ar[4], br[4];
#pragma unroll
            for (int i = 0; i < 4; i++) ar[i] = As[k][ty * 4 + i];
#pragma unroll
            for (int j = 0; j < 4; j++) br[j] = Bs[k][tx * 4 + j];
#pragma unroll
            for (int i = 0; i < 4; i++)
#pragma unroll
                for (int j = 0; j < 4; j++) acc[i][j] += ar[i] * br[j];
        }
        __syncthreads();
    }
    float* P = g_ba_part[z];
#pragma unroll
    for (int i = 0; i < 4; i++)
#pragma unroll
        for (int j = 0; j < 4; j++)
            P[(size_t)(m0 + ty * 4 + i) * 64 + tx * 4 + j] = acc[i][j];
}

// ---------------------------------------------------------------------------
// Depthwise causal conv (KSZ=4) + SiLU + gates, s-tiled x4:
// each block computes 4 consecutive positions; 7 loads serve 4 outputs.
// ---------------------------------------------------------------------------
__global__ __launch_bounds__(256) void conv_gate_kernel(
    const float* __restrict__ conv_w, const float* __restrict__ A_log,
    const float* __restrict__ dt_bias)
{
    const int s0 = blockIdx.x * 4;
    for (int c = threadIdx.x; c < 8192; c += 256) {
        int col;
        float* dst;
        int stride;
        if (c < 2048) {
            int kh = c >> 7, d = c & 127;
            col = kh * 768 + d;
            dst = &g_q[(size_t)s0 * KEY_DIM + c];
            stride = KEY_DIM;
        } else if (c < 4096) {
            int cc = c - 2048;
            int kh = cc >> 7, d = cc & 127;
            col = kh * 768 + 128 + d;
            dst = &g_k[(size_t)s0 * KEY_DIM + cc];
            stride = KEY_DIM;
        } else {
            int cc = c - 4096;
            int vh = cc >> 7, d = cc & 127;
            col = (vh >> 1) * 768 + 256 + (vh & 1) * 128 + d;
            dst = &g_v[(size_t)s0 * VAL_DIM + cc];
            stride = VAL_DIM;
        }
        float w0 = conv_w[0 * 8192 + c];
        float w1 = conv_w[1 * 8192 + c];
        float w2 = conv_w[2 * 8192 + c];
        float w3 = conv_w[3 * 8192 + c];
        float x[7];
#pragma unroll
        for (int t = 0; t < 7; t++) {
            int ss = s0 + t - 3;
            x[t] = (ss >= 0) ? g_qkvz[(size_t)ss * QKVZ_N + col] : 0.f;
        }
#pragma unroll
        for (int t = 0; t < 4; t++) {
            float acc = x[t] * w0 + x[t + 1] * w1 + x[t + 2] * w2 + x[t + 3] * w3;
            dst[(size_t)t * stride] = acc / (1.f + __expf(-acc));
        }
    }
    if (threadIdx.x < 128) {                  // 4 positions x 32 heads
        int s  = s0 + (threadIdx.x >> 5);
        int vh = threadIdx.x & 31;
        int kh = vh >> 1, j = vh & 1;
        float bg = 0.f, ag = 0.f;
#pragma unroll
        for (int z = 0; z < BA_SPLITS; z++) {
            bg += g_ba_part[z][s * 64 + kh * 4 + j];
            ag += g_ba_part[z][s * 64 + kh * 4 + 2 + j];
        }
        g_beta[s * N_VH + vh] = 1.f / (1.f + expf(-bg));
        float x = ag + dt_bias[vh];
        float sp = (x > 20.f) ? x : log1pf(expf(x));
        g_g[s * N_VH + vh] = -expf(A_log[vh]) * sp;
    }
}

// ---------------------------------------------------------------------------
// Intra-chunk kernel (decay table + fused dual matmul with f32x2 + warp scan)
// ---------------------------------------------------------------------------
constexpr int INTRA_SMEM = (64 * SKP * 2 + 64 * SDP * 2 + 64 * SYP + 192) * 4;

__global__ __launch_bounds__(256) void intra_kernel()
{
    extern __shared__ float sm[];
    float* sK  = sm;
    float* sQ  = sK + 64 * SKP;
    float* sD  = sQ + 64 * SKP;
    float* sL  = sD + 64 * SDP;
    float* sY  = sL + 64 * SDP;
    float* sgc = sY + 64 * SYP;
    float* sb  = sgc + 64;
    float* sE  = sb + 64;

    const int c   = blockIdx.x;
    const int h   = blockIdx.y;
    const int kh  = h >> 1;
    const int s0  = c * CH;
    const int tid = threadIdx.x;
    const size_t base = (size_t)(c * N_VH + h);

    for (int idx = tid; idx < CH * D_K; idx += 256) {
        int i = idx >> 7, d = idx & 127;
        sK[i * SKP + d] = g_k[(size_t)(s0 + i) * KEY_DIM + kh * D_K + d];
        sQ[i * SKP + d] = g_q[(size_t)(s0 + i) * KEY_DIM + kh * D_K + d] * RSQRT_DK;
    }
    if (tid < CH) {
        sb[tid]  = g_beta[(s0 + tid) * N_VH + h];
        sgc[tid] = g_g[(s0 + tid) * N_VH + h];
    }
    __syncthreads();

    // inclusive cumsum of g: one warp, 2 elems/lane
    if (tid < 32) {
        float x0 = sgc[2 * tid], x1 = sgc[2 * tid + 1];
        float s = x0 + x1;
#pragma unroll
        for (int off = 1; off < 32; off <<= 1) {
            float t = __shfl_up_sync(0xffffffffu, s, off);
            if (tid >= off) s += t;
        }
        float excl = s - (x0 + x1);
        sgc[2 * tid]     = excl + x0;
        sgc[2 * tid + 1] = excl + x0 + x1;
    }
    __syncthreads();

    // decay table + e^{gc}
    for (int idx = tid; idx < CH * CH; idx += 256) {
        int i = idx >> 6, j = idx & 63;
        sD[i * SDP + j] = (j <= i) ? __expf(sgc[i] - sgc[j]) : 0.f;
    }
    if (tid < CH) sE[tid] = __expf(sgc[tid]);
    __syncthreads();

    // fused dual matmul via f32x2 pairs over d: accL = k.k^T ; accA = q.k^T
    {
        const int ty = tid >> 4, tx = tid & 15;
        const int i0 = ty * 4, j0 = tx * 4;
        u64 accLp[4][4], accAp[4][4];
#pragma unroll
        for (int ii = 0; ii < 4; ii++)
#pragma unroll
            for (int jj = 0; jj < 4; jj++) { accLp[ii][jj] = 0ull; accAp[ii][jj] = 0ull; }
        for (int d = 0; d < D_K; d += 2) {
            u64 avp[4], qvp[4], bvp[4];
#pragma unroll
            for (int ii = 0; ii < 4; ii++) {
                avp[ii] = *reinterpret_cast<const u64*>(&sK[(i0 + ii) * SKP + d]);
                qvp[ii] = *reinterpret_cast<const u64*>(&sQ[(i0 + ii) * SKP + d]);
            }
#pragma unroll
            for (int jj = 0; jj < 4; jj++)
                bvp[jj] = *reinterpret_cast<const u64*>(&sK[(j0 + jj) * SKP + d]);
#pragma unroll
            for (int ii = 0; ii < 4; ii++)
#pragma unroll
                for (int jj = 0; jj < 4; jj++) {
                    fma2(accLp[ii][jj], avp[ii], bvp[jj]);
                    fma2(accAp[ii][jj], qvp[ii], bvp[jj]);
                }
        }
#pragma unroll
        for (int ii = 0; ii < 4; ii++)
#pragma unroll
            for (int jj = 0; jj < 4; jj++) {
                int i = i0 + ii, j = j0 + jj;
                float l0, l1, a0, a1;
                unpack2(accLp[ii][jj], l0, l1);
                unpack2(accAp[ii][jj], a0, a1);
                float dec = sD[i * SDP + j];
                sL[i * SDP + j] = (j < i) ? -(l0 + l1) * sb[i] * dec : 0.f;
                g_am[base * (CH * CH) + i * CH + j] = (a0 + a1) * dec;  // dec=0 for j>i
            }
    }

    // Y init: [v*beta | k*beta*e^{gc}]
    for (int idx = tid; idx < CH * 256; idx += 256) {
        int i = idx >> 8, cc = idx & 255;
        float v;
        if (cc < 128) v = g_v[(size_t)(s0 + i) * VAL_DIM + h * D_V + cc] * sb[i];
        else          v = sK[i * SKP + (cc - 128)] * sb[i] * sE[i];
        sY[i * SYP + cc] = v;
    }
    __syncthreads();

    // forward substitution (I-L)Y = B; one column per thread
    {
        const int cc = tid;
        for (int i = 1; i < CH; i++) {
            const float* lrow = &sL[i * SDP];
            float a0 = 0.f, a1 = 0.f, a2 = 0.f, a3 = 0.f;
            int j = 0;
            for (; j + 4 <= i; j += 4) {
                a0 += lrow[j + 0] * sY[(j + 0) * SYP + cc];
                a1 += lrow[j + 1] * sY[(j + 1) * SYP + cc];
                a2 += lrow[j + 2] * sY[(j + 2) * SYP + cc];
                a3 += lrow[j + 3] * sY[(j + 3) * SYP + cc];
            }
            for (; j < i; j++) a0 += lrow[j] * sY[j * SYP + cc];
            sY[i * SYP + cc] += (a0 + a1) + (a2 + a3);
        }
    }
    __syncthreads();

    // outputs
    for (int idx = tid; idx < CH * D_K; idx += 256) {
        int i = idx >> 7, d = idx & 127;
        g_vi [base * (CH * D_V) + idx] = sY[i * SYP + d];
        g_kcd[base * (CH * D_K) + idx] = sY[i * SYP + 128 + d];
        g_kg [base * (CH * D_K) + idx] = sK[i * SKP + d] * sD[63 * SDP + i];
        g_qg [base * (CH * D_K) + idx] = sQ[i * SKP + d] * sE[i];
    }
    if (tid == 0) g_egl[c * N_VH + h] = sE[63];
}

// ---------------------------------------------------------------------------
// Inter-chunk scan (round-10 version: 256 threads, triangular am loop)
// ---------------------------------------------------------------------------
constexpr int SK2 = 132;   // kcd/qg/kg row stride
constexpr int SC2 = 68;    // am row stride
constexpr int SV2 = 36;    // vi row stride
constexpr int SST = 36;    // state row stride
constexpr int SBT = 36;    // v_new row stride
constexpr int SCAN_SMEM =
    (128 * SST + 3 * 64 * SK2 + 64 * SC2 + 64 * SV2 + 64 * SBT) * 4;

__global__ __launch_bounds__(256) void scan_kernel()
{
    extern __shared__ float sm[];
    float* sSt  = sm;                    // 128*36
    float* sKcd = sSt + 128 * SST;       // 64*132
    float* sQg  = sKcd + 64 * SK2;
    float* sKg  = sQg + 64 * SK2;
    float* sC   = sKg + 64 * SK2;        // 64*68
    float* sVi  = sC + 64 * SC2;         // 64*36
    float* sB   = sVi + 64 * SV2;        // 64*36

    const int h   = blockIdx.x;
    const int grp = blockIdx.y;
    const int e0  = grp * 32;
    const int tid = threadIdx.x;
    const int tx  = tid & 7;
    const int ty  = tid >> 3;
    const uint32_t uKcd = smem_u32(sKcd), uQg = smem_u32(sQg), uKg = smem_u32(sKg);
    const uint32_t uC = smem_u32(sC), uVi = smem_u32(sVi);

    for (int idx = tid; idx < 128 * SST; idx += 256) sSt[idx] = 0.f;
    __syncthreads();

    auto issue_loads = [&](int c) {
        const size_t base = (size_t)(c * N_VH + h);
        const float* kcd = g_kcd + base * (CH * D_K);
        const float* qg  = g_qg  + base * (CH * D_K);
        const float* kg  = g_kg  + base * (CH * D_K);
        const float* am  = g_am  + base * (CH * CH);
        const float* vi  = g_vi  + base * (CH * D_V);
#pragma unroll
        for (int it = 0; it < 8; it++) {
            int idx = tid + it * 256;
            int r = idx >> 5, q = idx & 31;
            CP_ASYNC16(uKcd + (uint32_t)(r * SK2 + q * 4) * 4, kcd + r * 128 + q * 4);
            CP_ASYNC16(uQg  + (uint32_t)(r * SK2 + q * 4) * 4, qg  + r * 128 + q * 4);
            CP_ASYNC16(uKg  + (uint32_t)(r * SK2 + q * 4) * 4, kg  + r * 128 + q * 4);
        }
#pragma unroll
        for (int it = 0; it < 4; it++) {
            int idx = tid + it * 256;
            int r = idx >> 4, q = idx & 15;
            CP_ASYNC16(uC + (uint32_t)(r * SC2 + q * 4) * 4, am + r * 64 + q * 4);
        }
#pragma unroll
        for (int it = 0; it < 2; it++) {
            int i2 = tid + it * 256;
            int rr = i2 >> 3, qq = i2 & 7;
            CP_ASYNC16(uVi + (uint32_t)(rr * SV2 + qq * 4) * 4, vi + rr * 128 + e0 + qq * 4);
        }
        CP_COMMIT();
    };

    issue_loads(0);

    for (int c = 0; c < NCH; c++) {
        CP_WAIT0();
        __syncthreads();                           // S1: tiles ready

        // merged: kst = kcd@state ; ost = qg@state   (f32x2 packed)
        u64 kst[2][2] = {0ull, 0ull, 0ull, 0ull};
        u64 ost[2][2] = {0ull, 0ull, 0ull, 0ull};
        for (int kd = 0; kd < D_K; kd++) {
            ulonglong2 b = *reinterpret_cast<const ulonglong2*>(&sSt[kd * SST + tx * 4]);
            u64 pk0 = pack2(sKcd[(ty * 2 + 0) * SK2 + kd], sKcd[(ty * 2 + 0) * SK2 + kd]);
            u64 pk1 = pack2(sKcd[(ty * 2 + 1) * SK2 + kd], sKcd[(ty * 2 + 1) * SK2 + kd]);
            u64 pq0 = pack2(sQg[(ty * 2 + 0) * SK2 + kd], sQg[(ty * 2 + 0) * SK2 + kd]);
            u64 pq1 = pack2(sQg[(ty * 2 + 1) * SK2 + kd], sQg[(ty * 2 + 1) * SK2 + kd]);
            fma2(kst[0][0], pk0, b.x); fma2(kst[0][1], pk0, b.y);
            fma2(kst[1][0], pk1, b.x); fma2(kst[1][1], pk1, b.y);
            fma2(ost[0][0], pq0, b.x); fma2(ost[0][1], pq0, b.y);
            fma2(ost[1][0], pq1, b.x); fma2(ost[1][1], pq1, b.y);
        }
        // v_new = vi - kst  -> sB
#pragma unroll
        for (int ii = 0; ii < 2; ii++) {
            float k0, k1, k2, k3;
            unpack2(kst[ii][0], k0, k1);
            unpack2(kst[ii][1], k2, k3);
            const float* vr = &sVi[(ty * 2 + ii) * SV2 + tx * 4];
            float* br = &sB[(ty * 2 + ii) * SBT + tx * 4];
            br[0] = vr[0] - k0; br[1] = vr[1] - k1;
            br[2] = vr[2] - k2; br[3] = vr[3] - k3;
        }
        __syncthreads();                           // S2: v_new ready

        // ost += am @ v_new  (lower-triangular)
        {
            const int jmax = ty * 2 + 2;
            for (int j = 0; j < jmax; j++) {
                ulonglong2 b = *reinterpret_cast<const ulonglong2*>(&sB[j * SBT + tx * 4]);
                u64 p0 = pack2(sC[(ty * 2 + 0) * SC2 + j], sC[(ty * 2 + 0) * SC2 + j]);
                u64 p1 = pack2(sC[(ty * 2 + 1) * SC2 + j], sC[(ty * 2 + 1) * SC2 + j]);
                fma2(ost[0][0], p0, b.x); fma2(ost[0][1], p0, b.y);
                fma2(ost[1][0], p1, b.x); fma2(ost[1][1], p1, b.y);
            }
        }
        // sacc = kg^T @ v_new
        u64 sacc[4][2];
#pragma unroll
        for (int dd = 0; dd < 4; dd++) { sacc[dd][0] = 0ull; sacc[dd][1] = 0ull; }
        for (int t = 0; t < CH; t++) {
            ulonglong2 av = *reinterpret_cast<const ulonglong2*>(&sKg[t * SK2 + ty * 4]);
            ulonglong2 b  = *reinterpret_cast<const ulonglong2*>(&sB[t * SBT + tx * 4]);
            float a0, a1, a2, a3;
            unpack2(av.x, a0, a1);
            unpack2(av.y, a2, a3);
            u64 q0 = pack2(a0, a0), q1 = pack2(a1, a1);
            u64 q2 = pack2(a2, a2), q3 = pack2(a3, a3);
            fma2(sacc[0][0], q0, b.x); fma2(sacc[0][1], q0, b.y);
            fma2(sacc[1][0], q1, b.x); fma2(sacc[1][1], q1, b.y);
            fma2(sacc[2][0], q2, b.x); fma2(sacc[2][1], q2, b.y);
            fma2(sacc[3][0], q3, b.x); fma2(sacc[3][1], q3, b.y);
        }
        const float egl = g_egl[c * N_VH + h];
        __syncthreads();                           // S3: all tile reads done

        if (c + 1 < NCH) issue_loads(c + 1);       // overlap with tail work

        // state = state*egl + sacc
        const u64 pe = pack2(egl, egl);
#pragma unroll
        for (int dd = 0; dd < 4; dd++)
#pragma unroll
            for (int p = 0; p < 2; p++) {
                u64* sp = reinterpret_cast<u64*>(&sSt[(ty * 4 + dd) * SST + tx * 4 + p * 2]);
                u64 st = *sp;
                fma2(sacc[dd][p], pe, st);
                *sp = sacc[dd][p];
            }
        // out store
#pragma unroll
        for (int ii = 0; ii < 2; ii++) {
            ulonglong2 ov;
            ov.x = ost[ii][0];
            ov.y = ost[ii][1];
            *reinterpret_cast<ulonglong2*>(
                &g_core[(size_t)(c * CH + ty * 2 + ii) * VAL_DIM + h * D_V + e0 + tx * 4]) = ov;
        }
    }
}

// ---------------------------------------------------------------------------
// Gated RMSNorm, fused bf16 hi/lo split output
// ---------------------------------------------------------------------------
__global__ __launch_bounds__(128) void norm_kernel(
    const float* __restrict__ norm_w, bf16* __restrict__ Ah, bf16* __restrict__ Al)
{
    __shared__ float red[4];
    const int s = blockIdx.x, vh = blockIdx.y;
    const int d = threadIdx.x;
    const int kh = vh >> 1;
    float x  = g_core[(size_t)(s * N_VH + vh) * D_V + d];
    float zv = g_qkvz[(size_t)s * QKVZ_N + kh * 768 + 512 + (vh & 1) * 128 + d];
    float xf = x * (zv / (1.f + __expf(-zv)));
    float v = xf * xf;
#pragma unroll
    for (int o = 16; o > 0; o >>= 1) v += __shfl_xor_sync(0xffffffffu, v, o);
    if ((d & 31) == 0) red[d >> 5] = v;
    __syncthreads();
    float var = (red[0] + red[1] + red[2] + red[3]) * (1.f / 128.f);
    float y = xf * rsqrtf(var + 1e-6f) * norm_w[d];
    size_t o = (size_t)s * VAL_DIM + vh * D_V + d;
    bf16 hy = __float2bfloat16_rn(y);
    Ah[o] = hy;
    Al[o] = __float2bfloat16_rn(y - __bfloat162float(hy));
}

// ---------------------------------------------------------------------------
// Launch (mma_gemm qkvz stays the 4th launch for ncu verification)
// ---------------------------------------------------------------------------
extern "C" void kernel_launch(void* const* d_in, const int* in_sizes, int n_in,
                              void* d_out, int out_size)
{
    const float* hidden  = (const float*)d_in[0];
    const float* W_qkvz  = (const float*)d_in[1];
    const float* W_ba    = (const float*)d_in[2];
    const float* conv_w  = (const float*)d_in[3];
    const float* A_log   = (const float*)d_in[4];
    const float* dt_bias = (const float*)d_in[5];
    const float* norm_w  = (const float*)d_in[6];
    const float* W_out   = (const float*)d_in[7];
    float* out = (float*)d_out;

    float *qkvz;
    bf16 *Ah, *Al, *Bh, *Bl;
    cudaGetSymbolAddress((void**)&qkvz, g_qkvz);
    cudaGetSymbolAddress((void**)&Ah,   g_Ah);
    cudaGetSymbolAddress((void**)&Al,   g_Al);
    cudaGetSymbolAddress((void**)&Bh,   g_Bh);
    cudaGetSymbolAddress((void**)&Bl,   g_Bl);

    static bool attr_set = false;
    if (!attr_set) {
        cudaFuncSetAttribute(intra_kernel, cudaFuncAttributeMaxDynamicSharedMemorySize, INTRA_SMEM);
        cudaFuncSetAttribute(scan_kernel,  cudaFuncAttributeMaxDynamicSharedMemorySize, SCAN_SMEM);
        cudaFuncSetAttribute(mma_gemm_kernel, cudaFuncAttributeMaxDynamicSharedMemorySize, GSMEM);
        attr_set = true;
    }

    // 1-2: operand prep for qkvz GEMM
    {
        size_t n4 = (size_t)S_LEN * EMB_D / 4;
        split_bf16_kernel<<<(unsigned)((n4 + 255) / 256), 256>>>(hidden, Ah, Al, n4);
        transpose_split_bf16<<<dim3(QKVZ_N / 32, EMB_D / 32), 256>>>(W_qkvz, Bh, Bl, EMB_D, QKVZ_N);
    }
    // 3: ba split-K partials (independent)
    ba_gemm_kernel<<<dim3(S_LEN / 64, BA_SPLITS), 256>>>(hidden, W_ba);
    // 4: qkvz GEMM  <- ncu captures this launch
    mma_gemm_kernel<<<dim3(S_LEN / 128, QKVZ_N / 128), 256, GSMEM>>>(
        Ah, Al, Bh, Bl, qkvz, S_LEN, QKVZ_N, EMB_D);
    // 5: conv + gates (s-tiled x4, ba reduce folded in)
    conv_gate_kernel<<<S_LEN / 4, 256>>>(conv_w, A_log, dt_bias);
    // 6-7: delta-rule core
    intra_kernel<<<dim3(NCH, N_VH), 256, INTRA_SMEM>>>();
    scan_kernel<<<dim3(N_VH, 4), 256, SCAN_SMEM>>>();
    // 8: gated RMSNorm + fused bf16 split
    norm_kernel<<<dim3(S_LEN, N_VH), 128>>>(norm_w, Ah, Al);
    // 9-10: out GEMM
    transpose_split_bf16<<<dim3(EMB_D / 32, VAL_DIM / 32), 256>>>(W_out, Bh, Bl, VAL_DIM, EMB_D);
    mma_gemm_kernel<<<dim3(S_LEN / 128, EMB_D / 128), 256, GSMEM>>>(
        Ah, Al, Bh, Bl, out, S_LEN, EMB_D, VAL_DIM);
}

// round 13
// speedup vs baseline: 1.0958x; 1.0013x over previous
#include <cuda_runtime.h>
#include <cuda_bf16.h>
#include <math.h>
#include <stdint.h>

using bf16 = __nv_bfloat16;
typedef unsigned long long u64;

// ---------------------------------------------------------------------------
// Problem constants
// ---------------------------------------------------------------------------
constexpr int S_LEN   = 4096;
constexpr int EMB_D   = 2048;
constexpr int N_KH    = 16;
constexpr int N_VH    = 32;
constexpr int D_K     = 128;
constexpr int D_V     = 128;
constexpr int KEY_DIM = N_KH * D_K;                  // 2048
constexpr int VAL_DIM = N_VH * D_V;                  // 4096
constexpr int QKVZ_N  = 2 * KEY_DIM + 2 * VAL_DIM;   // 12288
constexpr int CH      = 64;
constexpr int NCH     = S_LEN / CH;                  // 64
constexpr float RSQRT_DK = 0.08838834764831845f;

constexpr int SKP = 130;   // 64x128 f32 tiles (intra) -- even for 8B pairs
constexpr int SDP = 65;    // 64x64 tiles (intra)
constexpr int SYP = 257;   // 64x256 solve buffer

// ---------------------------------------------------------------------------
// Scratch (static device globals)
// ---------------------------------------------------------------------------
__device__ float g_qkvz[(size_t)S_LEN * QKVZ_N];
__device__ float g_ba_part[16][(size_t)S_LEN * 64];
__device__ float g_q   [(size_t)S_LEN * KEY_DIM];
__device__ float g_k   [(size_t)S_LEN * KEY_DIM];
__device__ float g_v   [(size_t)S_LEN * VAL_DIM];
__device__ float g_beta[(size_t)S_LEN * N_VH];
__device__ float g_g   [(size_t)S_LEN * N_VH];
__device__ float g_qg  [(size_t)NCH * N_VH * CH * D_K];
__device__ float g_kg  [(size_t)NCH * N_VH * CH * D_K];
__device__ float g_kcd [(size_t)NCH * N_VH * CH * D_K];
__device__ float g_vi  [(size_t)NCH * N_VH * CH * D_V];
__device__ float g_am  [(size_t)NCH * N_VH * CH * CH];
__device__ float g_egl [(size_t)NCH * N_VH];
__device__ float g_core[(size_t)S_LEN * VAL_DIM];
// bf16-split operands for the tensor-core GEMMs
__device__ bf16 g_Ah[(size_t)4096 * 4096];
__device__ bf16 g_Al[(size_t)4096 * 4096];
__device__ bf16 g_Bh[(size_t)12288 * 2048];   // [N][K] K-major
__device__ bf16 g_Bl[(size_t)12288 * 2048];

// ---------------------------------------------------------------------------
// Helpers
// ---------------------------------------------------------------------------
__device__ __forceinline__ uint32_t smem_u32(const void* p) {
    uint32_t a;
    asm("{ .reg .u64 t; cvta.to.shared.u64 t, %1; cvt.u32.u64 %0, t; }" : "=r"(a) : "l"(p));
    return a;
}
#define CP_ASYNC16(dst, src) \
    asm volatile("cp.async.cg.shared.global [%0], [%1], 16;" :: "r"(dst), "l"(src))
#define CP_COMMIT() asm volatile("cp.async.commit_group;")
#define CP_WAIT0()  asm volatile("cp.async.wait_group 0;")

// packed dual-fp32 FMA (sm_100+ baseline PTX)
__device__ __forceinline__ u64 pack2(float lo, float hi) {
    u64 r;
    asm("mov.b64 %0, {%1, %2};" : "=l"(r) : "f"(lo), "f"(hi));
    return r;
}
__device__ __forceinline__ void unpack2(u64 v, float& lo, float& hi) {
    asm("mov.b64 {%0, %1}, %2;" : "=f"(lo), "=f"(hi) : "l"(v));
}
__device__ __forceinline__ void fma2(u64& d, u64 a, u64 b) {
    asm("fma.rn.f32x2 %0, %1, %2, %0;" : "+l"(d) : "l"(a), "l"(b));
}

// Non-volatile MMA wrapper: pure register dataflow, compiler may reschedule.
__device__ __forceinline__ void mma16816(float* cc, const uint32_t* a, const uint32_t* b) {
    asm("mma.sync.aligned.m16n8k16.row.col.f32.bf16.bf16.f32 "
        "{%0,%1,%2,%3}, {%4,%5,%6,%7}, {%8,%9}, {%0,%1,%2,%3};"
        : "+f"(cc[0]), "+f"(cc[1]), "+f"(cc[2]), "+f"(cc[3])
        : "r"(a[0]), "r"(a[1]), "r"(a[2]), "r"(a[3]), "r"(b[0]), "r"(b[1]));
}

// ---------------------------------------------------------------------------
// Prep: elementwise bf16 hi/lo split of an fp32 matrix (layout preserved)
// ---------------------------------------------------------------------------
__global__ __launch_bounds__(256) void split_bf16_kernel(
    const float* __restrict__ X, bf16* __restrict__ Xh, bf16* __restrict__ Xl, size_t n4)
{
    size_t i = (size_t)blockIdx.x * 256 + threadIdx.x;
    if (i >= n4) return;
    float4 v = reinterpret_cast<const float4*>(X)[i];
    bf16 h0 = __float2bfloat16_rn(v.x);
    bf16 h1 = __float2bfloat16_rn(v.y);
    bf16 h2 = __float2bfloat16_rn(v.z);
    bf16 h3 = __float2bfloat16_rn(v.w);
    bf16 l0 = __float2bfloat16_rn(v.x - __bfloat162float(h0));
    bf16 l1 = __float2bfloat16_rn(v.y - __bfloat162float(h1));
    bf16 l2 = __float2bfloat16_rn(v.z - __bfloat162float(h2));
    bf16 l3 = __float2bfloat16_rn(v.w - __bfloat162float(h3));
    __nv_bfloat162* ph = reinterpret_cast<__nv_bfloat162*>(Xh);
    __nv_bfloat162* pl = reinterpret_cast<__nv_bfloat162*>(Xl);
    ph[2 * i]     = __nv_bfloat162(h0, h1);
    ph[2 * i + 1] = __nv_bfloat162(h2, h3);
    pl[2 * i]     = __nv_bfloat162(l0, l1);
    pl[2 * i + 1] = __nv_bfloat162(l2, l3);
}

// Prep: W[K][N] -> Bt[N][K] with bf16 hi/lo split
__global__ __launch_bounds__(256) void transpose_split_bf16(
    const float* __restrict__ W, bf16* __restrict__ Bh, bf16* __restrict__ Bl, int K, int N)
{
    __shared__ float t[32][33];
    const int n0 = blockIdx.x * 32, k0 = blockIdx.y * 32;
    const int c = threadIdx.x & 31, r0 = threadIdx.x >> 5;
#pragma unroll
    for (int i = 0; i < 4; i++)
        t[r0 + i * 8][c] = W[(size_t)(k0 + r0 + i * 8) * N + n0 + c];
    __syncthreads();
#pragma unroll
    for (int i = 0; i < 4; i++) {
        int rr = r0 + i * 8;
        float x = t[c][rr];
        bf16 h = __float2bfloat16_rn(x);
        size_t o = (size_t)(n0 + rr) * K + k0 + c;
        Bh[o] = h;
        Bl[o] = __float2bfloat16_rn(x - __bfloat162float(h));
    }
}

// ---------------------------------------------------------------------------
// bf16-split tensor-core GEMM via mma.sync (round-10/12 structure, measured)
// CTA 128x128, BK=32, 256 threads, 2-stage cp.async, 2 CTAs/SM.
// ---------------------------------------------------------------------------
constexpr int GROWB  = 80;             // smem bytes per 32-half row (64 + 16 pad)
constexpr int GTILE  = 128 * GROWB;    // 10240 B per operand tile
constexpr int GSTAGE = 4 * GTILE;      // Ah, Al, Bh, Bl
constexpr int GSMEM  = 2 * GSTAGE;     // 81920 B

__global__ __launch_bounds__(256, 2) void mma_gemm_kernel(
    const bf16* __restrict__ Ah, const bf16* __restrict__ Al,
    const bf16* __restrict__ Bh, const bf16* __restrict__ Bl,
    float* __restrict__ C, int M, int N, int K)
{
    extern __shared__ char smg[];
    const uint32_t sbase = smem_u32(smg);
    const int tid  = threadIdx.x;
    const int lane = tid & 31, wid = tid >> 5;
    const int m0 = blockIdx.x * 128, n0 = blockIdx.y * 128;
    const int wm = (wid >> 2) * 64, wn = (wid & 3) * 32;
    const int NT = K / 32;

    float acc[4][4][4];
#pragma unroll
    for (int a = 0; a < 4; a++)
#pragma unroll
        for (int b = 0; b < 4; b++)
#pragma unroll
            for (int c = 0; c < 4; c++) acc[a][b][c] = 0.f;

    auto load_stage = [&](int kt, int st) {
        const int kc = kt * 32;
        const uint32_t dbase = sbase + st * GSTAGE;
#pragma unroll
        for (int it = 0; it < 8; it++) {
            int idx = tid + it * 256;
            int type = idx >> 9;            // 0:Ah 1:Al 2:Bh 3:Bl
            int rem = idx & 511;
            int r = rem >> 2, c = rem & 3;  // 128 rows x 4 float4 (32 halves)
            const bf16* src;
            if (type == 0)      src = Ah + (size_t)(m0 + r) * K + kc + c * 8;
            else if (type == 1) src = Al + (size_t)(m0 + r) * K + kc + c * 8;
            else if (type == 2) src = Bh + (size_t)(n0 + r) * K + kc + c * 8;
            else                src = Bl + (size_t)(n0 + r) * K + kc + c * 8;
            uint32_t dst = dbase + type * GTILE + r * GROWB + c * 16;
            CP_ASYNC16(dst, src);
        }
    };

    const int arow = lane & 15;
    const uint32_t aoff = (uint32_t)(lane >> 4) * 16;
    const int brow = (lane & 7) + ((lane >> 4) << 3);
    const uint32_t boff = (uint32_t)((lane >> 3) & 1) * 16;

    load_stage(0, 0);
    CP_COMMIT();

    for (int kt = 0; kt < NT; kt++) {
        const int st = kt & 1;
        CP_WAIT0();
        __syncthreads();
        if (kt + 1 < NT) {
            load_stage(kt + 1, st ^ 1);
            CP_COMMIT();
        }
        const uint32_t ab = sbase + st * GSTAGE;
        const uint32_t bb = ab + 2 * GTILE;
#pragma unroll
        for (int ks = 0; ks < 2; ks++) {
            const uint32_t kb = ks * 32;
            uint32_t aF[4][4], bH[2][4], bL[2][4];
#pragma unroll
            for (int mt = 0; mt < 4; mt++)
                asm volatile("ldmatrix.sync.aligned.m8n8.x4.shared.b16 {%0,%1,%2,%3}, [%4];"
                    : "=r"(aF[mt][0]), "=r"(aF[mt][1]), "=r"(aF[mt][2]), "=r"(aF[mt][3])
                    : "r"(ab + (uint32_t)(wm + mt * 16 + arow) * GROWB + aoff + kb));
#pragma unroll
            for (int gg = 0; gg < 2; gg++) {
                uint32_t ba_ = bb + (uint32_t)(wn + gg * 16 + brow) * GROWB + boff + kb;
                asm volatile("ldmatrix.sync.aligned.m8n8.x4.shared.b16 {%0,%1,%2,%3}, [%4];"
                    : "=r"(bH[gg][0]), "=r"(bH[gg][1]), "=r"(bH[gg][2]), "=r"(bH[gg][3])
                    : "r"(ba_));
                asm volatile("ldmatrix.sync.aligned.m8n8.x4.shared.b16 {%0,%1,%2,%3}, [%4];"
                    : "=r"(bL[gg][0]), "=r"(bL[gg][1]), "=r"(bL[gg][2]), "=r"(bL[gg][3])
                    : "r"(ba_ + GTILE));
            }
            // Pass 1: Ah * Bh
#pragma unroll
            for (int mt = 0; mt < 4; mt++)
#pragma unroll
                for (int nt = 0; nt < 4; nt++)
                    mma16816(acc[mt][nt], aF[mt], &bH[nt >> 1][(nt & 1) * 2]);
            // Pass 2: Ah * Bl
#pragma unroll
            for (int mt = 0; mt < 4; mt++)
#pragma unroll
                for (int nt = 0; nt < 4; nt++)
                    mma16816(acc[mt][nt], aF[mt], &bL[nt >> 1][(nt & 1) * 2]);
            // Reload A-low fragments, then Pass 3: Al * Bh
#pragma unroll
            for (int mt = 0; mt < 4; mt++)
                asm volatile("ldmatrix.sync.aligned.m8n8.x4.shared.b16 {%0,%1,%2,%3}, [%4];"
                    : "=r"(aF[mt][0]), "=r"(aF[mt][1]), "=r"(aF[mt][2]), "=r"(aF[mt][3])
                    : "r"(ab + GTILE + (uint32_t)(wm + mt * 16 + arow) * GROWB + aoff + kb));
#pragma unroll
            for (int mt = 0; mt < 4; mt++)
#pragma unroll
                for (int nt = 0; nt < 4; nt++)
                    mma16816(acc[mt][nt], aF[mt], &bH[nt >> 1][(nt & 1) * 2]);
        }
    }

#pragma unroll
    for (int mt = 0; mt < 4; mt++) {
        int row = m0 + wm + mt * 16 + (lane >> 2);
#pragma unroll
        for (int nt = 0; nt < 4; nt++) {
            int col = n0 + wn + nt * 8 + 2 * (lane & 3);
            *reinterpret_cast<float2*>(C + (size_t)row * N + col) =
                make_float2(acc[mt][nt][0], acc[mt][nt][1]);
            *reinterpret_cast<float2*>(C + (size_t)(row + 8) * N + col) =
                make_float2(acc[mt][nt][2], acc[mt][nt][3]);
        }
    }
}

// ---------------------------------------------------------------------------
// ba = hidden @ W_ba  : split-K (16 slices); reduce folded into conv_gate
// ---------------------------------------------------------------------------
constexpr int BA_SPLITS = 16;
constexpr int BA_KSEG   = EMB_D / BA_SPLITS;   // 128

__global__ __launch_bounds__(256) void ba_gemm_kernel(
    const float* __restrict__ A, const float* __restrict__ B)
{
    __shared__ float As[16][64];
    __shared__ float Bs[16][64];
    const int m0 = blockIdx.x * 64;
    const int z  = blockIdx.y;
    const int k0 = z * BA_KSEG;
    const int tid = threadIdx.x;
    const int tx = tid & 15, ty = tid >> 4;
    float acc[4][4] = {};

    for (int kk = 0; kk < BA_KSEG; kk += 16) {
        int r = tid >> 2, c4 = (tid & 3) * 4;
        float4 av = *reinterpret_cast<const float4*>(A + (size_t)(m0 + r) * EMB_D + k0 + kk + c4);
        As[c4 + 0][r] = av.x; As[c4 + 1][r] = av.y;
        As[c4 + 2][r] = av.z; As[c4 + 3][r] = av.w;
        int r2 = tid >> 4, c2 = (tid & 15) * 4;
        *reinterpret_cast<float4*>(&Bs[r2][c2]) =
            *reinterpret_cast<const float4*>(B + (size_t)(k0 + kk + r2) * 64 + c2);
        __syncthreads();
#pragma unroll
        for (int k = 0; k < 16; k++) {
            float ar[4], br[4];
#pragma unroll
            for (int i = 0; i < 4; i++) ar[i] = As[k][ty * 4 + i];
#pragma unroll
            for (int j = 0; j < 4; j++) br[j] = Bs[k][tx * 4 + j];
#pragma unroll
            for (int i = 0; i < 4; i++)
#pragma unroll
                for (int j = 0; j < 4; j++) acc[i][j] += ar[i] * br[j];
        }
        __syncthreads();
    }
    float* P = g_ba_part[z];
#pragma unroll
    for (int i = 0; i < 4; i++)
#pragma unroll
        for (int j = 0; j < 4; j++)
            P[(size_t)(m0 + ty * 4 + i) * 64 + tx * 4 + j] = acc[i][j];
}

// ---------------------------------------------------------------------------
// Depthwise causal conv (KSZ=4) + SiLU + gates, s-tiled x4
// ---------------------------------------------------------------------------
__global__ __launch_bounds__(256) void conv_gate_kernel(
    const float* __restrict__ conv_w, const float* __restrict__ A_log,
    const float* __restrict__ dt_bias)
{
    const int s0 = blockIdx.x * 4;
    for (int c = threadIdx.x; c < 8192; c += 256) {
        int col;
        float* dst;
        int stride;
        if (c < 2048) {
            int kh = c >> 7, d = c & 127;
            col = kh * 768 + d;
            dst = &g_q[(size_t)s0 * KEY_DIM + c];
            stride = KEY_DIM;
        } else if (c < 4096) {
            int cc = c - 2048;
            int kh = cc >> 7, d = cc & 127;
            col = kh * 768 + 128 + d;
            dst = &g_k[(size_t)s0 * KEY_DIM + cc];
            stride = KEY_DIM;
        } else {
            int cc = c - 4096;
            int vh = cc >> 7, d = cc & 127;
            col = (vh >> 1) * 768 + 256 + (vh & 1) * 128 + d;
            dst = &g_v[(size_t)s0 * VAL_DIM + cc];
            stride = VAL_DIM;
        }
        float w0 = conv_w[0 * 8192 + c];
        float w1 = conv_w[1 * 8192 + c];
        float w2 = conv_w[2 * 8192 + c];
        float w3 = conv_w[3 * 8192 + c];
        float x[7];
#pragma unroll
        for (int t = 0; t < 7; t++) {
            int ss = s0 + t - 3;
            x[t] = (ss >= 0) ? g_qkvz[(size_t)ss * QKVZ_N + col] : 0.f;
        }
#pragma unroll
        for (int t = 0; t < 4; t++) {
            float acc = x[t] * w0 + x[t + 1] * w1 + x[t + 2] * w2 + x[t + 3] * w3;
            dst[(size_t)t * stride] = acc / (1.f + __expf(-acc));
        }
    }
    if (threadIdx.x < 128) {                  // 4 positions x 32 heads
        int s  = s0 + (threadIdx.x >> 5);
        int vh = threadIdx.x & 31;
        int kh = vh >> 1, j = vh & 1;
        float bg = 0.f, ag = 0.f;
#pragma unroll
        for (int z = 0; z < BA_SPLITS; z++) {
            bg += g_ba_part[z][s * 64 + kh * 4 + j];
            ag += g_ba_part[z][s * 64 + kh * 4 + 2 + j];
        }
        g_beta[s * N_VH + vh] = 1.f / (1.f + expf(-bg));
        float x = ag + dt_bias[vh];
        float sp = (x > 20.f) ? x : log1pf(expf(x));
        g_g[s * N_VH + vh] = -expf(A_log[vh]) * sp;
    }
}

// ---------------------------------------------------------------------------
// Intra-chunk kernel (decay table + fused dual matmul with f32x2 + warp scan)
// ---------------------------------------------------------------------------
constexpr int INTRA_SMEM = (64 * SKP * 2 + 64 * SDP * 2 + 64 * SYP + 192) * 4;

__global__ __launch_bounds__(256) void intra_kernel()
{
    extern __shared__ float sm[];
    float* sK  = sm;
    float* sQ  = sK + 64 * SKP;
    float* sD  = sQ + 64 * SKP;
    float* sL  = sD + 64 * SDP;
    float* sY  = sL + 64 * SDP;
    float* sgc = sY + 64 * SYP;
    float* sb  = sgc + 64;
    float* sE  = sb + 64;

    const int c   = blockIdx.x;
    const int h   = blockIdx.y;
    const int kh  = h >> 1;
    const int s0  = c * CH;
    const int tid = threadIdx.x;
    const size_t base = (size_t)(c * N_VH + h);

    for (int idx = tid; idx < CH * D_K; idx += 256) {
        int i = idx >> 7, d = idx & 127;
        sK[i * SKP + d] = g_k[(size_t)(s0 + i) * KEY_DIM + kh * D_K + d];
        sQ[i * SKP + d] = g_q[(size_t)(s0 + i) * KEY_DIM + kh * D_K + d] * RSQRT_DK;
    }
    if (tid < CH) {
        sb[tid]  = g_beta[(s0 + tid) * N_VH + h];
        sgc[tid] = g_g[(s0 + tid) * N_VH + h];
    }
    __syncthreads();

    // inclusive cumsum of g: one warp, 2 elems/lane
    if (tid < 32) {
        float x0 = sgc[2 * tid], x1 = sgc[2 * tid + 1];
        float s = x0 + x1;
#pragma unroll
        for (int off = 1; off < 32; off <<= 1) {
            float t = __shfl_up_sync(0xffffffffu, s, off);
            if (tid >= off) s += t;
        }
        float excl = s - (x0 + x1);
        sgc[2 * tid]     = excl + x0;
        sgc[2 * tid + 1] = excl + x0 + x1;
    }
    __syncthreads();

    // decay table + e^{gc}
    for (int idx = tid; idx < CH * CH; idx += 256) {
        int i = idx >> 6, j = idx & 63;
        sD[i * SDP + j] = (j <= i) ? __expf(sgc[i] - sgc[j]) : 0.f;
    }
    if (tid < CH) sE[tid] = __expf(sgc[tid]);
    __syncthreads();

    // fused dual matmul via f32x2 pairs over d: accL = k.k^T ; accA = q.k^T
    {
        const int ty = tid >> 4, tx = tid & 15;
        const int i0 = ty * 4, j0 = tx * 4;
        u64 accLp[4][4], accAp[4][4];
#pragma unroll
        for (int ii = 0; ii < 4; ii++)
#pragma unroll
            for (int jj = 0; jj < 4; jj++) { accLp[ii][jj] = 0ull; accAp[ii][jj] = 0ull; }
        for (int d = 0; d < D_K; d += 2) {
            u64 avp[4], qvp[4], bvp[4];
#pragma unroll
            for (int ii = 0; ii < 4; ii++) {
                avp[ii] = *reinterpret_cast<const u64*>(&sK[(i0 + ii) * SKP + d]);
                qvp[ii] = *reinterpret_cast<const u64*>(&sQ[(i0 + ii) * SKP + d]);
            }
#pragma unroll
            for (int jj = 0; jj < 4; jj++)
                bvp[jj] = *reinterpret_cast<const u64*>(&sK[(j0 + jj) * SKP + d]);
#pragma unroll
            for (int ii = 0; ii < 4; ii++)
#pragma unroll
                for (int jj = 0; jj < 4; jj++) {
                    fma2(accLp[ii][jj], avp[ii], bvp[jj]);
                    fma2(accAp[ii][jj], qvp[ii], bvp[jj]);
                }
        }
#pragma unroll
        for (int ii = 0; ii < 4; ii++)
#pragma unroll
            for (int jj = 0; jj < 4; jj++) {
                int i = i0 + ii, j = j0 + jj;
                float l0, l1, a0, a1;
                unpack2(accLp[ii][jj], l0, l1);
                unpack2(accAp[ii][jj], a0, a1);
                float dec = sD[i * SDP + j];
                sL[i * SDP + j] = (j < i) ? -(l0 + l1) * sb[i] * dec : 0.f;
                g_am[base * (CH * CH) + i * CH + j] = (a0 + a1) * dec;  // dec=0 for j>i
            }
    }

    // Y init: [v*beta | k*beta*e^{gc}]
    for (int idx = tid; idx < CH * 256; idx += 256) {
        int i = idx >> 8, cc = idx & 255;
        float v;
        if (cc < 128) v = g_v[(size_t)(s0 + i) * VAL_DIM + h * D_V + cc] * sb[i];
        else          v = sK[i * SKP + (cc - 128)] * sb[i] * sE[i];
        sY[i * SYP + cc] = v;
    }
    __syncthreads();

    // forward substitution (I-L)Y = B; one column per thread
    {
        const int cc = tid;
        for (int i = 1; i < CH; i++) {
            const float* lrow = &sL[i * SDP];
            float a0 = 0.f, a1 = 0.f, a2 = 0.f, a3 = 0.f;
            int j = 0;
            for (; j + 4 <= i; j += 4) {
                a0 += lrow[j + 0] * sY[(j + 0) * SYP + cc];
                a1 += lrow[j + 1] * sY[(j + 1) * SYP + cc];
                a2 += lrow[j + 2] * sY[(j + 2) * SYP + cc];
                a3 += lrow[j + 3] * sY[(j + 3) * SYP + cc];
            }
            for (; j < i; j++) a0 += lrow[j] * sY[j * SYP + cc];
            sY[i * SYP + cc] += (a0 + a1) + (a2 + a3);
        }
    }
    __syncthreads();

    // outputs
    for (int idx = tid; idx < CH * D_K; idx += 256) {
        int i = idx >> 7, d = idx & 127;
        g_vi [base * (CH * D_V) + idx] = sY[i * SYP + d];
        g_kcd[base * (CH * D_K) + idx] = sY[i * SYP + 128 + d];
        g_kg [base * (CH * D_K) + idx] = sK[i * SKP + d] * sD[63 * SDP + i];
        g_qg [base * (CH * D_K) + idx] = sQ[i * SKP + d] * sE[i];
    }
    if (tid == 0) g_egl[c * N_VH + h] = sE[63];
}

// ---------------------------------------------------------------------------
// Inter-chunk scan: 256 threads; S1 loop processes kd pairs with packed
// 8B kcd/qg loads; kg loop unrolled x2. Same accumulation order as before.
// ---------------------------------------------------------------------------
constexpr int SK2 = 132;   // kcd/qg/kg row stride
constexpr int SC2 = 68;    // am row stride
constexpr int SV2 = 36;    // vi row stride
constexpr int SST = 36;    // state row stride
constexpr int SBT = 36;    // v_new row stride
constexpr int SCAN_SMEM =
    (128 * SST + 3 * 64 * SK2 + 64 * SC2 + 64 * SV2 + 64 * SBT) * 4;

__global__ __launch_bounds__(256) void scan_kernel()
{
    extern __shared__ float sm[];
    float* sSt  = sm;                    // 128*36
    float* sKcd = sSt + 128 * SST;       // 64*132
    float* sQg  = sKcd + 64 * SK2;
    float* sKg  = sQg + 64 * SK2;
    float* sC   = sKg + 64 * SK2;        // 64*68
    float* sVi  = sC + 64 * SC2;         // 64*36
    float* sB   = sVi + 64 * SV2;        // 64*36

    const int h   = blockIdx.x;
    const int grp = blockIdx.y;
    const int e0  = grp * 32;
    const int tid = threadIdx.x;
    const int tx  = tid & 7;
    const int ty  = tid >> 3;
    const uint32_t uKcd = smem_u32(sKcd), uQg = smem_u32(sQg), uKg = smem_u32(sKg);
    const uint32_t uC = smem_u32(sC), uVi = smem_u32(sVi);

    for (int idx = tid; idx < 128 * SST; idx += 256) sSt[idx] = 0.f;
    __syncthreads();

    auto issue_loads = [&](int c) {
        const size_t base = (size_t)(c * N_VH + h);
        const float* kcd = g_kcd + base * (CH * D_K);
        const float* qg  = g_qg  + base * (CH * D_K);
        const float* kg  = g_kg  + base * (CH * D_K);
        const float* am  = g_am  + base * (CH * CH);
        const float* vi  = g_vi  + base * (CH * D_V);
#pragma unroll
        for (int it = 0; it < 8; it++) {
            int idx = tid + it * 256;
            int r = idx >> 5, q = idx & 31;
            CP_ASYNC16(uKcd + (uint32_t)(r * SK2 + q * 4) * 4, kcd + r * 128 + q * 4);
            CP_ASYNC16(uQg  + (uint32_t)(r * SK2 + q * 4) * 4, qg  + r * 128 + q * 4);
            CP_ASYNC16(uKg  + (uint32_t)(r * SK2 + q * 4) * 4, kg  + r * 128 + q * 4);
        }
#pragma unroll
        for (int it = 0; it < 4; it++) {
            int idx = tid + it * 256;
            int r = idx >> 4, q = idx & 15;
            CP_ASYNC16(uC + (uint32_t)(r * SC2 + q * 4) * 4, am + r * 64 + q * 4);
        }
#pragma unroll
        for (int it = 0; it < 2; it++) {
            int i2 = tid + it * 256;
            int rr = i2 >> 3, qq = i2 & 7;
            CP_ASYNC16(uVi + (uint32_t)(rr * SV2 + qq * 4) * 4, vi + rr * 128 + e0 + qq * 4);
        }
        CP_COMMIT();
    };

    issue_loads(0);

    for (int c = 0; c < NCH; c++) {
        CP_WAIT0();
        __syncthreads();                           // S1: tiles ready

        // merged: kst = kcd@state ; ost = qg@state  (2 kd per iter, packed)
        u64 kst[2][2] = {0ull, 0ull, 0ull, 0ull};
        u64 ost[2][2] = {0ull, 0ull, 0ull, 0ull};
        const float* kr0 = &sKcd[(ty * 2 + 0) * SK2];
        const float* kr1 = &sKcd[(ty * 2 + 1) * SK2];
        const float* qr0 = &sQg[(ty * 2 + 0) * SK2];
        const float* qr1 = &sQg[(ty * 2 + 1) * SK2];
        for (int kd = 0; kd < D_K; kd += 2) {
            ulonglong2 b0 = *reinterpret_cast<const ulonglong2*>(&sSt[kd * SST + tx * 4]);
            ulonglong2 b1 = *reinterpret_cast<const ulonglong2*>(&sSt[(kd + 1) * SST + tx * 4]);
            float ka0, ka1, kb0, kb1, qa0, qa1, qb0, qb1;
            unpack2(*reinterpret_cast<const u64*>(kr0 + kd), ka0, ka1);
            unpack2(*reinterpret_cast<const u64*>(kr1 + kd), kb0, kb1);
            unpack2(*reinterpret_cast<const u64*>(qr0 + kd), qa0, qa1);
            unpack2(*reinterpret_cast<const u64*>(qr1 + kd), qb0, qb1);
            // kd term
            u64 p;
            p = pack2(ka0, ka0); fma2(kst[0][0], p, b0.x); fma2(kst[0][1], p, b0.y);
            p = pack2(kb0, kb0); fma2(kst[1][0], p, b0.x); fma2(kst[1][1], p, b0.y);
            p = pack2(qa0, qa0); fma2(ost[0][0], p, b0.x); fma2(ost[0][1], p, b0.y);
            p = pack2(qb0, qb0); fma2(ost[1][0], p, b0.x); fma2(ost[1][1], p, b0.y);
            // kd+1 term
            p = pack2(ka1, ka1); fma2(kst[0][0], p, b1.x); fma2(kst[0][1], p, b1.y);
            p = pack2(kb1, kb1); fma2(kst[1][0], p, b1.x); fma2(kst[1][1], p, b1.y);
            p = pack2(qa1, qa1); fma2(ost[0][0], p, b1.x); fma2(ost[0][1], p, b1.y);
            p = pack2(qb1, qb1); fma2(ost[1][0], p, b1.x); fma2(ost[1][1], p, b1.y);
        }
        // v_new = vi - kst  -> sB
#pragma unroll
        for (int ii = 0; ii < 2; ii++) {
            float k0, k1, k2, k3;
            unpack2(kst[ii][0], k0, k1);
            unpack2(kst[ii][1], k2, k3);
            const float* vr = &sVi[(ty * 2 + ii) * SV2 + tx * 4];
            float* br = &sB[(ty * 2 + ii) * SBT + tx * 4];
            br[0] = vr[0] - k0; br[1] = vr[1] - k1;
            br[2] = vr[2] - k2; br[3] = vr[3] - k3;
        }
        __syncthreads();                           // S2: v_new ready

        // ost += am @ v_new  (lower-triangular)
        {
            const int jmax = ty * 2 + 2;
            for (int j = 0; j < jmax; j++) {
                ulonglong2 b = *reinterpret_cast<const ulonglong2*>(&sB[j * SBT + tx * 4]);
                u64 p0 = pack2(sC[(ty * 2 + 0) * SC2 + j], sC[(ty * 2 + 0) * SC2 + j]);
                u64 p1 = pack2(sC[(ty * 2 + 1) * SC2 + j], sC[(ty * 2 + 1) * SC2 + j]);
                fma2(ost[0][0], p0, b.x); fma2(ost[0][1], p0, b.y);
                fma2(ost[1][0], p1, b.x); fma2(ost[1][1], p1, b.y);
            }
        }
        // sacc = kg^T @ v_new  (t unrolled x2)
        u64 sacc[4][2];
#pragma unroll
        for (int dd = 0; dd < 4; dd++) { sacc[dd][0] = 0ull; sacc[dd][1] = 0ull; }
        for (int t = 0; t < CH; t += 2) {
            ulonglong2 av0 = *reinterpret_cast<const ulonglong2*>(&sKg[t * SK2 + ty * 4]);
            ulonglong2 av1 = *reinterpret_cast<const ulonglong2*>(&sKg[(t + 1) * SK2 + ty * 4]);
            ulonglong2 b0  = *reinterpret_cast<const ulonglong2*>(&sB[t * SBT + tx * 4]);
            ulonglong2 b1  = *reinterpret_cast<const ulonglong2*>(&sB[(t + 1) * SBT + tx * 4]);
            float a0, a1, a2, a3, c0, c1, c2, c3;
            unpack2(av0.x, a0, a1);
            unpack2(av0.y, a2, a3);
            unpack2(av1.x, c0, c1);
            unpack2(av1.y, c2, c3);
            u64 q;
            q = pack2(a0, a0); fma2(sacc[0][0], q, b0.x); fma2(sacc[0][1], q, b0.y);
            q = pack2(a1, a1); fma2(sacc[1][0], q, b0.x); fma2(sacc[1][1], q, b0.y);
            q = pack2(a2, a2); fma2(sacc[2][0], q, b0.x); fma2(sacc[2][1], q, b0.y);
            q = pack2(a3, a3); fma2(sacc[3][0], q, b0.x); fma2(sacc[3][1], q, b0.y);
            q = pack2(c0, c0); fma2(sacc[0][0], q, b1.x); fma2(sacc[0][1], q, b1.y);
            q = pack2(c1, c1); fma2(sacc[1][0], q, b1.x); fma2(sacc[1][1], q, b1.y);
            q = pack2(c2, c2); fma2(sacc[2][0], q, b1.x); fma2(sacc[2][1], q, b1.y);
            q = pack2(c3, c3); fma2(sacc[3][0], q, b1.x); fma2(sacc[3][1], q, b1.y);
        }
        const float egl = g_egl[c * N_VH + h];
        __syncthreads();                           // S3: all tile reads done

        if (c + 1 < NCH) issue_loads(c + 1);       // overlap with tail work

        // state = state*egl + sacc
        const u64 pe = pack2(egl, egl);
#pragma unroll
        for (int dd = 0; dd < 4; dd++)
#pragma unroll
            for (int p = 0; p < 2; p++) {
                u64* sp = reinterpret_cast<u64*>(&sSt[(ty * 4 + dd) * SST + tx * 4 + p * 2]);
                u64 st = *sp;
                fma2(sacc[dd][p], pe, st);
                *sp = sacc[dd][p];
            }
        // out store
#pragma unroll
        for (int ii = 0; ii < 2; ii++) {
            ulonglong2 ov;
            ov.x = ost[ii][0];
            ov.y = ost[ii][1];
            *reinterpret_cast<ulonglong2*>(
                &g_core[(size_t)(c * CH + ty * 2 + ii) * VAL_DIM + h * D_V + e0 + tx * 4]) = ov;
        }
    }
}

// ---------------------------------------------------------------------------
// Gated RMSNorm, 2 rows per block, fused bf16 hi/lo split output
// ---------------------------------------------------------------------------
__global__ __launch_bounds__(256) void norm_kernel(
    const float* __restrict__ norm_w, bf16* __restrict__ Ah, bf16* __restrict__ Al)
{
    __shared__ float red[8];
    const int s  = blockIdx.x;
    const int vh = blockIdx.y * 2 + (threadIdx.x >> 7);
    const int d  = threadIdx.x & 127;
    const int w  = threadIdx.x >> 5;          // 0..7
    const int g  = w >> 2;                     // row group 0/1
    const int kh = vh >> 1;
    float x  = g_core[(size_t)(s * N_VH + vh) * D_V + d];
    float zv = g_qkvz[(size_t)s * QKVZ_N + kh * 768 + 512 + (vh & 1) * 128 + d];
    float xf = x * (zv / (1.f + __expf(-zv)));
    float v = xf * xf;
#pragma unroll
    for (int o = 16; o > 0; o >>= 1) v += __shfl_xor_sync(0xffffffffu, v, o);
    if ((threadIdx.x & 31) == 0) red[w] = v;
    __syncthreads();
    float var = (red[g * 4 + 0] + red[g * 4 + 1] + red[g * 4 + 2] + red[g * 4 + 3]) * (1.f / 128.f);
    float y = xf * rsqrtf(var + 1e-6f) * norm_w[d];
    size_t o = (size_t)s * VAL_DIM + vh * D_V + d;
    bf16 hy = __float2bfloat16_rn(y);
    Ah[o] = hy;
    Al[o] = __float2bfloat16_rn(y - __bfloat162float(hy));
}

// ---------------------------------------------------------------------------
// Launch (mma_gemm qkvz stays the 4th launch for ncu verification)
// ---------------------------------------------------------------------------
extern "C" void kernel_launch(void* const* d_in, const int* in_sizes, int n_in,
                              void* d_out, int out_size)
{
    const float* hidden  = (const float*)d_in[0];
    const float* W_qkvz  = (const float*)d_in[1];
    const float* W_ba    = (const float*)d_in[2];
    const float* conv_w  = (const float*)d_in[3];
    const float* A_log   = (const float*)d_in[4];
    const float* dt_bias = (const float*)d_in[5];
    const float* norm_w  = (const float*)d_in[6];
    const float* W_out   = (const float*)d_in[7];
    float* out = (float*)d_out;

    float *qkvz;
    bf16 *Ah, *Al, *Bh, *Bl;
    cudaGetSymbolAddress((void**)&qkvz, g_qkvz);
    cudaGetSymbolAddress((void**)&Ah,   g_Ah);
    cudaGetSymbolAddress((void**)&Al,   g_Al);
    cudaGetSymbolAddress((void**)&Bh,   g_Bh);
    cudaGetSymbolAddress((void**)&Bl,   g_Bl);

    static bool attr_set = false;
    if (!attr_set) {
        cudaFuncSetAttribute(intra_kernel, cudaFuncAttributeMaxDynamicSharedMemorySize, INTRA_SMEM);
        cudaFuncSetAttribute(scan_kernel,  cudaFuncAttributeMaxDynamicSharedMemorySize, SCAN_SMEM);
        cudaFuncSetAttribute(mma_gemm_kernel, cudaFuncAttributeMaxDynamicSharedMemorySize, GSMEM);
        attr_set = true;
    }

    // 1-2: operand prep for qkvz GEMM
    {
        size_t n4 = (size_t)S_LEN * EMB_D / 4;
        split_bf16_kernel<<<(unsigned)((n4 + 255) / 256), 256>>>(hidden, Ah, Al, n4);
        transpose_split_bf16<<<dim3(QKVZ_N / 32, EMB_D / 32), 256>>>(W_qkvz, Bh, Bl, EMB_D, QKVZ_N);
    }
    // 3: ba split-K partials (independent)
    ba_gemm_kernel<<<dim3(S_LEN / 64, BA_SPLITS), 256>>>(hidden, W_ba);
    // 4: qkvz GEMM  <- ncu captures this launch
    mma_gemm_kernel<<<dim3(S_LEN / 128, QKVZ_N / 128), 256, GSMEM>>>(
        Ah, Al, Bh, Bl, qkvz, S_LEN, QKVZ_N, EMB_D);
    // 5: conv + gates (s-tiled x4, ba reduce folded in)
    conv_gate_kernel<<<S_LEN / 4, 256>>>(conv_w, A_log, dt_bias);
    // 6-7: delta-rule core
    intra_kernel<<<dim3(NCH, N_VH), 256, INTRA_SMEM>>>();
    scan_kernel<<<dim3(N_VH, 4), 256, SCAN_SMEM>>>();
    // 8: gated RMSNorm + fused bf16 split (2 rows per block)
    norm_kernel<<<dim3(S_LEN, N_VH / 2), 256>>>(norm_w, Ah, Al);
    // 9-10: out GEMM
    transpose_split_bf16<<<dim3(EMB_D / 32, VAL_DIM / 32), 256>>>(W_out, Bh, Bl, VAL_DIM, EMB_D);
    mma_gemm_kernel<<<dim3(S_LEN / 128, EMB_D / 128), 256, GSMEM>>>(
        Ah, Al, Bh, Bl, out, S_LEN, EMB_D, VAL_DIM);
}

// round 14
// speedup vs baseline: 1.3240x; 1.2082x over previous
#include <cuda_runtime.h>
#include <cuda_bf16.h>
#include <cuda_fp16.h>
#include <math.h>
#include <stdint.h>

using f16 = __half;
typedef unsigned long long u64;

// ---------------------------------------------------------------------------
// Problem constants
// ---------------------------------------------------------------------------
constexpr int S_LEN   = 4096;
constexpr int EMB_D   = 2048;
constexpr int N_KH    = 16;
constexpr int N_VH    = 32;
constexpr int D_K     = 128;
constexpr int D_V     = 128;
constexpr int KEY_DIM = N_KH * D_K;                  // 2048
constexpr int VAL_DIM = N_VH * D_V;                  // 4096
constexpr int QKVZ_N  = 2 * KEY_DIM + 2 * VAL_DIM;   // 12288
constexpr int CH      = 64;
constexpr int NCH     = S_LEN / CH;                  // 64
constexpr float RSQRT_DK = 0.08838834764831845f;

constexpr int SKP = 130;   // 64x128 f32 tiles (intra) -- even for 8B pairs
constexpr int SDP = 65;    // 64x64 tiles (intra)
constexpr int SYP = 257;   // 64x256 solve buffer

// ---------------------------------------------------------------------------
// Scratch (static device globals)
// ---------------------------------------------------------------------------
__device__ float g_qkvz[(size_t)S_LEN * QKVZ_N];
__device__ float g_ba_part[16][(size_t)S_LEN * 64];
__device__ float g_q   [(size_t)S_LEN * KEY_DIM];
__device__ float g_k   [(size_t)S_LEN * KEY_DIM];
__device__ float g_v   [(size_t)S_LEN * VAL_DIM];
__device__ float g_beta[(size_t)S_LEN * N_VH];
__device__ float g_g   [(size_t)S_LEN * N_VH];
__device__ float g_qg  [(size_t)NCH * N_VH * CH * D_K];
__device__ float g_kg  [(size_t)NCH * N_VH * CH * D_K];
__device__ float g_kcd [(size_t)NCH * N_VH * CH * D_K];
__device__ float g_vi  [(size_t)NCH * N_VH * CH * D_V];
__device__ float g_am  [(size_t)NCH * N_VH * CH * CH];
__device__ float g_egl [(size_t)NCH * N_VH];
__device__ float g_core[(size_t)S_LEN * VAL_DIM];
// fp16 operands for the tensor-core GEMMs (A: hi only; B: hi/lo split)
__device__ f16 g_Ah[(size_t)4096 * 4096];
__device__ f16 g_Bh[(size_t)12288 * 2048];   // [N][K] K-major
__device__ f16 g_Bl[(size_t)12288 * 2048];

// ---------------------------------------------------------------------------
// Helpers
// ---------------------------------------------------------------------------
__device__ __forceinline__ uint32_t smem_u32(const void* p) {
    uint32_t a;
    asm("{ .reg .u64 t; cvta.to.shared.u64 t, %1; cvt.u32.u64 %0, t; }" : "=r"(a) : "l"(p));
    return a;
}
#define CP_ASYNC16(dst, src) \
    asm volatile("cp.async.cg.shared.global [%0], [%1], 16;" :: "r"(dst), "l"(src))
#define CP_COMMIT() asm volatile("cp.async.commit_group;")
#define CP_WAIT0()  asm volatile("cp.async.wait_group 0;")

// packed dual-fp32 FMA (sm_100+ baseline PTX)
__device__ __forceinline__ u64 pack2(float lo, float hi) {
    u64 r;
    asm("mov.b64 %0, {%1, %2};" : "=l"(r) : "f"(lo), "f"(hi));
    return r;
}
__device__ __forceinline__ void unpack2(u64 v, float& lo, float& hi) {
    asm("mov.b64 {%0, %1}, %2;" : "=f"(lo), "=f"(hi) : "l"(v));
}
__device__ __forceinline__ void fma2(u64& d, u64 a, u64 b) {
    asm("fma.rn.f32x2 %0, %1, %2, %0;" : "+l"(d) : "l"(a), "l"(b));
}

// Non-volatile fp16 MMA wrapper.
__device__ __forceinline__ void mma16816h(float* cc, const uint32_t* a, const uint32_t* b) {
    asm("mma.sync.aligned.m16n8k16.row.col.f32.f16.f16.f32 "
        "{%0,%1,%2,%3}, {%4,%5,%6,%7}, {%8,%9}, {%0,%1,%2,%3};"
        : "+f"(cc[0]), "+f"(cc[1]), "+f"(cc[2]), "+f"(cc[3])
        : "r"(a[0]), "r"(a[1]), "r"(a[2]), "r"(a[3]), "r"(b[0]), "r"(b[1]));
}

// ---------------------------------------------------------------------------
// Prep: elementwise fp16 conversion of an fp32 matrix (A operand: hi only)
// ---------------------------------------------------------------------------
__global__ __launch_bounds__(256) void cvt_f16_kernel(
    const float* __restrict__ X, f16* __restrict__ Xh, size_t n4)
{
    size_t i = (size_t)blockIdx.x * 256 + threadIdx.x;
    if (i >= n4) return;
    float4 v = reinterpret_cast<const float4*>(X)[i];
    __half2* ph = reinterpret_cast<__half2*>(Xh);
    ph[2 * i]     = __half2(__float2half_rn(v.x), __float2half_rn(v.y));
    ph[2 * i + 1] = __half2(__float2half_rn(v.z), __float2half_rn(v.w));
}

// Prep: W[K][N] -> Bt[N][K] with fp16 hi/lo split
__global__ __launch_bounds__(256) void transpose_split_f16(
    const float* __restrict__ W, f16* __restrict__ Bh, f16* __restrict__ Bl, int K, int N)
{
    __shared__ float t[32][33];
    const int n0 = blockIdx.x * 32, k0 = blockIdx.y * 32;
    const int c = threadIdx.x & 31, r0 = threadIdx.x >> 5;
#pragma unroll
    for (int i = 0; i < 4; i++)
        t[r0 + i * 8][c] = W[(size_t)(k0 + r0 + i * 8) * N + n0 + c];
    __syncthreads();
#pragma unroll
    for (int i = 0; i < 4; i++) {
        int rr = r0 + i * 8;
        float x = t[c][rr];
        f16 h = __float2half_rn(x);
        size_t o = (size_t)(n0 + rr) * K + k0 + c;
        Bh[o] = h;
        Bl[o] = __float2half_rn(x - __half2float(h));
    }
}

// ---------------------------------------------------------------------------
// fp16 2-term tensor-core GEMM via mma.sync: C = A @ Bt^T,
// D = Ah*Bh + Ah*Bl (A hi-only; B split).  CTA 128x128, BK=32, 256 threads,
// 2-stage cp.async, 2 CTAs/SM (smem 60KB/CTA).
// ---------------------------------------------------------------------------
constexpr int GROWB  = 80;             // smem bytes per 32-half row (64 + 16 pad)
constexpr int GTILE  = 128 * GROWB;    // 10240 B per operand tile
constexpr int GSTAGE = 3 * GTILE;      // Ah, Bh, Bl
constexpr int GSMEM  = 2 * GSTAGE;     // 61440 B

__global__ __launch_bounds__(256, 2) void mma_gemm_kernel(
    const f16* __restrict__ Ah,
    const f16* __restrict__ Bh, const f16* __restrict__ Bl,
    float* __restrict__ C, int M, int N, int K)
{
    extern __shared__ char smg[];
    const uint32_t sbase = smem_u32(smg);
    const int tid  = threadIdx.x;
    const int lane = tid & 31, wid = tid >> 5;
    const int m0 = blockIdx.x * 128, n0 = blockIdx.y * 128;
    const int wm = (wid >> 2) * 64, wn = (wid & 3) * 32;
    const int NT = K / 32;

    float acc[4][4][4];
#pragma unroll
    for (int a = 0; a < 4; a++)
#pragma unroll
        for (int b = 0; b < 4; b++)
#pragma unroll
            for (int c = 0; c < 4; c++) acc[a][b][c] = 0.f;

    auto load_stage = [&](int kt, int st) {
        const int kc = kt * 32;
        const uint32_t dbase = sbase + st * GSTAGE;
#pragma unroll
        for (int it = 0; it < 6; it++) {       // 1536 float4: Ah, Bh, Bl
            int idx = tid + it * 256;
            int type = idx >> 9;               // 0:Ah 1:Bh 2:Bl
            int rem = idx & 511;
            int r = rem >> 2, c = rem & 3;     // 128 rows x 4 float4 (32 halves)
            const f16* src;
            if (type == 0)      src = Ah + (size_t)(m0 + r) * K + kc + c * 8;
            else if (type == 1) src = Bh + (size_t)(n0 + r) * K + kc + c * 8;
            else                src = Bl + (size_t)(n0 + r) * K + kc + c * 8;
            uint32_t dst = dbase + type * GTILE + r * GROWB + c * 16;
            CP_ASYNC16(dst, src);
        }
    };

    const int arow = lane & 15;
    const uint32_t aoff = (uint32_t)(lane >> 4) * 16;
    const int brow = (lane & 7) + ((lane >> 4) << 3);
    const uint32_t boff = (uint32_t)((lane >> 3) & 1) * 16;

    load_stage(0, 0);
    CP_COMMIT();

    for (int kt = 0; kt < NT; kt++) {
        const int st = kt & 1;
        CP_WAIT0();
        __syncthreads();
        if (kt + 1 < NT) {
            load_stage(kt + 1, st ^ 1);
            CP_COMMIT();
        }
        const uint32_t ab = sbase + st * GSTAGE;
        const uint32_t bb = ab + GTILE;
#pragma unroll
        for (int ks = 0; ks < 2; ks++) {
            const uint32_t kb = ks * 32;
            uint32_t aF[4][4], bH[2][4], bL[2][4];
#pragma unroll
            for (int mt = 0; mt < 4; mt++)
                asm volatile("ldmatrix.sync.aligned.m8n8.x4.shared.b16 {%0,%1,%2,%3}, [%4];"
                    : "=r"(aF[mt][0]), "=r"(aF[mt][1]), "=r"(aF[mt][2]), "=r"(aF[mt][3])
                    : "r"(ab + (uint32_t)(wm + mt * 16 + arow) * GROWB + aoff + kb));
#pragma unroll
            for (int gg = 0; gg < 2; gg++) {
                uint32_t ba_ = bb + (uint32_t)(wn + gg * 16 + brow) * GROWB + boff + kb;
                asm volatile("ldmatrix.sync.aligned.m8n8.x4.shared.b16 {%0,%1,%2,%3}, [%4];"
                    : "=r"(bH[gg][0]), "=r"(bH[gg][1]), "=r"(bH[gg][2]), "=r"(bH[gg][3])
                    : "r"(ba_));
                asm volatile("ldmatrix.sync.aligned.m8n8.x4.shared.b16 {%0,%1,%2,%3}, [%4];"
                    : "=r"(bL[gg][0]), "=r"(bL[gg][1]), "=r"(bL[gg][2]), "=r"(bL[gg][3])
                    : "r"(ba_ + GTILE));
            }
            // Pass 1: Ah * Bh
#pragma unroll
            for (int mt = 0; mt < 4; mt++)
#pragma unroll
                for (int nt = 0; nt < 4; nt++)
                    mma16816h(acc[mt][nt], aF[mt], &bH[nt >> 1][(nt & 1) * 2]);
            // Pass 2: Ah * Bl
#pragma unroll
            for (int mt = 0; mt < 4; mt++)
#pragma unroll
                for (int nt = 0; nt < 4; nt++)
                    mma16816h(acc[mt][nt], aF[mt], &bL[nt >> 1][(nt & 1) * 2]);
        }
    }

#pragma unroll
    for (int mt = 0; mt < 4; mt++) {
        int row = m0 + wm + mt * 16 + (lane >> 2);
#pragma unroll
        for (int nt = 0; nt < 4; nt++) {
            int col = n0 + wn + nt * 8 + 2 * (lane & 3);
            *reinterpret_cast<float2*>(C + (size_t)row * N + col) =
                make_float2(acc[mt][nt][0], acc[mt][nt][1]);
            *reinterpret_cast<float2*>(C + (size_t)(row + 8) * N + col) =
                make_float2(acc[mt][nt][2], acc[mt][nt][3]);
        }
    }
}

// ---------------------------------------------------------------------------
// ba = hidden @ W_ba  : split-K (16 slices); reduce folded into conv_gate
// ---------------------------------------------------------------------------
constexpr int BA_SPLITS = 16;
constexpr int BA_KSEG   = EMB_D / BA_SPLITS;   // 128

__global__ __launch_bounds__(256) void ba_gemm_kernel(
    const float* __restrict__ A, const float* __restrict__ B)
{
    __shared__ float As[16][64];
    __shared__ float Bs[16][64];
    const int m0 = blockIdx.x * 64;
    const int z  = blockIdx.y;
    const int k0 = z * BA_KSEG;
    const int tid = threadIdx.x;
    const int tx = tid & 15, ty = tid >> 4;
    float acc[4][4] = {};

    for (int kk = 0; kk < BA_KSEG; kk += 16) {
        int r = tid >> 2, c4 = (tid & 3) * 4;
        float4 av = *reinterpret_cast<const float4*>(A + (size_t)(m0 + r) * EMB_D + k0 + kk + c4);
        As[c4 + 0][r] = av.x; As[c4 + 1][r] = av.y;
        As[c4 + 2][r] = av.z; As[c4 + 3][r] = av.w;
        int r2 = tid >> 4, c2 = (tid & 15) * 4;
        *reinterpret_cast<float4*>(&Bs[r2][c2]) =
            *reinterpret_cast<const float4*>(B + (size_t)(k0 + kk + r2) * 64 + c2);
        __syncthreads();
#pragma unroll
        for (int k = 0; k < 16; k++) {
            float ar[4], br[4];
#pragma unroll
            for (int i = 0; i < 4; i++) ar[i] = As[k][ty * 4 + i];
#pragma unroll
            for (int j = 0; j < 4; j++) br[j] = Bs[k][tx * 4 + j];
#pragma unroll
            for (int i = 0; i < 4; i++)
#pragma unroll
                for (int j = 0; j < 4; j++) acc[i][j] += ar[i] * br[j];
        }
        __syncthreads();
    }
    float* P = g_ba_part[z];
#pragma unroll
    for (int i = 0; i < 4; i++)
#pragma unroll
        for (int j = 0; j < 4; j++)
            P[(size_t)(m0 + ty * 4 + i) * 64 + tx * 4 + j] = acc[i][j];
}

// ---------------------------------------------------------------------------
// Depthwise causal conv (KSZ=4) + SiLU + gates, s-tiled x4
// ---------------------------------------------------------------------------
__global__ __launch_bounds__(256) void conv_gate_kernel(
    const float* __restrict__ conv_w, const float* __restrict__ A_log,
    const float* __restrict__ dt_bias)
{
    const int s0 = blockIdx.x * 4;
    for (int c = threadIdx.x; c < 8192; c += 256) {
        int col;
        float* dst;
        int stride;
        if (c < 2048) {
            int kh = c >> 7, d = c & 127;
            col = kh * 768 + d;
            dst = &g_q[(size_t)s0 * KEY_DIM + c];
            stride = KEY_DIM;
        } else if (c < 4096) {
            int cc = c - 2048;
            int kh = cc >> 7, d = cc & 127;
            col = kh * 768 + 128 + d;
            dst = &g_k[(size_t)s0 * KEY_DIM + cc];
            stride = KEY_DIM;
        } else {
            int cc = c - 4096;
            int vh = cc >> 7, d = cc & 127;
            col = (vh >> 1) * 768 + 256 + (vh & 1) * 128 + d;
            dst = &g_v[(size_t)s0 * VAL_DIM + cc];
            stride = VAL_DIM;
        }
        float w0 = conv_w[0 * 8192 + c];
        float w1 = conv_w[1 * 8192 + c];
        float w2 = conv_w[2 * 8192 + c];
        float w3 = conv_w[3 * 8192 + c];
        float x[7];
#pragma unroll
        for (int t = 0; t < 7; t++) {
            int ss = s0 + t - 3;
            x[t] = (ss >= 0) ? g_qkvz[(size_t)ss * QKVZ_N + col] : 0.f;
        }
#pragma unroll
        for (int t = 0; t < 4; t++) {
            float acc = x[t] * w0 + x[t + 1] * w1 + x[t + 2] * w2 + x[t + 3] * w3;
            dst[(size_t)t * stride] = acc / (1.f + __expf(-acc));
        }
    }
    if (threadIdx.x < 128) {                  // 4 positions x 32 heads
        int s  = s0 + (threadIdx.x >> 5);
        int vh = threadIdx.x & 31;
        int kh = vh >> 1, j = vh & 1;
        float bg = 0.f, ag = 0.f;
#pragma unroll
        for (int z = 0; z < BA_SPLITS; z++) {
            bg += g_ba_part[z][s * 64 + kh * 4 + j];
            ag += g_ba_part[z][s * 64 + kh * 4 + 2 + j];
        }
        g_beta[s * N_VH + vh] = 1.f / (1.f + expf(-bg));
        float x = ag + dt_bias[vh];
        float sp = (x > 20.f) ? x : log1pf(expf(x));
        g_g[s * N_VH + vh] = -expf(A_log[vh]) * sp;
    }
}

// ---------------------------------------------------------------------------
// Intra-chunk kernel (decay table + fused dual matmul with f32x2 + warp scan)
// ---------------------------------------------------------------------------
constexpr int INTRA_SMEM = (64 * SKP * 2 + 64 * SDP * 2 + 64 * SYP + 192) * 4;

__global__ __launch_bounds__(256) void intra_kernel()
{
    extern __shared__ float sm[];
    float* sK  = sm;
    float* sQ  = sK + 64 * SKP;
    float* sD  = sQ + 64 * SKP;
    float* sL  = sD + 64 * SDP;
    float* sY  = sL + 64 * SDP;
    float* sgc = sY + 64 * SYP;
    float* sb  = sgc + 64;
    float* sE  = sb + 64;

    const int c   = blockIdx.x;
    const int h   = blockIdx.y;
    const int kh  = h >> 1;
    const int s0  = c * CH;
    const int tid = threadIdx.x;
    const size_t base = (size_t)(c * N_VH + h);

    for (int idx = tid; idx < CH * D_K; idx += 256) {
        int i = idx >> 7, d = idx & 127;
        sK[i * SKP + d] = g_k[(size_t)(s0 + i) * KEY_DIM + kh * D_K + d];
        sQ[i * SKP + d] = g_q[(size_t)(s0 + i) * KEY_DIM + kh * D_K + d] * RSQRT_DK;
    }
    if (tid < CH) {
        sb[tid]  = g_beta[(s0 + tid) * N_VH + h];
        sgc[tid] = g_g[(s0 + tid) * N_VH + h];
    }
    __syncthreads();

    // inclusive cumsum of g: one warp, 2 elems/lane
    if (tid < 32) {
        float x0 = sgc[2 * tid], x1 = sgc[2 * tid + 1];
        float s = x0 + x1;
#pragma unroll
        for (int off = 1; off < 32; off <<= 1) {
            float t = __shfl_up_sync(0xffffffffu, s, off);
            if (tid >= off) s += t;
        }
        float excl = s - (x0 + x1);
        sgc[2 * tid]     = excl + x0;
        sgc[2 * tid + 1] = excl + x0 + x1;
    }
    __syncthreads();

    // decay table + e^{gc}
    for (int idx = tid; idx < CH * CH; idx += 256) {
        int i = idx >> 6, j = idx & 63;
        sD[i * SDP + j] = (j <= i) ? __expf(sgc[i] - sgc[j]) : 0.f;
    }
    if (tid < CH) sE[tid] = __expf(sgc[tid]);
    __syncthreads();

    // fused dual matmul via f32x2 pairs over d: accL = k.k^T ; accA = q.k^T
    {
        const int ty = tid >> 4, tx = tid & 15;
        const int i0 = ty * 4, j0 = tx * 4;
        u64 accLp[4][4], accAp[4][4];
#pragma unroll
        for (int ii = 0; ii < 4; ii++)
#pragma unroll
            for (int jj = 0; jj < 4; jj++) { accLp[ii][jj] = 0ull; accAp[ii][jj] = 0ull; }
        for (int d = 0; d < D_K; d += 2) {
            u64 avp[4], qvp[4], bvp[4];
#pragma unroll
            for (int ii = 0; ii < 4; ii++) {
                avp[ii] = *reinterpret_cast<const u64*>(&sK[(i0 + ii) * SKP + d]);
                qvp[ii] = *reinterpret_cast<const u64*>(&sQ[(i0 + ii) * SKP + d]);
            }
#pragma unroll
            for (int jj = 0; jj < 4; jj++)
                bvp[jj] = *reinterpret_cast<const u64*>(&sK[(j0 + jj) * SKP + d]);
#pragma unroll
            for (int ii = 0; ii < 4; ii++)
#pragma unroll
                for (int jj = 0; jj < 4; jj++) {
                    fma2(accLp[ii][jj], avp[ii], bvp[jj]);
                    fma2(accAp[ii][jj], qvp[ii], bvp[jj]);
                }
        }
#pragma unroll
        for (int ii = 0; ii < 4; ii++)
#pragma unroll
            for (int jj = 0; jj < 4; jj++) {
                int i = i0 + ii, j = j0 + jj;
                float l0, l1, a0, a1;
                unpack2(accLp[ii][jj], l0, l1);
                unpack2(accAp[ii][jj], a0, a1);
                float dec = sD[i * SDP + j];
                sL[i * SDP + j] = (j < i) ? -(l0 + l1) * sb[i] * dec : 0.f;
                g_am[base * (CH * CH) + i * CH + j] = (a0 + a1) * dec;  // dec=0 for j>i
            }
    }

    // Y init: [v*beta | k*beta*e^{gc}]
    for (int idx = tid; idx < CH * 256; idx += 256) {
        int i = idx >> 8, cc = idx & 255;
        float v;
        if (cc < 128) v = g_v[(size_t)(s0 + i) * VAL_DIM + h * D_V + cc] * sb[i];
        else          v = sK[i * SKP + (cc - 128)] * sb[i] * sE[i];
        sY[i * SYP + cc] = v;
    }
    __syncthreads();

    // forward substitution (I-L)Y = B; one column per thread
    {
        const int cc = tid;
        for (int i = 1; i < CH; i++) {
            const float* lrow = &sL[i * SDP];
            float a0 = 0.f, a1 = 0.f, a2 = 0.f, a3 = 0.f;
            int j = 0;
            for (; j + 4 <= i; j += 4) {
                a0 += lrow[j + 0] * sY[(j + 0) * SYP + cc];
                a1 += lrow[j + 1] * sY[(j + 1) * SYP + cc];
                a2 += lrow[j + 2] * sY[(j + 2) * SYP + cc];
                a3 += lrow[j + 3] * sY[(j + 3) * SYP + cc];
            }
            for (; j < i; j++) a0 += lrow[j] * sY[j * SYP + cc];
            sY[i * SYP + cc] += (a0 + a1) + (a2 + a3);
        }
    }
    __syncthreads();

    // outputs
    for (int idx = tid; idx < CH * D_K; idx += 256) {
        int i = idx >> 7, d = idx & 127;
        g_vi [base * (CH * D_V) + idx] = sY[i * SYP + d];
        g_kcd[base * (CH * D_K) + idx] = sY[i * SYP + 128 + d];
        g_kg [base * (CH * D_K) + idx] = sK[i * SKP + d] * sD[63 * SDP + i];
        g_qg [base * (CH * D_K) + idx] = sQ[i * SKP + d] * sE[i];
    }
    if (tid == 0) g_egl[c * N_VH + h] = sE[63];
}

// ---------------------------------------------------------------------------
// Inter-chunk scan (round-13 version)
// ---------------------------------------------------------------------------
constexpr int SK2 = 132;
constexpr int SC2 = 68;
constexpr int SV2 = 36;
constexpr int SST = 36;
constexpr int SBT = 36;
constexpr int SCAN_SMEM =
    (128 * SST + 3 * 64 * SK2 + 64 * SC2 + 64 * SV2 + 64 * SBT) * 4;

__global__ __launch_bounds__(256) void scan_kernel()
{
    extern __shared__ float sm[];
    float* sSt  = sm;
    float* sKcd = sSt + 128 * SST;
    float* sQg  = sKcd + 64 * SK2;
    float* sKg  = sQg + 64 * SK2;
    float* sC   = sKg + 64 * SK2;
    float* sVi  = sC + 64 * SC2;
    float* sB   = sVi + 64 * SV2;

    const int h   = blockIdx.x;
    const int grp = blockIdx.y;
    const int e0  = grp * 32;
    const int tid = threadIdx.x;
    const int tx  = tid & 7;
    const int ty  = tid >> 3;
    const uint32_t uKcd = smem_u32(sKcd), uQg = smem_u32(sQg), uKg = smem_u32(sKg);
    const uint32_t uC = smem_u32(sC), uVi = smem_u32(sVi);

    for (int idx = tid; idx < 128 * SST; idx += 256) sSt[idx] = 0.f;
    __syncthreads();

    auto issue_loads = [&](int c) {
        const size_t base = (size_t)(c * N_VH + h);
        const float* kcd = g_kcd + base * (CH * D_K);
        const float* qg  = g_qg  + base * (CH * D_K);
        const float* kg  = g_kg  + base * (CH * D_K);
        const float* am  = g_am  + base * (CH * CH);
        const float* vi  = g_vi  + base * (CH * D_V);
#pragma unroll
        for (int it = 0; it < 8; it++) {
            int idx = tid + it * 256;
            int r = idx >> 5, q = idx & 31;
            CP_ASYNC16(uKcd + (uint32_t)(r * SK2 + q * 4) * 4, kcd + r * 128 + q * 4);
            CP_ASYNC16(uQg  + (uint32_t)(r * SK2 + q * 4) * 4, qg  + r * 128 + q * 4);
            CP_ASYNC16(uKg  + (uint32_t)(r * SK2 + q * 4) * 4, kg  + r * 128 + q * 4);
        }
#pragma unroll
        for (int it = 0; it < 4; it++) {
            int idx = tid + it * 256;
            int r = idx >> 4, q = idx & 15;
            CP_ASYNC16(uC + (uint32_t)(r * SC2 + q * 4) * 4, am + r * 64 + q * 4);
        }
#pragma unroll
        for (int it = 0; it < 2; it++) {
            int i2 = tid + it * 256;
            int rr = i2 >> 3, qq = i2 & 7;
            CP_ASYNC16(uVi + (uint32_t)(rr * SV2 + qq * 4) * 4, vi + rr * 128 + e0 + qq * 4);
        }
        CP_COMMIT();
    };

    issue_loads(0);

    for (int c = 0; c < NCH; c++) {
        CP_WAIT0();
        __syncthreads();                           // S1: tiles ready

        u64 kst[2][2] = {0ull, 0ull, 0ull, 0ull};
        u64 ost[2][2] = {0ull, 0ull, 0ull, 0ull};
        const float* kr0 = &sKcd[(ty * 2 + 0) * SK2];
        const float* kr1 = &sKcd[(ty * 2 + 1) * SK2];
        const float* qr0 = &sQg[(ty * 2 + 0) * SK2];
        const float* qr1 = &sQg[(ty * 2 + 1) * SK2];
        for (int kd = 0; kd < D_K; kd += 2) {
            ulonglong2 b0 = *reinterpret_cast<const ulonglong2*>(&sSt[kd * SST + tx * 4]);
            ulonglong2 b1 = *reinterpret_cast<const ulonglong2*>(&sSt[(kd + 1) * SST + tx * 4]);
            float ka0, ka1, kb0, kb1, qa0, qa1, qb0, qb1;
            unpack2(*reinterpret_cast<const u64*>(kr0 + kd), ka0, ka1);
            unpack2(*reinterpret_cast<const u64*>(kr1 + kd), kb0, kb1);
            unpack2(*reinterpret_cast<const u64*>(qr0 + kd), qa0, qa1);
            unpack2(*reinterpret_cast<const u64*>(qr1 + kd), qb0, qb1);
            u64 p;
            p = pack2(ka0, ka0); fma2(kst[0][0], p, b0.x); fma2(kst[0][1], p, b0.y);
            p = pack2(kb0, kb0); fma2(kst[1][0], p, b0.x); fma2(kst[1][1], p, b0.y);
            p = pack2(qa0, qa0); fma2(ost[0][0], p, b0.x); fma2(ost[0][1], p, b0.y);
            p = pack2(qb0, qb0); fma2(ost[1][0], p, b0.x); fma2(ost[1][1], p, b0.y);
            p = pack2(ka1, ka1); fma2(kst[0][0], p, b1.x); fma2(kst[0][1], p, b1.y);
            p = pack2(kb1, kb1); fma2(kst[1][0], p, b1.x); fma2(kst[1][1], p, b1.y);
            p = pack2(qa1, qa1); fma2(ost[0][0], p, b1.x); fma2(ost[0][1], p, b1.y);
            p = pack2(qb1, qb1); fma2(ost[1][0], p, b1.x); fma2(ost[1][1], p, b1.y);
        }
#pragma unroll
        for (int ii = 0; ii < 2; ii++) {
            float k0, k1, k2, k3;
            unpack2(kst[ii][0], k0, k1);
            unpack2(kst[ii][1], k2, k3);
            const float* vr = &sVi[(ty * 2 + ii) * SV2 + tx * 4];
            float* br = &sB[(ty * 2 + ii) * SBT + tx * 4];
            br[0] = vr[0] - k0; br[1] = vr[1] - k1;
            br[2] = vr[2] - k2; br[3] = vr[3] - k3;
        }
        __syncthreads();                           // S2: v_new ready

        {
            const int jmax = ty * 2 + 2;
            for (int j = 0; j < jmax; j++) {
                ulonglong2 b = *reinterpret_cast<const ulonglong2*>(&sB[j * SBT + tx * 4]);
                u64 p0 = pack2(sC[(ty * 2 + 0) * SC2 + j], sC[(ty * 2 + 0) * SC2 + j]);
                u64 p1 = pack2(sC[(ty * 2 + 1) * SC2 + j], sC[(ty * 2 + 1) * SC2 + j]);
                fma2(ost[0][0], p0, b.x); fma2(ost[0][1], p0, b.y);
                fma2(ost[1][0], p1, b.x); fma2(ost[1][1], p1, b.y);
            }
        }
        u64 sacc[4][2];
#pragma unroll
        for (int dd = 0; dd < 4; dd++) { sacc[dd][0] = 0ull; sacc[dd][1] = 0ull; }
        for (int t = 0; t < CH; t += 2) {
            ulonglong2 av0 = *reinterpret_cast<const ulonglong2*>(&sKg[t * SK2 + ty * 4]);
            ulonglong2 av1 = *reinterpret_cast<const ulonglong2*>(&sKg[(t + 1) * SK2 + ty * 4]);
            ulonglong2 b0  = *reinterpret_cast<const ulonglong2*>(&sB[t * SBT + tx * 4]);
            ulonglong2 b1  = *reinterpret_cast<const ulonglong2*>(&sB[(t + 1) * SBT + tx * 4]);
            float a0, a1, a2, a3, c0, c1, c2, c3;
            unpack2(av0.x, a0, a1);
            unpack2(av0.y, a2, a3);
            unpack2(av1.x, c0, c1);
            unpack2(av1.y, c2, c3);
            u64 q;
            q = pack2(a0, a0); fma2(sacc[0][0], q, b0.x); fma2(sacc[0][1], q, b0.y);
            q = pack2(a1, a1); fma2(sacc[1][0], q, b0.x); fma2(sacc[1][1], q, b0.y);
            q = pack2(a2, a2); fma2(sacc[2][0], q, b0.x); fma2(sacc[2][1], q, b0.y);
            q = pack2(a3, a3); fma2(sacc[3][0], q, b0.x); fma2(sacc[3][1], q, b0.y);
            q = pack2(c0, c0); fma2(sacc[0][0], q, b1.x); fma2(sacc[0][1], q, b1.y);
            q = pack2(c1, c1); fma2(sacc[1][0], q, b1.x); fma2(sacc[1][1], q, b1.y);
            q = pack2(c2, c2); fma2(sacc[2][0], q, b1.x); fma2(sacc[2][1], q, b1.y);
            q = pack2(c3, c3); fma2(sacc[3][0], q, b1.x); fma2(sacc[3][1], q, b1.y);
        }
        const float egl = g_egl[c * N_VH + h];
        __syncthreads();                           // S3: all tile reads done

        if (c + 1 < NCH) issue_loads(c + 1);

        const u64 pe = pack2(egl, egl);
#pragma unroll
        for (int dd = 0; dd < 4; dd++)
#pragma unroll
            for (int p = 0; p < 2; p++) {
                u64* sp = reinterpret_cast<u64*>(&sSt[(ty * 4 + dd) * SST + tx * 4 + p * 2]);
                u64 st = *sp;
                fma2(sacc[dd][p], pe, st);
                *sp = sacc[dd][p];
            }
#pragma unroll
        for (int ii = 0; ii < 2; ii++) {
            ulonglong2 ov;
            ov.x = ost[ii][0];
            ov.y = ost[ii][1];
            *reinterpret_cast<ulonglong2*>(
                &g_core[(size_t)(c * CH + ty * 2 + ii) * VAL_DIM + h * D_V + e0 + tx * 4]) = ov;
        }
    }
}

// ---------------------------------------------------------------------------
// Gated RMSNorm, 2 rows per block, fused fp16 output (A operand hi only)
// ---------------------------------------------------------------------------
__global__ __launch_bounds__(256) void norm_kernel(
    const float* __restrict__ norm_w, f16* __restrict__ Ah)
{
    __shared__ float red[8];
    const int s  = blockIdx.x;
    const int vh = blockIdx.y * 2 + (threadIdx.x >> 7);
    const int d  = threadIdx.x & 127;
    const int w  = threadIdx.x >> 5;
    const int g  = w >> 2;
    const int kh = vh >> 1;
    float x  = g_core[(size_t)(s * N_VH + vh) * D_V + d];
    float zv = g_qkvz[(size_t)s * QKVZ_N + kh * 768 + 512 + (vh & 1) * 128 + d];
    float xf = x * (zv / (1.f + __expf(-zv)));
    float v = xf * xf;
#pragma unroll
    for (int o = 16; o > 0; o >>= 1) v += __shfl_xor_sync(0xffffffffu, v, o);
    if ((threadIdx.x & 31) == 0) red[w] = v;
    __syncthreads();
    float var = (red[g * 4 + 0] + red[g * 4 + 1] + red[g * 4 + 2] + red[g * 4 + 3]) * (1.f / 128.f);
    float y = xf * rsqrtf(var + 1e-6f) * norm_w[d];
    Ah[(size_t)s * VAL_DIM + vh * D_V + d] = __float2half_rn(y);
}

// ---------------------------------------------------------------------------
// Launch (mma_gemm qkvz stays the 4th launch for ncu verification)
// ---------------------------------------------------------------------------
extern "C" void kernel_launch(void* const* d_in, const int* in_sizes, int n_in,
                              void* d_out, int out_size)
{
    const float* hidden  = (const float*)d_in[0];
    const float* W_qkvz  = (const float*)d_in[1];
    const float* W_ba    = (const float*)d_in[2];
    const float* conv_w  = (const float*)d_in[3];
    const float* A_log   = (const float*)d_in[4];
    const float* dt_bias = (const float*)d_in[5];
    const float* norm_w  = (const float*)d_in[6];
    const float* W_out   = (const float*)d_in[7];
    float* out = (float*)d_out;

    float *qkvz;
    f16 *Ah, *Bh, *Bl;
    cudaGetSymbolAddress((void**)&qkvz, g_qkvz);
    cudaGetSymbolAddress((void**)&Ah,   g_Ah);
    cudaGetSymbolAddress((void**)&Bh,   g_Bh);
    cudaGetSymbolAddress((void**)&Bl,   g_Bl);

    static bool attr_set = false;
    if (!attr_set) {
        cudaFuncSetAttribute(intra_kernel, cudaFuncAttributeMaxDynamicSharedMemorySize, INTRA_SMEM);
        cudaFuncSetAttribute(scan_kernel,  cudaFuncAttributeMaxDynamicSharedMemorySize, SCAN_SMEM);
        cudaFuncSetAttribute(mma_gemm_kernel, cudaFuncAttributeMaxDynamicSharedMemorySize, GSMEM);
        attr_set = true;
    }

    // 1-2: operand prep for qkvz GEMM
    {
        size_t n4 = (size_t)S_LEN * EMB_D / 4;
        cvt_f16_kernel<<<(unsigned)((n4 + 255) / 256), 256>>>(hidden, Ah, n4);
        transpose_split_f16<<<dim3(QKVZ_N / 32, EMB_D / 32), 256>>>(W_qkvz, Bh, Bl, EMB_D, QKVZ_N);
    }
    // 3: ba split-K partials (independent)
    ba_gemm_kernel<<<dim3(S_LEN / 64, BA_SPLITS), 256>>>(hidden, W_ba);
    // 4: qkvz GEMM  <- ncu captures this launch
    mma_gemm_kernel<<<dim3(S_LEN / 128, QKVZ_N / 128), 256, GSMEM>>>(
        Ah, Bh, Bl, qkvz, S_LEN, QKVZ_N, EMB_D);
    // 5: conv + gates (s-tiled x4, ba reduce folded in)
    conv_gate_kernel<<<S_LEN / 4, 256>>>(conv_w, A_log, dt_bias);
    // 6-7: delta-rule core
    intra_kernel<<<dim3(NCH, N_VH), 256, INTRA_SMEM>>>();
    scan_kernel<<<dim3(N_VH, 4), 256, SCAN_SMEM>>>();
    // 8: gated RMSNorm + fused fp16 convert (2 rows per block)
    norm_kernel<<<dim3(S_LEN, N_VH / 2), 256>>>(norm_w, Ah);
    // 9-10: out GEMM
    transpose_split_f16<<<dim3(EMB_D / 32, VAL_DIM / 32), 256>>>(W_out, Bh, Bl, VAL_DIM, EMB_D);
    mma_gemm_kernel<<<dim3(S_LEN / 128, EMB_D / 128), 256, GSMEM>>>(
        Ah, Bh, Bl, out, S_LEN, EMB_D, VAL_DIM);
}

// round 15
// speedup vs baseline: 1.3970x; 1.0552x over previous
#include <cuda_runtime.h>
#include <cuda_bf16.h>
#include <cuda_fp16.h>
#include <math.h>
#include <stdint.h>

using f16 = __half;
typedef unsigned long long u64;

// ---------------------------------------------------------------------------
// Problem constants
// ---------------------------------------------------------------------------
constexpr int S_LEN   = 4096;
constexpr int EMB_D   = 2048;
constexpr int N_KH    = 16;
constexpr int N_VH    = 32;
constexpr int D_K     = 128;
constexpr int D_V     = 128;
constexpr int KEY_DIM = N_KH * D_K;                  // 2048
constexpr int VAL_DIM = N_VH * D_V;                  // 4096
constexpr int QKVZ_N  = 2 * KEY_DIM + 2 * VAL_DIM;   // 12288
constexpr int CH      = 64;
constexpr int NCH     = S_LEN / CH;                  // 64
constexpr float RSQRT_DK = 0.08838834764831845f;

constexpr int SKP = 130;   // 64x128 f32 tiles (intra) -- even for 8B pairs
constexpr int SDP = 65;    // 64x64 tiles (intra)
constexpr int SYP = 257;   // 64x256 solve buffer

// ---------------------------------------------------------------------------
// Scratch (static device globals)
// ---------------------------------------------------------------------------
__device__ float g_qkvz[(size_t)S_LEN * QKVZ_N];
__device__ float g_ba_part[16][(size_t)S_LEN * 64];
__device__ float g_q   [(size_t)S_LEN * KEY_DIM];
__device__ float g_k   [(size_t)S_LEN * KEY_DIM];
__device__ float g_v   [(size_t)S_LEN * VAL_DIM];
__device__ float g_beta[(size_t)S_LEN * N_VH];
__device__ float g_g   [(size_t)S_LEN * N_VH];
__device__ float g_qg  [(size_t)NCH * N_VH * CH * D_K];
__device__ float g_kg  [(size_t)NCH * N_VH * CH * D_K];
__device__ float g_kcd [(size_t)NCH * N_VH * CH * D_K];
__device__ float g_vi  [(size_t)NCH * N_VH * CH * D_V];
__device__ float g_am  [(size_t)NCH * N_VH * CH * CH];
__device__ float g_egl [(size_t)NCH * N_VH];
__device__ float g_core[(size_t)S_LEN * VAL_DIM];
// fp16 operands for the tensor-core GEMMs (A: hi only; B: hi/lo split)
__device__ f16 g_Ah[(size_t)4096 * 4096];
__device__ f16 g_Bh[(size_t)12288 * 2048];   // [N][K] K-major
__device__ f16 g_Bl[(size_t)12288 * 2048];

// ---------------------------------------------------------------------------
// Helpers
// ---------------------------------------------------------------------------
__device__ __forceinline__ uint32_t smem_u32(const void* p) {
    uint32_t a;
    asm("{ .reg .u64 t; cvta.to.shared.u64 t, %1; cvt.u32.u64 %0, t; }" : "=r"(a) : "l"(p));
    return a;
}
#define CP_ASYNC16(dst, src) \
    asm volatile("cp.async.cg.shared.global [%0], [%1], 16;" :: "r"(dst), "l"(src))
#define CP_COMMIT() asm volatile("cp.async.commit_group;")
#define CP_WAIT0()  asm volatile("cp.async.wait_group 0;")

// packed dual-fp32 FMA (sm_100+ baseline PTX)
__device__ __forceinline__ u64 pack2(float lo, float hi) {
    u64 r;
    asm("mov.b64 %0, {%1, %2};" : "=l"(r) : "f"(lo), "f"(hi));
    return r;
}
__device__ __forceinline__ void unpack2(u64 v, float& lo, float& hi) {
    asm("mov.b64 {%0, %1}, %2;" : "=f"(lo), "=f"(hi) : "l"(v));
}
__device__ __forceinline__ void fma2(u64& d, u64 a, u64 b) {
    asm("fma.rn.f32x2 %0, %1, %2, %0;" : "+l"(d) : "l"(a), "l"(b));
}

// Non-volatile fp16 MMA wrapper.
__device__ __forceinline__ void mma16816h(float* cc, const uint32_t* a, const uint32_t* b) {
    asm("mma.sync.aligned.m16n8k16.row.col.f32.f16.f16.f32 "
        "{%0,%1,%2,%3}, {%4,%5,%6,%7}, {%8,%9}, {%0,%1,%2,%3};"
        : "+f"(cc[0]), "+f"(cc[1]), "+f"(cc[2]), "+f"(cc[3])
        : "r"(a[0]), "r"(a[1]), "r"(a[2]), "r"(a[3]), "r"(b[0]), "r"(b[1]));
}

// ---------------------------------------------------------------------------
// Prep: elementwise fp16 conversion of an fp32 matrix (A operand: hi only)
// ---------------------------------------------------------------------------
__global__ __launch_bounds__(256) void cvt_f16_kernel(
    const float* __restrict__ X, f16* __restrict__ Xh, size_t n4)
{
    size_t i = (size_t)blockIdx.x * 256 + threadIdx.x;
    if (i >= n4) return;
    float4 v = reinterpret_cast<const float4*>(X)[i];
    __half2* ph = reinterpret_cast<__half2*>(Xh);
    ph[2 * i]     = __half2(__float2half_rn(v.x), __float2half_rn(v.y));
    ph[2 * i + 1] = __half2(__float2half_rn(v.z), __float2half_rn(v.w));
}

// Prep: W[K][N] -> Bt[N][K] with fp16 hi/lo split
__global__ __launch_bounds__(256) void transpose_split_f16(
    const float* __restrict__ W, f16* __restrict__ Bh, f16* __restrict__ Bl, int K, int N)
{
    __shared__ float t[32][33];
    const int n0 = blockIdx.x * 32, k0 = blockIdx.y * 32;
    const int c = threadIdx.x & 31, r0 = threadIdx.x >> 5;
#pragma unroll
    for (int i = 0; i < 4; i++)
        t[r0 + i * 8][c] = W[(size_t)(k0 + r0 + i * 8) * N + n0 + c];
    __syncthreads();
#pragma unroll
    for (int i = 0; i < 4; i++) {
        int rr = r0 + i * 8;
        float x = t[c][rr];
        f16 h = __float2half_rn(x);
        size_t o = (size_t)(n0 + rr) * K + k0 + c;
        Bh[o] = h;
        Bl[o] = __float2half_rn(x - __half2float(h));
    }
}

// ---------------------------------------------------------------------------
// fp16 2-term tensor-core GEMM: C = A @ Bt^T, D = Ah*Bh + Ah*Bl.
// CTA 128x128, BK=64 (halved barrier count), 256 threads, 2-stage cp.async,
// 2 CTAs/SM (smem 108KB/CTA).
// ---------------------------------------------------------------------------
constexpr int GROWB  = 144;            // smem bytes per 64-half row (128 + 16 pad)
constexpr int GTILE  = 128 * GROWB;    // 18432 B per operand tile
constexpr int GSTAGE = 3 * GTILE;      // Ah, Bh, Bl -> 55296 B
constexpr int GSMEM  = 2 * GSTAGE;     // 110592 B

__global__ __launch_bounds__(256, 2) void mma_gemm_kernel(
    const f16* __restrict__ Ah,
    const f16* __restrict__ Bh, const f16* __restrict__ Bl,
    float* __restrict__ C, int M, int N, int K)
{
    extern __shared__ char smg[];
    const uint32_t sbase = smem_u32(smg);
    const int tid  = threadIdx.x;
    const int lane = tid & 31, wid = tid >> 5;
    const int m0 = blockIdx.x * 128, n0 = blockIdx.y * 128;
    const int wm = (wid >> 2) * 64, wn = (wid & 3) * 32;
    const int NT = K / 64;

    float acc[4][4][4];
#pragma unroll
    for (int a = 0; a < 4; a++)
#pragma unroll
        for (int b = 0; b < 4; b++)
#pragma unroll
            for (int c = 0; c < 4; c++) acc[a][b][c] = 0.f;

    auto load_stage = [&](int kt, int st) {
        const int kc = kt * 64;
        const uint32_t dbase = sbase + st * GSTAGE;
#pragma unroll
        for (int it = 0; it < 12; it++) {      // 3072 float4: Ah, Bh, Bl
            int idx = tid + it * 256;
            int type = idx >> 10;              // 0:Ah 1:Bh 2:Bl (1024 f4 each)
            int rem = idx & 1023;
            int r = rem >> 3, c = rem & 7;     // 128 rows x 8 float4 (64 halves)
            const f16* src;
            if (type == 0)      src = Ah + (size_t)(m0 + r) * K + kc + c * 8;
            else if (type == 1) src = Bh + (size_t)(n0 + r) * K + kc + c * 8;
            else                src = Bl + (size_t)(n0 + r) * K + kc + c * 8;
            uint32_t dst = dbase + type * GTILE + r * GROWB + c * 16;
            CP_ASYNC16(dst, src);
        }
    };

    const int arow = lane & 15;
    const uint32_t aoff = (uint32_t)(lane >> 4) * 16;
    const int brow = (lane & 7) + ((lane >> 4) << 3);
    const uint32_t boff = (uint32_t)((lane >> 3) & 1) * 16;

    load_stage(0, 0);
    CP_COMMIT();

    for (int kt = 0; kt < NT; kt++) {
        const int st = kt & 1;
        CP_WAIT0();
        __syncthreads();
        if (kt + 1 < NT) {
            load_stage(kt + 1, st ^ 1);
            CP_COMMIT();
        }
        const uint32_t ab = sbase + st * GSTAGE;
        const uint32_t bb = ab + GTILE;
#pragma unroll
        for (int ks = 0; ks < 4; ks++) {
            const uint32_t kb = ks * 32;       // 16 k-halves = 32 B per subtile
            uint32_t aF[4][4], bH[2][4], bL[2][4];
#pragma unroll
            for (int mt = 0; mt < 4; mt++)
                asm volatile("ldmatrix.sync.aligned.m8n8.x4.shared.b16 {%0,%1,%2,%3}, [%4];"
                    : "=r"(aF[mt][0]), "=r"(aF[mt][1]), "=r"(aF[mt][2]), "=r"(aF[mt][3])
                    : "r"(ab + (uint32_t)(wm + mt * 16 + arow) * GROWB + aoff + kb));
#pragma unroll
            for (int gg = 0; gg < 2; gg++) {
                uint32_t ba_ = bb + (uint32_t)(wn + gg * 16 + brow) * GROWB + boff + kb;
                asm volatile("ldmatrix.sync.aligned.m8n8.x4.shared.b16 {%0,%1,%2,%3}, [%4];"
                    : "=r"(bH[gg][0]), "=r"(bH[gg][1]), "=r"(bH[gg][2]), "=r"(bH[gg][3])
                    : "r"(ba_));
                asm volatile("ldmatrix.sync.aligned.m8n8.x4.shared.b16 {%0,%1,%2,%3}, [%4];"
                    : "=r"(bL[gg][0]), "=r"(bL[gg][1]), "=r"(bL[gg][2]), "=r"(bL[gg][3])
                    : "r"(ba_ + GTILE));
            }
            // Pass 1: Ah * Bh
#pragma unroll
            for (int mt = 0; mt < 4; mt++)
#pragma unroll
                for (int nt = 0; nt < 4; nt++)
                    mma16816h(acc[mt][nt], aF[mt], &bH[nt >> 1][(nt & 1) * 2]);
            // Pass 2: Ah * Bl
#pragma unroll
            for (int mt = 0; mt < 4; mt++)
#pragma unroll
                for (int nt = 0; nt < 4; nt++)
                    mma16816h(acc[mt][nt], aF[mt], &bL[nt >> 1][(nt & 1) * 2]);
        }
    }

#pragma unroll
    for (int mt = 0; mt < 4; mt++) {
        int row = m0 + wm + mt * 16 + (lane >> 2);
#pragma unroll
        for (int nt = 0; nt < 4; nt++) {
            int col = n0 + wn + nt * 8 + 2 * (lane & 3);
            *reinterpret_cast<float2*>(C + (size_t)row * N + col) =
                make_float2(acc[mt][nt][0], acc[mt][nt][1]);
            *reinterpret_cast<float2*>(C + (size_t)(row + 8) * N + col) =
                make_float2(acc[mt][nt][2], acc[mt][nt][3]);
        }
    }
}

// ---------------------------------------------------------------------------
// ba = hidden @ W_ba  : split-K (16 slices); reduce folded into conv_gate
// ---------------------------------------------------------------------------
constexpr int BA_SPLITS = 16;
constexpr int BA_KSEG   = EMB_D / BA_SPLITS;   // 128

__global__ __launch_bounds__(256) void ba_gemm_kernel(
    const float* __restrict__ A, const float* __restrict__ B)
{
    __shared__ float As[16][64];
    __shared__ float Bs[16][64];
    const int m0 = blockIdx.x * 64;
    const int z  = blockIdx.y;
    const int k0 = z * BA_KSEG;
    const int tid = threadIdx.x;
    const int tx = tid & 15, ty = tid >> 4;
    float acc[4][4] = {};

    for (int kk = 0; kk < BA_KSEG; kk += 16) {
        int r = tid >> 2, c4 = (tid & 3) * 4;
        float4 av = *reinterpret_cast<const float4*>(A + (size_t)(m0 + r) * EMB_D + k0 + kk + c4);
        As[c4 + 0][r] = av.x; As[c4 + 1][r] = av.y;
        As[c4 + 2][r] = av.z; As[c4 + 3][r] = av.w;
        int r2 = tid >> 4, c2 = (tid & 15) * 4;
        *reinterpret_cast<float4*>(&Bs[r2][c2]) =
            *reinterpret_cast<const float4*>(B + (size_t)(k0 + kk + r2) * 64 + c2);
        __syncthreads();
#pragma unroll
        for (int k = 0; k < 16; k++) {
            float ar[4], br[4];
#pragma unroll
            for (int i = 0; i < 4; i++) ar[i] = As[k][ty * 4 + i];
#pragma unroll
            for (int j = 0; j < 4; j++) br[j] = Bs[k][tx * 4 + j];
#pragma unroll
            for (int i = 0; i < 4; i++)
#pragma unroll
                for (int j = 0; j < 4; j++) acc[i][j] += ar[i] * br[j];
        }
        __syncthreads();
    }
    float* P = g_ba_part[z];
#pragma unroll
    for (int i = 0; i < 4; i++)
#pragma unroll
        for (int j = 0; j < 4; j++)
            P[(size_t)(m0 + ty * 4 + i) * 64 + tx * 4 + j] = acc[i][j];
}

// ---------------------------------------------------------------------------
// Depthwise causal conv (KSZ=4) + SiLU + gates, s-tiled x4
// ---------------------------------------------------------------------------
__global__ __launch_bounds__(256) void conv_gate_kernel(
    const float* __restrict__ conv_w, const float* __restrict__ A_log,
    const float* __restrict__ dt_bias)
{
    const int s0 = blockIdx.x * 4;
    for (int c = threadIdx.x; c < 8192; c += 256) {
        int col;
        float* dst;
        int stride;
        if (c < 2048) {
            int kh = c >> 7, d = c & 127;
            col = kh * 768 + d;
            dst = &g_q[(size_t)s0 * KEY_DIM + c];
            stride = KEY_DIM;
        } else if (c < 4096) {
            int cc = c - 2048;
            int kh = cc >> 7, d = cc & 127;
            col = kh * 768 + 128 + d;
            dst = &g_k[(size_t)s0 * KEY_DIM + cc];
            stride = KEY_DIM;
        } else {
            int cc = c - 4096;
            int vh = cc >> 7, d = cc & 127;
            col = (vh >> 1) * 768 + 256 + (vh & 1) * 128 + d;
            dst = &g_v[(size_t)s0 * VAL_DIM + cc];
            stride = VAL_DIM;
        }
        float w0 = conv_w[0 * 8192 + c];
        float w1 = conv_w[1 * 8192 + c];
        float w2 = conv_w[2 * 8192 + c];
        float w3 = conv_w[3 * 8192 + c];
        float x[7];
#pragma unroll
        for (int t = 0; t < 7; t++) {
            int ss = s0 + t - 3;
            x[t] = (ss >= 0) ? g_qkvz[(size_t)ss * QKVZ_N + col] : 0.f;
        }
#pragma unroll
        for (int t = 0; t < 4; t++) {
            float acc = x[t] * w0 + x[t + 1] * w1 + x[t + 2] * w2 + x[t + 3] * w3;
            dst[(size_t)t * stride] = acc / (1.f + __expf(-acc));
        }
    }
    if (threadIdx.x < 128) {                  // 4 positions x 32 heads
        int s  = s0 + (threadIdx.x >> 5);
        int vh = threadIdx.x & 31;
        int kh = vh >> 1, j = vh & 1;
        float bg = 0.f, ag = 0.f;
#pragma unroll
        for (int z = 0; z < BA_SPLITS; z++) {
            bg += g_ba_part[z][s * 64 + kh * 4 + j];
            ag += g_ba_part[z][s * 64 + kh * 4 + 2 + j];
        }
        g_beta[s * N_VH + vh] = 1.f / (1.f + expf(-bg));
        float x = ag + dt_bias[vh];
        float sp = (x > 20.f) ? x : log1pf(expf(x));
        g_g[s * N_VH + vh] = -expf(A_log[vh]) * sp;
    }
}

// ---------------------------------------------------------------------------
// Intra-chunk kernel (decay table + fused dual matmul with f32x2 + warp scan)
// ---------------------------------------------------------------------------
constexpr int INTRA_SMEM = (64 * SKP * 2 + 64 * SDP * 2 + 64 * SYP + 192) * 4;

__global__ __launch_bounds__(256) void intra_kernel()
{
    extern __shared__ float sm[];
    float* sK  = sm;
    float* sQ  = sK + 64 * SKP;
    float* sD  = sQ + 64 * SKP;
    float* sL  = sD + 64 * SDP;
    float* sY  = sL + 64 * SDP;
    float* sgc = sY + 64 * SYP;
    float* sb  = sgc + 64;
    float* sE  = sb + 64;

    const int c   = blockIdx.x;
    const int h   = blockIdx.y;
    const int kh  = h >> 1;
    const int s0  = c * CH;
    const int tid = threadIdx.x;
    const size_t base = (size_t)(c * N_VH + h);

    for (int idx = tid; idx < CH * D_K; idx += 256) {
        int i = idx >> 7, d = idx & 127;
        sK[i * SKP + d] = g_k[(size_t)(s0 + i) * KEY_DIM + kh * D_K + d];
        sQ[i * SKP + d] = g_q[(size_t)(s0 + i) * KEY_DIM + kh * D_K + d] * RSQRT_DK;
    }
    if (tid < CH) {
        sb[tid]  = g_beta[(s0 + tid) * N_VH + h];
        sgc[tid] = g_g[(s0 + tid) * N_VH + h];
    }
    __syncthreads();

    // inclusive cumsum of g: one warp, 2 elems/lane
    if (tid < 32) {
        float x0 = sgc[2 * tid], x1 = sgc[2 * tid + 1];
        float s = x0 + x1;
#pragma unroll
        for (int off = 1; off < 32; off <<= 1) {
            float t = __shfl_up_sync(0xffffffffu, s, off);
            if (tid >= off) s += t;
        }
        float excl = s - (x0 + x1);
        sgc[2 * tid]     = excl + x0;
        sgc[2 * tid + 1] = excl + x0 + x1;
    }
    __syncthreads();

    // decay table + e^{gc}
    for (int idx = tid; idx < CH * CH; idx += 256) {
        int i = idx >> 6, j = idx & 63;
        sD[i * SDP + j] = (j <= i) ? __expf(sgc[i] - sgc[j]) : 0.f;
    }
    if (tid < CH) sE[tid] = __expf(sgc[tid]);
    __syncthreads();

    // fused dual matmul via f32x2 pairs over d: accL = k.k^T ; accA = q.k^T
    {
        const int ty = tid >> 4, tx = tid & 15;
        const int i0 = ty * 4, j0 = tx * 4;
        u64 accLp[4][4], accAp[4][4];
#pragma unroll
        for (int ii = 0; ii < 4; ii++)
#pragma unroll
            for (int jj = 0; jj < 4; jj++) { accLp[ii][jj] = 0ull; accAp[ii][jj] = 0ull; }
        for (int d = 0; d < D_K; d += 2) {
            u64 avp[4], qvp[4], bvp[4];
#pragma unroll
            for (int ii = 0; ii < 4; ii++) {
                avp[ii] = *reinterpret_cast<const u64*>(&sK[(i0 + ii) * SKP + d]);
                qvp[ii] = *reinterpret_cast<const u64*>(&sQ[(i0 + ii) * SKP + d]);
            }
#pragma unroll
            for (int jj = 0; jj < 4; jj++)
                bvp[jj] = *reinterpret_cast<const u64*>(&sK[(j0 + jj) * SKP + d]);
#pragma unroll
            for (int ii = 0; ii < 4; ii++)
#pragma unroll
                for (int jj = 0; jj < 4; jj++) {
                    fma2(accLp[ii][jj], avp[ii], bvp[jj]);
                    fma2(accAp[ii][jj], qvp[ii], bvp[jj]);
                }
        }
#pragma unroll
        for (int ii = 0; ii < 4; ii++)
#pragma unroll
            for (int jj = 0; jj < 4; jj++) {
                int i = i0 + ii, j = j0 + jj;
                float l0, l1, a0, a1;
                unpack2(accLp[ii][jj], l0, l1);
                unpack2(accAp[ii][jj], a0, a1);
                float dec = sD[i * SDP + j];
                sL[i * SDP + j] = (j < i) ? -(l0 + l1) * sb[i] * dec : 0.f;
                g_am[base * (CH * CH) + i * CH + j] = (a0 + a1) * dec;  // dec=0 for j>i
            }
    }

    // Y init: [v*beta | k*beta*e^{gc}]
    for (int idx = tid; idx < CH * 256; idx += 256) {
        int i = idx >> 8, cc = idx & 255;
        float v;
        if (cc < 128) v = g_v[(size_t)(s0 + i) * VAL_DIM + h * D_V + cc] * sb[i];
        else          v = sK[i * SKP + (cc - 128)] * sb[i] * sE[i];
        sY[i * SYP + cc] = v;
    }
    __syncthreads();

    // forward substitution (I-L)Y = B; one column per thread
    {
        const int cc = tid;
        for (int i = 1; i < CH; i++) {
            const float* lrow = &sL[i * SDP];
            float a0 = 0.f, a1 = 0.f, a2 = 0.f, a3 = 0.f;
            int j = 0;
            for (; j + 4 <= i; j += 4) {
                a0 += lrow[j + 0] * sY[(j + 0) * SYP + cc];
                a1 += lrow[j + 1] * sY[(j + 1) * SYP + cc];
                a2 += lrow[j + 2] * sY[(j + 2) * SYP + cc];
                a3 += lrow[j + 3] * sY[(j + 3) * SYP + cc];
            }
            for (; j < i; j++) a0 += lrow[j] * sY[j * SYP + cc];
            sY[i * SYP + cc] += (a0 + a1) + (a2 + a3);
        }
    }
    __syncthreads();

    // outputs
    for (int idx = tid; idx < CH * D_K; idx += 256) {
        int i = idx >> 7, d = idx & 127;
        g_vi [base * (CH * D_V) + idx] = sY[i * SYP + d];
        g_kcd[base * (CH * D_K) + idx] = sY[i * SYP + 128 + d];
        g_kg [base * (CH * D_K) + idx] = sK[i * SKP + d] * sD[63 * SDP + i];
        g_qg [base * (CH * D_K) + idx] = sQ[i * SKP + d] * sE[i];
    }
    if (tid == 0) g_egl[c * N_VH + h] = sE[63];
}

// ---------------------------------------------------------------------------
// Inter-chunk scan (round-13 structure + smem-preloaded egl)
// ---------------------------------------------------------------------------
constexpr int SK2 = 132;
constexpr int SC2 = 68;
constexpr int SV2 = 36;
constexpr int SST = 36;
constexpr int SBT = 36;
constexpr int SCAN_SMEM =
    (128 * SST + 3 * 64 * SK2 + 64 * SC2 + 64 * SV2 + 64 * SBT + 64) * 4;

__global__ __launch_bounds__(256) void scan_kernel()
{
    extern __shared__ float sm[];
    float* sSt  = sm;
    float* sKcd = sSt + 128 * SST;
    float* sQg  = sKcd + 64 * SK2;
    float* sKg  = sQg + 64 * SK2;
    float* sC   = sKg + 64 * SK2;
    float* sVi  = sC + 64 * SC2;
    float* sB   = sVi + 64 * SV2;
    float* sEgl = sB + 64 * SBT;         // 64 per-chunk exp(g_last)

    const int h   = blockIdx.x;
    const int grp = blockIdx.y;
    const int e0  = grp * 32;
    const int tid = threadIdx.x;
    const int tx  = tid & 7;
    const int ty  = tid >> 3;
    const uint32_t uKcd = smem_u32(sKcd), uQg = smem_u32(sQg), uKg = smem_u32(sKg);
    const uint32_t uC = smem_u32(sC), uVi = smem_u32(sVi);

    for (int idx = tid; idx < 128 * SST; idx += 256) sSt[idx] = 0.f;
    if (tid < NCH) sEgl[tid] = g_egl[tid * N_VH + h];
    __syncthreads();

    auto issue_loads = [&](int c) {
        const size_t base = (size_t)(c * N_VH + h);
        const float* kcd = g_kcd + base * (CH * D_K);
        const float* qg  = g_qg  + base * (CH * D_K);
        const float* kg  = g_kg  + base * (CH * D_K);
        const float* am  = g_am  + base * (CH * CH);
        const float* vi  = g_vi  + base * (CH * D_V);
#pragma unroll
        for (int it = 0; it < 8; it++) {
            int idx = tid + it * 256;
            int r = idx >> 5, q = idx & 31;
            CP_ASYNC16(uKcd + (uint32_t)(r * SK2 + q * 4) * 4, kcd + r * 128 + q * 4);
            CP_ASYNC16(uQg  + (uint32_t)(r * SK2 + q * 4) * 4, qg  + r * 128 + q * 4);
            CP_ASYNC16(uKg  + (uint32_t)(r * SK2 + q * 4) * 4, kg  + r * 128 + q * 4);
        }
#pragma unroll
        for (int it = 0; it < 4; it++) {
            int idx = tid + it * 256;
            int r = idx >> 4, q = idx & 15;
            CP_ASYNC16(uC + (uint32_t)(r * SC2 + q * 4) * 4, am + r * 64 + q * 4);
        }
#pragma unroll
        for (int it = 0; it < 2; it++) {
            int i2 = tid + it * 256;
            int rr = i2 >> 3, qq = i2 & 7;
            CP_ASYNC16(uVi + (uint32_t)(rr * SV2 + qq * 4) * 4, vi + rr * 128 + e0 + qq * 4);
        }
        CP_COMMIT();
    };

    issue_loads(0);

    for (int c = 0; c < NCH; c++) {
        CP_WAIT0();
        __syncthreads();                           // S1: tiles ready

        u64 kst[2][2] = {0ull, 0ull, 0ull, 0ull};
        u64 ost[2][2] = {0ull, 0ull, 0ull, 0ull};
        const float* kr0 = &sKcd[(ty * 2 + 0) * SK2];
        const float* kr1 = &sKcd[(ty * 2 + 1) * SK2];
        const float* qr0 = &sQg[(ty * 2 + 0) * SK2];
        const float* qr1 = &sQg[(ty * 2 + 1) * SK2];
        for (int kd = 0; kd < D_K; kd += 2) {
            ulonglong2 b0 = *reinterpret_cast<const ulonglong2*>(&sSt[kd * SST + tx * 4]);
            ulonglong2 b1 = *reinterpret_cast<const ulonglong2*>(&sSt[(kd + 1) * SST + tx * 4]);
            float ka0, ka1, kb0, kb1, qa0, qa1, qb0, qb1;
            unpack2(*reinterpret_cast<const u64*>(kr0 + kd), ka0, ka1);
            unpack2(*reinterpret_cast<const u64*>(kr1 + kd), kb0, kb1);
            unpack2(*reinterpret_cast<const u64*>(qr0 + kd), qa0, qa1);
            unpack2(*reinterpret_cast<const u64*>(qr1 + kd), qb0, qb1);
            u64 p;
            p = pack2(ka0, ka0); fma2(kst[0][0], p, b0.x); fma2(kst[0][1], p, b0.y);
            p = pack2(kb0, kb0); fma2(kst[1][0], p, b0.x); fma2(kst[1][1], p, b0.y);
            p = pack2(qa0, qa0); fma2(ost[0][0], p, b0.x); fma2(ost[0][1], p, b0.y);
            p = pack2(qb0, qb0); fma2(ost[1][0], p, b0.x); fma2(ost[1][1], p, b0.y);
            p = pack2(ka1, ka1); fma2(kst[0][0], p, b1.x); fma2(kst[0][1], p, b1.y);
            p = pack2(kb1, kb1); fma2(kst[1][0], p, b1.x); fma2(kst[1][1], p, b1.y);
            p = pack2(qa1, qa1); fma2(ost[0][0], p, b1.x); fma2(ost[0][1], p, b1.y);
            p = pack2(qb1, qb1); fma2(ost[1][0], p, b1.x); fma2(ost[1][1], p, b1.y);
        }
#pragma unroll
        for (int ii = 0; ii < 2; ii++) {
            float k0, k1, k2, k3;
            unpack2(kst[ii][0], k0, k1);
            unpack2(kst[ii][1], k2, k3);
            const float* vr = &sVi[(ty * 2 + ii) * SV2 + tx * 4];
            float* br = &sB[(ty * 2 + ii) * SBT + tx * 4];
            br[0] = vr[0] - k0; br[1] = vr[1] - k1;
            br[2] = vr[2] - k2; br[3] = vr[3] - k3;
        }
        __syncthreads();                           // S2: v_new ready

        {
            const int jmax = ty * 2 + 2;
            for (int j = 0; j < jmax; j++) {
                ulonglong2 b = *reinterpret_cast<const ulonglong2*>(&sB[j * SBT + tx * 4]);
                u64 p0 = pack2(sC[(ty * 2 + 0) * SC2 + j], sC[(ty * 2 + 0) * SC2 + j]);
                u64 p1 = pack2(sC[(ty * 2 + 1) * SC2 + j], sC[(ty * 2 + 1) * SC2 + j]);
                fma2(ost[0][0], p0, b.x); fma2(ost[0][1], p0, b.y);
                fma2(ost[1][0], p1, b.x); fma2(ost[1][1], p1, b.y);
            }
        }
        u64 sacc[4][2];
#pragma unroll
        for (int dd = 0; dd < 4; dd++) { sacc[dd][0] = 0ull; sacc[dd][1] = 0ull; }
        for (int t = 0; t < CH; t += 2) {
            ulonglong2 av0 = *reinterpret_cast<const ulonglong2*>(&sKg[t * SK2 + ty * 4]);
            ulonglong2 av1 = *reinterpret_cast<const ulonglong2*>(&sKg[(t + 1) * SK2 + ty * 4]);
            ulonglong2 b0  = *reinterpret_cast<const ulonglong2*>(&sB[t * SBT + tx * 4]);
            ulonglong2 b1  = *reinterpret_cast<const ulonglong2*>(&sB[(t + 1) * SBT + tx * 4]);
            float a0, a1, a2, a3, c0, c1, c2, c3;
            unpack2(av0.x, a0, a1);
            unpack2(av0.y, a2, a3);
            unpack2(av1.x, c0, c1);
            unpack2(av1.y, c2, c3);
            u64 q;
            q = pack2(a0, a0); fma2(sacc[0][0], q, b0.x); fma2(sacc[0][1], q, b0.y);
            q = pack2(a1, a1); fma2(sacc[1][0], q, b0.x); fma2(sacc[1][1], q, b0.y);
            q = pack2(a2, a2); fma2(sacc[2][0], q, b0.x); fma2(sacc[2][1], q, b0.y);
            q = pack2(a3, a3); fma2(sacc[3][0], q, b0.x); fma2(sacc[3][1], q, b0.y);
            q = pack2(c0, c0); fma2(sacc[0][0], q, b1.x); fma2(sacc[0][1], q, b1.y);
            q = pack2(c1, c1); fma2(sacc[1][0], q, b1.x); fma2(sacc[1][1], q, b1.y);
            q = pack2(c2, c2); fma2(sacc[2][0], q, b1.x); fma2(sacc[2][1], q, b1.y);
            q = pack2(c3, c3); fma2(sacc[3][0], q, b1.x); fma2(sacc[3][1], q, b1.y);
        }
        const float egl = sEgl[c];
        __syncthreads();                           // S3: all tile reads done

        if (c + 1 < NCH) issue_loads(c + 1);

        const u64 pe = pack2(egl, egl);
#pragma unroll
        for (int dd = 0; dd < 4; dd++)
#pragma unroll
            for (int p = 0; p < 2; p++) {
                u64* sp = reinterpret_cast<u64*>(&sSt[(ty * 4 + dd) * SST + tx * 4 + p * 2]);
                u64 st = *sp;
                fma2(sacc[dd][p], pe, st);
                *sp = sacc[dd][p];
            }
#pragma unroll
        for (int ii = 0; ii < 2; ii++) {
            ulonglong2 ov;
            ov.x = ost[ii][0];
            ov.y = ost[ii][1];
            *reinterpret_cast<ulonglong2*>(
                &g_core[(size_t)(c * CH + ty * 2 + ii) * VAL_DIM + h * D_V + e0 + tx * 4]) = ov;
        }
    }
}

// ---------------------------------------------------------------------------
// Gated RMSNorm, 2 rows per block, fused fp16 output (A operand hi only)
// ---------------------------------------------------------------------------
__global__ __launch_bounds__(256) void norm_kernel(
    const float* __restrict__ norm_w, f16* __restrict__ Ah)
{
    __shared__ float red[8];
    const int s  = blockIdx.x;
    const int vh = blockIdx.y * 2 + (threadIdx.x >> 7);
    const int d  = threadIdx.x & 127;
    const int w  = threadIdx.x >> 5;
    const int g  = w >> 2;
    const int kh = vh >> 1;
    float x  = g_core[(size_t)(s * N_VH + vh) * D_V + d];
    float zv = g_qkvz[(size_t)s * QKVZ_N + kh * 768 + 512 + (vh & 1) * 128 + d];
    float xf = x * (zv / (1.f + __expf(-zv)));
    float v = xf * xf;
#pragma unroll
    for (int o = 16; o > 0; o >>= 1) v += __shfl_xor_sync(0xffffffffu, v, o);
    if ((threadIdx.x & 31) == 0) red[w] = v;
    __syncthreads();
    float var = (red[g * 4 + 0] + red[g * 4 + 1] + red[g * 4 + 2] + red[g * 4 + 3]) * (1.f / 128.f);
    float y = xf * rsqrtf(var + 1e-6f) * norm_w[d];
    Ah[(size_t)s * VAL_DIM + vh * D_V + d] = __float2half_rn(y);
}

// ---------------------------------------------------------------------------
// Launch (mma_gemm qkvz stays the 4th launch for ncu verification)
// ---------------------------------------------------------------------------
extern "C" void kernel_launch(void* const* d_in, const int* in_sizes, int n_in,
                              void* d_out, int out_size)
{
    const float* hidden  = (const float*)d_in[0];
    const float* W_qkvz  = (const float*)d_in[1];
    const float* W_ba    = (const float*)d_in[2];
    const float* conv_w  = (const float*)d_in[3];
    const float* A_log   = (const float*)d_in[4];
    const float* dt_bias = (const float*)d_in[5];
    const float* norm_w  = (const float*)d_in[6];
    const float* W_out   = (const float*)d_in[7];
    float* out = (float*)d_out;

    float *qkvz;
    f16 *Ah, *Bh, *Bl;
    cudaGetSymbolAddress((void**)&qkvz, g_qkvz);
    cudaGetSymbolAddress((void**)&Ah,   g_Ah);
    cudaGetSymbolAddress((void**)&Bh,   g_Bh);
    cudaGetSymbolAddress((void**)&Bl,   g_Bl);

    static bool attr_set = false;
    if (!attr_set) {
        cudaFuncSetAttribute(intra_kernel, cudaFuncAttributeMaxDynamicSharedMemorySize, INTRA_SMEM);
        cudaFuncSetAttribute(scan_kernel,  cudaFuncAttributeMaxDynamicSharedMemorySize, SCAN_SMEM);
        cudaFuncSetAttribute(mma_gemm_kernel, cudaFuncAttributeMaxDynamicSharedMemorySize, GSMEM);
        attr_set = true;
    }

    // 1-2: operand prep for qkvz GEMM
    {
        size_t n4 = (size_t)S_LEN * EMB_D / 4;
        cvt_f16_kernel<<<(unsigned)((n4 + 255) / 256), 256>>>(hidden, Ah, n4);
        transpose_split_f16<<<dim3(QKVZ_N / 32, EMB_D / 32), 256>>>(W_qkvz, Bh, Bl, EMB_D, QKVZ_N);
    }
    // 3: ba split-K partials (independent)
    ba_gemm_kernel<<<dim3(S_LEN / 64, BA_SPLITS), 256>>>(hidden, W_ba);
    // 4: qkvz GEMM  <- ncu captures this launch
    mma_gemm_kernel<<<dim3(S_LEN / 128, QKVZ_N / 128), 256, GSMEM>>>(
        Ah, Bh, Bl, qkvz, S_LEN, QKVZ_N, EMB_D);
    // 5: conv + gates (s-tiled x4, ba reduce folded in)
    conv_gate_kernel<<<S_LEN / 4, 256>>>(conv_w, A_log, dt_bias);
    // 6-7: delta-rule core
    intra_kernel<<<dim3(NCH, N_VH), 256, INTRA_SMEM>>>();
    scan_kernel<<<dim3(N_VH, 4), 256, SCAN_SMEM>>>();
    // 8: gated RMSNorm + fused fp16 convert (2 rows per block)
    norm_kernel<<<dim3(S_LEN, N_VH / 2), 256>>>(norm_w, Ah);
    // 9-10: out GEMM
    transpose_split_f16<<<dim3(EMB_D / 32, VAL_DIM / 32), 256>>>(W_out, Bh, Bl, VAL_DIM, EMB_D);
    mma_gemm_kernel<<<dim3(S_LEN / 128, EMB_D / 128), 256, GSMEM>>>(
        Ah, Bh, Bl, out, S_LEN, EMB_D, VAL_DIM);
}

// round 16
// speedup vs baseline: 1.4058x; 1.0063x over previous
#include <cuda_runtime.h>
#include <cuda_bf16.h>
#include <cuda_fp16.h>
#include <math.h>
#include <stdint.h>

using f16 = __half;
typedef unsigned long long u64;

// ---------------------------------------------------------------------------
// Problem constants
// ---------------------------------------------------------------------------
constexpr int S_LEN   = 4096;
constexpr int EMB_D   = 2048;
constexpr int N_KH    = 16;
constexpr int N_VH    = 32;
constexpr int D_K     = 128;
constexpr int D_V     = 128;
constexpr int KEY_DIM = N_KH * D_K;                  // 2048
constexpr int VAL_DIM = N_VH * D_V;                  // 4096
constexpr int QKVZ_N  = 2 * KEY_DIM + 2 * VAL_DIM;   // 12288
constexpr int CH      = 64;
constexpr int NCH     = S_LEN / CH;                  // 64
constexpr float RSQRT_DK = 0.08838834764831845f;

constexpr int SKP = 130;   // 64x128 f32 tiles (intra) -- even for 8B pairs
constexpr int SDP = 65;    // 64x64 tiles (intra)
constexpr int SYP = 257;   // 64x256 solve buffer

// ---------------------------------------------------------------------------
// Scratch (static device globals)
// ---------------------------------------------------------------------------
__device__ float g_qkvz[(size_t)S_LEN * QKVZ_N];
__device__ float g_ba_part[16][(size_t)S_LEN * 64];
__device__ float g_q   [(size_t)S_LEN * KEY_DIM];
__device__ float g_k   [(size_t)S_LEN * KEY_DIM];
__device__ float g_v   [(size_t)S_LEN * VAL_DIM];
__device__ float g_beta[(size_t)S_LEN * N_VH];
__device__ float g_g   [(size_t)S_LEN * N_VH];
__device__ float g_qg  [(size_t)NCH * N_VH * CH * D_K];
__device__ float g_kg  [(size_t)NCH * N_VH * CH * D_K];
__device__ float g_kcd [(size_t)NCH * N_VH * CH * D_K];
__device__ float g_vi  [(size_t)NCH * N_VH * CH * D_V];
__device__ float g_am  [(size_t)NCH * N_VH * CH * CH];
__device__ float g_egl [(size_t)NCH * N_VH];
__device__ float g_core[(size_t)S_LEN * VAL_DIM];
// fp16 operands for the tensor-core GEMMs (A: hi only; B: hi/lo split)
__device__ f16 g_Ah [(size_t)4096 * 4096];
__device__ f16 g_Bh [(size_t)12288 * 2048];   // qkvz weights [N][K] K-major
__device__ f16 g_Bl [(size_t)12288 * 2048];
__device__ f16 g_Bh2[(size_t)2048 * 4096];    // out weights  [N][K] K-major
__device__ f16 g_Bl2[(size_t)2048 * 4096];

// ---------------------------------------------------------------------------
// Helpers
// ---------------------------------------------------------------------------
__device__ __forceinline__ uint32_t smem_u32(const void* p) {
    uint32_t a;
    asm("{ .reg .u64 t; cvta.to.shared.u64 t, %1; cvt.u32.u64 %0, t; }" : "=r"(a) : "l"(p));
    return a;
}
#define CP_ASYNC16(dst, src) \
    asm volatile("cp.async.cg.shared.global [%0], [%1], 16;" :: "r"(dst), "l"(src))
#define CP_COMMIT() asm volatile("cp.async.commit_group;")
#define CP_WAIT0()  asm volatile("cp.async.wait_group 0;")

// packed dual-fp32 FMA (sm_100+ baseline PTX)
__device__ __forceinline__ u64 pack2(float lo, float hi) {
    u64 r;
    asm("mov.b64 %0, {%1, %2};" : "=l"(r) : "f"(lo), "f"(hi));
    return r;
}
__device__ __forceinline__ void unpack2(u64 v, float& lo, float& hi) {
    asm("mov.b64 {%0, %1}, %2;" : "=f"(lo), "=f"(hi) : "l"(v));
}
__device__ __forceinline__ void fma2(u64& d, u64 a, u64 b) {
    asm("fma.rn.f32x2 %0, %1, %2, %0;" : "+l"(d) : "l"(a), "l"(b));
}

// Non-volatile fp16 MMA wrapper.
__device__ __forceinline__ void mma16816h(float* cc, const uint32_t* a, const uint32_t* b) {
    asm("mma.sync.aligned.m16n8k16.row.col.f32.f16.f16.f32 "
        "{%0,%1,%2,%3}, {%4,%5,%6,%7}, {%8,%9}, {%0,%1,%2,%3};"
        : "+f"(cc[0]), "+f"(cc[1]), "+f"(cc[2]), "+f"(cc[3])
        : "r"(a[0]), "r"(a[1]), "r"(a[2]), "r"(a[3]), "r"(b[0]), "r"(b[1]));
}

// ---------------------------------------------------------------------------
// Prep: elementwise fp16 conversion of an fp32 matrix (A operand: hi only)
// ---------------------------------------------------------------------------
__global__ __launch_bounds__(256) void cvt_f16_kernel(
    const float* __restrict__ X, f16* __restrict__ Xh, size_t n4)
{
    size_t i = (size_t)blockIdx.x * 256 + threadIdx.x;
    if (i >= n4) return;
    float4 v = reinterpret_cast<const float4*>(X)[i];
    __half2* ph = reinterpret_cast<__half2*>(Xh);
    ph[2 * i]     = __half2(__float2half_rn(v.x), __float2half_rn(v.y));
    ph[2 * i + 1] = __half2(__float2half_rn(v.z), __float2half_rn(v.w));
}

// Prep: W[K][N] -> Bt[N][K] with fp16 hi/lo split
__global__ __launch_bounds__(256) void transpose_split_f16(
    const float* __restrict__ W, f16* __restrict__ Bh, f16* __restrict__ Bl, int K, int N)
{
    __shared__ float t[32][33];
    const int n0 = blockIdx.x * 32, k0 = blockIdx.y * 32;
    const int c = threadIdx.x & 31, r0 = threadIdx.x >> 5;
#pragma unroll
    for (int i = 0; i < 4; i++)
        t[r0 + i * 8][c] = W[(size_t)(k0 + r0 + i * 8) * N + n0 + c];
    __syncthreads();
#pragma unroll
    for (int i = 0; i < 4; i++) {
        int rr = r0 + i * 8;
        float x = t[c][rr];
        f16 h = __float2half_rn(x);
        size_t o = (size_t)(n0 + rr) * K + k0 + c;
        Bh[o] = h;
        Bl[o] = __float2half_rn(x - __half2float(h));
    }
}

// ---------------------------------------------------------------------------
// fp16 2-term tensor-core GEMM: C = A @ Bt^T, D = Ah*Bh + Ah*Bl.
// CTA 128x128, BK=64, 256 threads, 2-stage cp.async, 2 CTAs/SM.
// ---------------------------------------------------------------------------
constexpr int GROWB  = 144;            // smem bytes per 64-half row (128 + 16 pad)
constexpr int GTILE  = 128 * GROWB;    // 18432 B per operand tile
constexpr int GSTAGE = 3 * GTILE;      // Ah, Bh, Bl -> 55296 B
constexpr int GSMEM  = 2 * GSTAGE;     // 110592 B

__global__ __launch_bounds__(256, 2) void mma_gemm_kernel(
    const f16* __restrict__ Ah,
    const f16* __restrict__ Bh, const f16* __restrict__ Bl,
    float* __restrict__ C, int M, int N, int K)
{
    extern __shared__ char smg[];
    const uint32_t sbase = smem_u32(smg);
    const int tid  = threadIdx.x;
    const int lane = tid & 31, wid = tid >> 5;
    const int m0 = blockIdx.x * 128, n0 = blockIdx.y * 128;
    const int wm = (wid >> 2) * 64, wn = (wid & 3) * 32;
    const int NT = K / 64;

    float acc[4][4][4];
#pragma unroll
    for (int a = 0; a < 4; a++)
#pragma unroll
        for (int b = 0; b < 4; b++)
#pragma unroll
            for (int c = 0; c < 4; c++) acc[a][b][c] = 0.f;

    auto load_stage = [&](int kt, int st) {
        const int kc = kt * 64;
        const uint32_t dbase = sbase + st * GSTAGE;
#pragma unroll
        for (int it = 0; it < 12; it++) {      // 3072 float4: Ah, Bh, Bl
            int idx = tid + it * 256;
            int type = idx >> 10;              // 0:Ah 1:Bh 2:Bl (1024 f4 each)
            int rem = idx & 1023;
            int r = rem >> 3, c = rem & 7;     // 128 rows x 8 float4 (64 halves)
            const f16* src;
            if (type == 0)      src = Ah + (size_t)(m0 + r) * K + kc + c * 8;
            else if (type == 1) src = Bh + (size_t)(n0 + r) * K + kc + c * 8;
            else                src = Bl + (size_t)(n0 + r) * K + kc + c * 8;
            uint32_t dst = dbase + type * GTILE + r * GROWB + c * 16;
            CP_ASYNC16(dst, src);
        }
    };

    const int arow = lane & 15;
    const uint32_t aoff = (uint32_t)(lane >> 4) * 16;
    const int brow = (lane & 7) + ((lane >> 4) << 3);
    const uint32_t boff = (uint32_t)((lane >> 3) & 1) * 16;

    load_stage(0, 0);
    CP_COMMIT();

    for (int kt = 0; kt < NT; kt++) {
        const int st = kt & 1;
        CP_WAIT0();
        __syncthreads();
        if (kt + 1 < NT) {
            load_stage(kt + 1, st ^ 1);
            CP_COMMIT();
        }
        const uint32_t ab = sbase + st * GSTAGE;
        const uint32_t bb = ab + GTILE;
#pragma unroll
        for (int ks = 0; ks < 4; ks++) {
            const uint32_t kb = ks * 32;       // 16 k-halves = 32 B per subtile
            uint32_t aF[4][4], bH[2][4], bL[2][4];
#pragma unroll
            for (int mt = 0; mt < 4; mt++)
                asm volatile("ldmatrix.sync.aligned.m8n8.x4.shared.b16 {%0,%1,%2,%3}, [%4];"
                    : "=r"(aF[mt][0]), "=r"(aF[mt][1]), "=r"(aF[mt][2]), "=r"(aF[mt][3])
                    : "r"(ab + (uint32_t)(wm + mt * 16 + arow) * GROWB + aoff + kb));
#pragma unroll
            for (int gg = 0; gg < 2; gg++) {
                uint32_t ba_ = bb + (uint32_t)(wn + gg * 16 + brow) * GROWB + boff + kb;
                asm volatile("ldmatrix.sync.aligned.m8n8.x4.shared.b16 {%0,%1,%2,%3}, [%4];"
                    : "=r"(bH[gg][0]), "=r"(bH[gg][1]), "=r"(bH[gg][2]), "=r"(bH[gg][3])
                    : "r"(ba_));
                asm volatile("ldmatrix.sync.aligned.m8n8.x4.shared.b16 {%0,%1,%2,%3}, [%4];"
                    : "=r"(bL[gg][0]), "=r"(bL[gg][1]), "=r"(bL[gg][2]), "=r"(bL[gg][3])
                    : "r"(ba_ + GTILE));
            }
            // Pass 1: Ah * Bh
#pragma unroll
            for (int mt = 0; mt < 4; mt++)
#pragma unroll
                for (int nt = 0; nt < 4; nt++)
                    mma16816h(acc[mt][nt], aF[mt], &bH[nt >> 1][(nt & 1) * 2]);
            // Pass 2: Ah * Bl
#pragma unroll
            for (int mt = 0; mt < 4; mt++)
#pragma unroll
                for (int nt = 0; nt < 4; nt++)
                    mma16816h(acc[mt][nt], aF[mt], &bL[nt >> 1][(nt & 1) * 2]);
        }
    }

#pragma unroll
    for (int mt = 0; mt < 4; mt++) {
        int row = m0 + wm + mt * 16 + (lane >> 2);
#pragma unroll
        for (int nt = 0; nt < 4; nt++) {
            int col = n0 + wn + nt * 8 + 2 * (lane & 3);
            *reinterpret_cast<float2*>(C + (size_t)row * N + col) =
                make_float2(acc[mt][nt][0], acc[mt][nt][1]);
            *reinterpret_cast<float2*>(C + (size_t)(row + 8) * N + col) =
                make_float2(acc[mt][nt][2], acc[mt][nt][3]);
        }
    }
}

// ---------------------------------------------------------------------------
// ba = hidden @ W_ba  : split-K (16 slices); reduce folded into conv_gate
// ---------------------------------------------------------------------------
constexpr int BA_SPLITS = 16;
constexpr int BA_KSEG   = EMB_D / BA_SPLITS;   // 128

__global__ __launch_bounds__(256) void ba_gemm_kernel(
    const float* __restrict__ A, const float* __restrict__ B)
{
    __shared__ float As[16][64];
    __shared__ float Bs[16][64];
    const int m0 = blockIdx.x * 64;
    const int z  = blockIdx.y;
    const int k0 = z * BA_KSEG;
    const int tid = threadIdx.x;
    const int tx = tid & 15, ty = tid >> 4;
    float acc[4][4] = {};

    for (int kk = 0; kk < BA_KSEG; kk += 16) {
        int r = tid >> 2, c4 = (tid & 3) * 4;
        float4 av = *reinterpret_cast<const float4*>(A + (size_t)(m0 + r) * EMB_D + k0 + kk + c4);
        As[c4 + 0][r] = av.x; As[c4 + 1][r] = av.y;
        As[c4 + 2][r] = av.z; As[c4 + 3][r] = av.w;
        int r2 = tid >> 4, c2 = (tid & 15) * 4;
        *reinterpret_cast<float4*>(&Bs[r2][c2]) =
            *reinterpret_cast<const float4*>(B + (size_t)(k0 + kk + r2) * 64 + c2);
        __syncthreads();
#pragma unroll
        for (int k = 0; k < 16; k++) {
            float ar[4], br[4];
#pragma unroll
            for (int i = 0; i < 4; i++) ar[i] = As[k][ty * 4 + i];
#pragma unroll
            for (int j = 0; j < 4; j++) br[j] = Bs[k][tx * 4 + j];
#pragma unroll
            for (int i = 0; i < 4; i++)
#pragma unroll
                for (int j = 0; j < 4; j++) acc[i][j] += ar[i] * br[j];
        }
        __syncthreads();
    }
    float* P = g_ba_part[z];
#pragma unroll
    for (int i = 0; i < 4; i++)
#pragma unroll
        for (int j = 0; j < 4; j++)
            P[(size_t)(m0 + ty * 4 + i) * 64 + tx * 4 + j] = acc[i][j];
}

// ---------------------------------------------------------------------------
// Depthwise causal conv (KSZ=4) + SiLU + gates, s-tiled x4
// ---------------------------------------------------------------------------
__global__ __launch_bounds__(256) void conv_gate_kernel(
    const float* __restrict__ conv_w, const float* __restrict__ A_log,
    const float* __restrict__ dt_bias)
{
    const int s0 = blockIdx.x * 4;
    for (int c = threadIdx.x; c < 8192; c += 256) {
        int col;
        float* dst;
        int stride;
        if (c < 2048) {
            int kh = c >> 7, d = c & 127;
            col = kh * 768 + d;
            dst = &g_q[(size_t)s0 * KEY_DIM + c];
            stride = KEY_DIM;
        } else if (c < 4096) {
            int cc = c - 2048;
            int kh = cc >> 7, d = cc & 127;
            col = kh * 768 + 128 + d;
            dst = &g_k[(size_t)s0 * KEY_DIM + cc];
            stride = KEY_DIM;
        } else {
            int cc = c - 4096;
            int vh = cc >> 7, d = cc & 127;
            col = (vh >> 1) * 768 + 256 + (vh & 1) * 128 + d;
            dst = &g_v[(size_t)s0 * VAL_DIM + cc];
            stride = VAL_DIM;
        }
        float w0 = conv_w[0 * 8192 + c];
        float w1 = conv_w[1 * 8192 + c];
        float w2 = conv_w[2 * 8192 + c];
        float w3 = conv_w[3 * 8192 + c];
        float x[7];
#pragma unroll
        for (int t = 0; t < 7; t++) {
            int ss = s0 + t - 3;
            x[t] = (ss >= 0) ? g_qkvz[(size_t)ss * QKVZ_N + col] : 0.f;
        }
#pragma unroll
        for (int t = 0; t < 4; t++) {
            float acc = x[t] * w0 + x[t + 1] * w1 + x[t + 2] * w2 + x[t + 3] * w3;
            dst[(size_t)t * stride] = acc / (1.f + __expf(-acc));
        }
    }
    if (threadIdx.x < 128) {                  // 4 positions x 32 heads
        int s  = s0 + (threadIdx.x >> 5);
        int vh = threadIdx.x & 31;
        int kh = vh >> 1, j = vh & 1;
        float bg = 0.f, ag = 0.f;
#pragma unroll
        for (int z = 0; z < BA_SPLITS; z++) {
            bg += g_ba_part[z][s * 64 + kh * 4 + j];
            ag += g_ba_part[z][s * 64 + kh * 4 + 2 + j];
        }
        g_beta[s * N_VH + vh] = 1.f / (1.f + expf(-bg));
        float x = ag + dt_bias[vh];
        float sp = (x > 20.f) ? x : log1pf(expf(x));
        g_g[s * N_VH + vh] = -expf(A_log[vh]) * sp;
    }
}

// ---------------------------------------------------------------------------
// Intra-chunk kernel (decay table + fused dual matmul with f32x2 + warp scan)
// ---------------------------------------------------------------------------
constexpr int INTRA_SMEM = (64 * SKP * 2 + 64 * SDP * 2 + 64 * SYP + 192) * 4;

__global__ __launch_bounds__(256) void intra_kernel()
{
    extern __shared__ float sm[];
    float* sK  = sm;
    float* sQ  = sK + 64 * SKP;
    float* sD  = sQ + 64 * SKP;
    float* sL  = sD + 64 * SDP;
    float* sY  = sL + 64 * SDP;
    float* sgc = sY + 64 * SYP;
    float* sb  = sgc + 64;
    float* sE  = sb + 64;

    const int c   = blockIdx.x;
    const int h   = blockIdx.y;
    const int kh  = h >> 1;
    const int s0  = c * CH;
    const int tid = threadIdx.x;
    const size_t base = (size_t)(c * N_VH + h);

    for (int idx = tid; idx < CH * D_K; idx += 256) {
        int i = idx >> 7, d = idx & 127;
        sK[i * SKP + d] = g_k[(size_t)(s0 + i) * KEY_DIM + kh * D_K + d];
        sQ[i * SKP + d] = g_q[(size_t)(s0 + i) * KEY_DIM + kh * D_K + d] * RSQRT_DK;
    }
    if (tid < CH) {
        sb[tid]  = g_beta[(s0 + tid) * N_VH + h];
        sgc[tid] = g_g[(s0 + tid) * N_VH + h];
    }
    __syncthreads();

    // inclusive cumsum of g: one warp, 2 elems/lane
    if (tid < 32) {
        float x0 = sgc[2 * tid], x1 = sgc[2 * tid + 1];
        float s = x0 + x1;
#pragma unroll
        for (int off = 1; off < 32; off <<= 1) {
            float t = __shfl_up_sync(0xffffffffu, s, off);
            if (tid >= off) s += t;
        }
        float excl = s - (x0 + x1);
        sgc[2 * tid]     = excl + x0;
        sgc[2 * tid + 1] = excl + x0 + x1;
    }
    __syncthreads();

    // decay table + e^{gc}
    for (int idx = tid; idx < CH * CH; idx += 256) {
        int i = idx >> 6, j = idx & 63;
        sD[i * SDP + j] = (j <= i) ? __expf(sgc[i] - sgc[j]) : 0.f;
    }
    if (tid < CH) sE[tid] = __expf(sgc[tid]);
    __syncthreads();

    // fused dual matmul via f32x2 pairs over d: accL = k.k^T ; accA = q.k^T
    {
        const int ty = tid >> 4, tx = tid & 15;
        const int i0 = ty * 4, j0 = tx * 4;
        u64 accLp[4][4], accAp[4][4];
#pragma unroll
        for (int ii = 0; ii < 4; ii++)
#pragma unroll
            for (int jj = 0; jj < 4; jj++) { accLp[ii][jj] = 0ull; accAp[ii][jj] = 0ull; }
        for (int d = 0; d < D_K; d += 2) {
            u64 avp[4], qvp[4], bvp[4];
#pragma unroll
            for (int ii = 0; ii < 4; ii++) {
                avp[ii] = *reinterpret_cast<const u64*>(&sK[(i0 + ii) * SKP + d]);
                qvp[ii] = *reinterpret_cast<const u64*>(&sQ[(i0 + ii) * SKP + d]);
            }
#pragma unroll
            for (int jj = 0; jj < 4; jj++)
                bvp[jj] = *reinterpret_cast<const u64*>(&sK[(j0 + jj) * SKP + d]);
#pragma unroll
            for (int ii = 0; ii < 4; ii++)
#pragma unroll
                for (int jj = 0; jj < 4; jj++) {
                    fma2(accLp[ii][jj], avp[ii], bvp[jj]);
                    fma2(accAp[ii][jj], qvp[ii], bvp[jj]);
                }
        }
#pragma unroll
        for (int ii = 0; ii < 4; ii++)
#pragma unroll
            for (int jj = 0; jj < 4; jj++) {
                int i = i0 + ii, j = j0 + jj;
                float l0, l1, a0, a1;
                unpack2(accLp[ii][jj], l0, l1);
                unpack2(accAp[ii][jj], a0, a1);
                float dec = sD[i * SDP + j];
                sL[i * SDP + j] = (j < i) ? -(l0 + l1) * sb[i] * dec : 0.f;
                g_am[base * (CH * CH) + i * CH + j] = (a0 + a1) * dec;  // dec=0 for j>i
            }
    }

    // Y init: [v*beta | k*beta*e^{gc}]
    for (int idx = tid; idx < CH * 256; idx += 256) {
        int i = idx >> 8, cc = idx & 255;
        float v;
        if (cc < 128) v = g_v[(size_t)(s0 + i) * VAL_DIM + h * D_V + cc] * sb[i];
        else          v = sK[i * SKP + (cc - 128)] * sb[i] * sE[i];
        sY[i * SYP + cc] = v;
    }
    __syncthreads();

    // forward substitution (I-L)Y = B; one column per thread
    {
        const int cc = tid;
        for (int i = 1; i < CH; i++) {
            const float* lrow = &sL[i * SDP];
            float a0 = 0.f, a1 = 0.f, a2 = 0.f, a3 = 0.f;
            int j = 0;
            for (; j + 4 <= i; j += 4) {
                a0 += lrow[j + 0] * sY[(j + 0) * SYP + cc];
                a1 += lrow[j + 1] * sY[(j + 1) * SYP + cc];
                a2 += lrow[j + 2] * sY[(j + 2) * SYP + cc];
                a3 += lrow[j + 3] * sY[(j + 3) * SYP + cc];
            }
            for (; j < i; j++) a0 += lrow[j] * sY[j * SYP + cc];
            sY[i * SYP + cc] += (a0 + a1) + (a2 + a3);
        }
    }
    __syncthreads();

    // outputs
    for (int idx = tid; idx < CH * D_K; idx += 256) {
        int i = idx >> 7, d = idx & 127;
        g_vi [base * (CH * D_V) + idx] = sY[i * SYP + d];
        g_kcd[base * (CH * D_K) + idx] = sY[i * SYP + 128 + d];
        g_kg [base * (CH * D_K) + idx] = sK[i * SKP + d] * sD[63 * SDP + i];
        g_qg [base * (CH * D_K) + idx] = sQ[i * SKP + d] * sE[i];
    }
    if (tid == 0) g_egl[c * N_VH + h] = sE[63];
}

// ---------------------------------------------------------------------------
// Inter-chunk scan (round-15 structure)
// ---------------------------------------------------------------------------
constexpr int SK2 = 132;
constexpr int SC2 = 68;
constexpr int SV2 = 36;
constexpr int SST = 36;
constexpr int SBT = 36;
constexpr int SCAN_SMEM =
    (128 * SST + 3 * 64 * SK2 + 64 * SC2 + 64 * SV2 + 64 * SBT + 64) * 4;

__global__ __launch_bounds__(256) void scan_kernel()
{
    extern __shared__ float sm[];
    float* sSt  = sm;
    float* sKcd = sSt + 128 * SST;
    float* sQg  = sKcd + 64 * SK2;
    float* sKg  = sQg + 64 * SK2;
    float* sC   = sKg + 64 * SK2;
    float* sVi  = sC + 64 * SC2;
    float* sB   = sVi + 64 * SV2;
    float* sEgl = sB + 64 * SBT;         // 64 per-chunk exp(g_last)

    const int h   = blockIdx.x;
    const int grp = blockIdx.y;
    const int e0  = grp * 32;
    const int tid = threadIdx.x;
    const int tx  = tid & 7;
    const int ty  = tid >> 3;
    const uint32_t uKcd = smem_u32(sKcd), uQg = smem_u32(sQg), uKg = smem_u32(sKg);
    const uint32_t uC = smem_u32(sC), uVi = smem_u32(sVi);

    for (int idx = tid; idx < 128 * SST; idx += 256) sSt[idx] = 0.f;
    if (tid < NCH) sEgl[tid] = g_egl[tid * N_VH + h];
    __syncthreads();

    auto issue_loads = [&](int c) {
        const size_t base = (size_t)(c * N_VH + h);
        const float* kcd = g_kcd + base * (CH * D_K);
        const float* qg  = g_qg  + base * (CH * D_K);
        const float* kg  = g_kg  + base * (CH * D_K);
        const float* am  = g_am  + base * (CH * CH);
        const float* vi  = g_vi  + base * (CH * D_V);
#pragma unroll
        for (int it = 0; it < 8; it++) {
            int idx = tid + it * 256;
            int r = idx >> 5, q = idx & 31;
            CP_ASYNC16(uKcd + (uint32_t)(r * SK2 + q * 4) * 4, kcd + r * 128 + q * 4);
            CP_ASYNC16(uQg  + (uint32_t)(r * SK2 + q * 4) * 4, qg  + r * 128 + q * 4);
            CP_ASYNC16(uKg  + (uint32_t)(r * SK2 + q * 4) * 4, kg  + r * 128 + q * 4);
        }
#pragma unroll
        for (int it = 0; it < 4; it++) {
            int idx = tid + it * 256;
            int r = idx >> 4, q = idx & 15;
            CP_ASYNC16(uC + (uint32_t)(r * SC2 + q * 4) * 4, am + r * 64 + q * 4);
        }
#pragma unroll
        for (int it = 0; it < 2; it++) {
            int i2 = tid + it * 256;
            int rr = i2 >> 3, qq = i2 & 7;
            CP_ASYNC16(uVi + (uint32_t)(rr * SV2 + qq * 4) * 4, vi + rr * 128 + e0 + qq * 4);
        }
        CP_COMMIT();
    };

    issue_loads(0);

    for (int c = 0; c < NCH; c++) {
        CP_WAIT0();
        __syncthreads();                           // S1: tiles ready

        u64 kst[2][2] = {0ull, 0ull, 0ull, 0ull};
        u64 ost[2][2] = {0ull, 0ull, 0ull, 0ull};
        const float* kr0 = &sKcd[(ty * 2 + 0) * SK2];
        const float* kr1 = &sKcd[(ty * 2 + 1) * SK2];
        const float* qr0 = &sQg[(ty * 2 + 0) * SK2];
        const float* qr1 = &sQg[(ty * 2 + 1) * SK2];
        for (int kd = 0; kd < D_K; kd += 2) {
            ulonglong2 b0 = *reinterpret_cast<const ulonglong2*>(&sSt[kd * SST + tx * 4]);
            ulonglong2 b1 = *reinterpret_cast<const ulonglong2*>(&sSt[(kd + 1) * SST + tx * 4]);
            float ka0, ka1, kb0, kb1, qa0, qa1, qb0, qb1;
            unpack2(*reinterpret_cast<const u64*>(kr0 + kd), ka0, ka1);
            unpack2(*reinterpret_cast<const u64*>(kr1 + kd), kb0, kb1);
            unpack2(*reinterpret_cast<const u64*>(qr0 + kd), qa0, qa1);
            unpack2(*reinterpret_cast<const u64*>(qr1 + kd), qb0, qb1);
            u64 p;
            p = pack2(ka0, ka0); fma2(kst[0][0], p, b0.x); fma2(kst[0][1], p, b0.y);
            p = pack2(kb0, kb0); fma2(kst[1][0], p, b0.x); fma2(kst[1][1], p, b0.y);
            p = pack2(qa0, qa0); fma2(ost[0][0], p, b0.x); fma2(ost[0][1], p, b0.y);
            p = pack2(qb0, qb0); fma2(ost[1][0], p, b0.x); fma2(ost[1][1], p, b0.y);
            p = pack2(ka1, ka1); fma2(kst[0][0], p, b1.x); fma2(kst[0][1], p, b1.y);
            p = pack2(kb1, kb1); fma2(kst[1][0], p, b1.x); fma2(kst[1][1], p, b1.y);
            p = pack2(qa1, qa1); fma2(ost[0][0], p, b1.x); fma2(ost[0][1], p, b1.y);
            p = pack2(qb1, qb1); fma2(ost[1][0], p, b1.x); fma2(ost[1][1], p, b1.y);
        }
#pragma unroll
        for (int ii = 0; ii < 2; ii++) {
            float k0, k1, k2, k3;
            unpack2(kst[ii][0], k0, k1);
            unpack2(kst[ii][1], k2, k3);
            const float* vr = &sVi[(ty * 2 + ii) * SV2 + tx * 4];
            float* br = &sB[(ty * 2 + ii) * SBT + tx * 4];
            br[0] = vr[0] - k0; br[1] = vr[1] - k1;
            br[2] = vr[2] - k2; br[3] = vr[3] - k3;
        }
        __syncthreads();                           // S2: v_new ready

        {
            const int jmax = ty * 2 + 2;
            for (int j = 0; j < jmax; j++) {
                ulonglong2 b = *reinterpret_cast<const ulonglong2*>(&sB[j * SBT + tx * 4]);
                u64 p0 = pack2(sC[(ty * 2 + 0) * SC2 + j], sC[(ty * 2 + 0) * SC2 + j]);
                u64 p1 = pack2(sC[(ty * 2 + 1) * SC2 + j], sC[(ty * 2 + 1) * SC2 + j]);
                fma2(ost[0][0], p0, b.x); fma2(ost[0][1], p0, b.y);
                fma2(ost[1][0], p1, b.x); fma2(ost[1][1], p1, b.y);
            }
        }
        u64 sacc[4][2];
#pragma unroll
        for (int dd = 0; dd < 4; dd++) { sacc[dd][0] = 0ull; sacc[dd][1] = 0ull; }
        for (int t = 0; t < CH; t += 2) {
            ulonglong2 av0 = *reinterpret_cast<const ulonglong2*>(&sKg[t * SK2 + ty * 4]);
            ulonglong2 av1 = *reinterpret_cast<const ulonglong2*>(&sKg[(t + 1) * SK2 + ty * 4]);
            ulonglong2 b0  = *reinterpret_cast<const ulonglong2*>(&sB[t * SBT + tx * 4]);
            ulonglong2 b1  = *reinterpret_cast<const ulonglong2*>(&sB[(t + 1) * SBT + tx * 4]);
            float a0, a1, a2, a3, c0, c1, c2, c3;
            unpack2(av0.x, a0, a1);
            unpack2(av0.y, a2, a3);
            unpack2(av1.x, c0, c1);
            unpack2(av1.y, c2, c3);
            u64 q;
            q = pack2(a0, a0); fma2(sacc[0][0], q, b0.x); fma2(sacc[0][1], q, b0.y);
            q = pack2(a1, a1); fma2(sacc[1][0], q, b0.x); fma2(sacc[1][1], q, b0.y);
            q = pack2(a2, a2); fma2(sacc[2][0], q, b0.x); fma2(sacc[2][1], q, b0.y);
            q = pack2(a3, a3); fma2(sacc[3][0], q, b0.x); fma2(sacc[3][1], q, b0.y);
            q = pack2(c0, c0); fma2(sacc[0][0], q, b1.x); fma2(sacc[0][1], q, b1.y);
            q = pack2(c1, c1); fma2(sacc[1][0], q, b1.x); fma2(sacc[1][1], q, b1.y);
            q = pack2(c2, c2); fma2(sacc[2][0], q, b1.x); fma2(sacc[2][1], q, b1.y);
            q = pack2(c3, c3); fma2(sacc[3][0], q, b1.x); fma2(sacc[3][1], q, b1.y);
        }
        const float egl = sEgl[c];
        __syncthreads();                           // S3: all tile reads done

        if (c + 1 < NCH) issue_loads(c + 1);

        const u64 pe = pack2(egl, egl);
#pragma unroll
        for (int dd = 0; dd < 4; dd++)
#pragma unroll
            for (int p = 0; p < 2; p++) {
                u64* sp = reinterpret_cast<u64*>(&sSt[(ty * 4 + dd) * SST + tx * 4 + p * 2]);
                u64 st = *sp;
                fma2(sacc[dd][p], pe, st);
                *sp = sacc[dd][p];
            }
#pragma unroll
        for (int ii = 0; ii < 2; ii++) {
            ulonglong2 ov;
            ov.x = ost[ii][0];
            ov.y = ost[ii][1];
            *reinterpret_cast<ulonglong2*>(
                &g_core[(size_t)(c * CH + ty * 2 + ii) * VAL_DIM + h * D_V + e0 + tx * 4]) = ov;
        }
    }
}

// ---------------------------------------------------------------------------
// Gated RMSNorm, 2 rows per block, fused fp16 output (A operand hi only)
// ---------------------------------------------------------------------------
__global__ __launch_bounds__(256) void norm_kernel(
    const float* __restrict__ norm_w, f16* __restrict__ Ah)
{
    __shared__ float red[8];
    const int s  = blockIdx.x;
    const int vh = blockIdx.y * 2 + (threadIdx.x >> 7);
    const int d  = threadIdx.x & 127;
    const int w  = threadIdx.x >> 5;
    const int g  = w >> 2;
    const int kh = vh >> 1;
    float x  = g_core[(size_t)(s * N_VH + vh) * D_V + d];
    float zv = g_qkvz[(size_t)s * QKVZ_N + kh * 768 + 512 + (vh & 1) * 128 + d];
    float xf = x * (zv / (1.f + __expf(-zv)));
    float v = xf * xf;
#pragma unroll
    for (int o = 16; o > 0; o >>= 1) v += __shfl_xor_sync(0xffffffffu, v, o);
    if ((threadIdx.x & 31) == 0) red[w] = v;
    __syncthreads();
    float var = (red[g * 4 + 0] + red[g * 4 + 1] + red[g * 4 + 2] + red[g * 4 + 3]) * (1.f / 128.f);
    float y = xf * rsqrtf(var + 1e-6f) * norm_w[d];
    Ah[(size_t)s * VAL_DIM + vh * D_V + d] = __float2half_rn(y);
}

// ---------------------------------------------------------------------------
// Launch: dual-stream overlap. Side stream (created once, on the uncaptured
// correctness call) runs ba_gemm + W_out transpose concurrent with the qkvz
// GEMM; event fork/join keeps the graph capture valid.
// ---------------------------------------------------------------------------
extern "C" void kernel_launch(void* const* d_in, const int* in_sizes, int n_in,
                              void* d_out, int out_size)
{
    const float* hidden  = (const float*)d_in[0];
    const float* W_qkvz  = (const float*)d_in[1];
    const float* W_ba    = (const float*)d_in[2];
    const float* conv_w  = (const float*)d_in[3];
    const float* A_log   = (const float*)d_in[4];
    const float* dt_bias = (const float*)d_in[5];
    const float* norm_w  = (const float*)d_in[6];
    const float* W_out   = (const float*)d_in[7];
    float* out = (float*)d_out;

    float *qkvz;
    f16 *Ah, *Bh, *Bl, *Bh2, *Bl2;
    cudaGetSymbolAddress((void**)&qkvz, g_qkvz);
    cudaGetSymbolAddress((void**)&Ah,   g_Ah);
    cudaGetSymbolAddress((void**)&Bh,   g_Bh);
    cudaGetSymbolAddress((void**)&Bl,   g_Bl);
    cudaGetSymbolAddress((void**)&Bh2,  g_Bh2);
    cudaGetSymbolAddress((void**)&Bl2,  g_Bl2);

    static bool init_done = false;
    static cudaStream_t s2;
    static cudaEvent_t evFork, evJoin;
    if (!init_done) {
        cudaFuncSetAttribute(intra_kernel, cudaFuncAttributeMaxDynamicSharedMemorySize, INTRA_SMEM);
        cudaFuncSetAttribute(scan_kernel,  cudaFuncAttributeMaxDynamicSharedMemorySize, SCAN_SMEM);
        cudaFuncSetAttribute(mma_gemm_kernel, cudaFuncAttributeMaxDynamicSharedMemorySize, GSMEM);
        cudaStreamCreateWithFlags(&s2, cudaStreamNonBlocking);
        cudaEventCreateWithFlags(&evFork, cudaEventDisableTiming);
        cudaEventCreateWithFlags(&evJoin, cudaEventDisableTiming);
        init_done = true;
    }

    // 1-2 (main): operand prep for qkvz GEMM
    {
        size_t n4 = (size_t)S_LEN * EMB_D / 4;
        cvt_f16_kernel<<<(unsigned)((n4 + 255) / 256), 256>>>(hidden, Ah, n4);
        transpose_split_f16<<<dim3(QKVZ_N / 32, EMB_D / 32), 256>>>(W_qkvz, Bh, Bl, EMB_D, QKVZ_N);
    }
    // fork side stream (depends only on harness inputs)
    cudaEventRecord(evFork, 0);
    cudaStreamWaitEvent(s2, evFork, 0);
    // 3 (s2): ba split-K partials
    ba_gemm_kernel<<<dim3(S_LEN / 64, BA_SPLITS), 256, 0, s2>>>(hidden, W_ba);
    // 4 (main): qkvz GEMM  <- ncu captures this launch
    mma_gemm_kernel<<<dim3(S_LEN / 128, QKVZ_N / 128), 256, GSMEM>>>(
        Ah, Bh, Bl, qkvz, S_LEN, QKVZ_N, EMB_D);
    // 5 (s2): W_out transpose into separate buffers (runs under qkvz GEMM)
    transpose_split_f16<<<dim3(EMB_D / 32, VAL_DIM / 32), 256, 0, s2>>>(
        W_out, Bh2, Bl2, VAL_DIM, EMB_D);
    cudaEventRecord(evJoin, s2);
    cudaStreamWaitEvent(0, evJoin, 0);
    // 6 (main): conv + gates (needs ba partials)
    conv_gate_kernel<<<S_LEN / 4, 256>>>(conv_w, A_log, dt_bias);
    // 7-8: delta-rule core
    intra_kernel<<<dim3(NCH, N_VH), 256, INTRA_SMEM>>>();
    scan_kernel<<<dim3(N_VH, 4), 256, SCAN_SMEM>>>();
    // 9: gated RMSNorm + fused fp16 convert
    norm_kernel<<<dim3(S_LEN, N_VH / 2), 256>>>(norm_w, Ah);
    // 10: out GEMM (uses Bh2/Bl2 prepared on the side stream)
    mma_gemm_kernel<<<dim3(S_LEN / 128, EMB_D / 128), 256, GSMEM>>>(
        Ah, Bh2, Bl2, out, S_LEN, EMB_D, VAL_DIM);
}